// round 4
// baseline (speedup 1.0000x reference)
#include <cuda_runtime.h>
#include <cuda_bf16.h>
#include <math.h>
#include <stdint.h>

#define BATCH 8
#define SEQ   2048
#define DIM   512
#define MTOT  (BATCH*SEQ)   // 16384

// ---------------------------------------------------------------------------
// Device scratch (allocation-free rule: __device__ globals)
// ---------------------------------------------------------------------------
__device__ __nv_bfloat16 g_xh[MTOT * DIM], g_xl[MTOT * DIM];
__device__ __nv_bfloat16 g_Wqt_h[DIM * DIM], g_Wqt_l[DIM * DIM];
__device__ __nv_bfloat16 g_Wkt_h[DIM * DIM], g_Wkt_l[DIM * DIM];
__device__ __nv_bfloat16 g_Wvt_h[DIM * DIM], g_Wvt_l[DIM * DIM];
__device__ __nv_bfloat16 g_Qh[MTOT * DIM], g_Ql[MTOT * DIM];
__device__ __nv_bfloat16 g_Kh[MTOT * DIM], g_Kl[MTOT * DIM];
__device__ float         g_V[MTOT * DIM];
__device__ __nv_bfloat16 g_Vth[MTOT * DIM], g_Vtl[MTOT * DIM];  // [B][DIM][SEQ]
__device__ float         g_S [(size_t)BATCH * SEQ * SEQ];
__device__ __nv_bfloat16 g_Ph[(size_t)BATCH * SEQ * SEQ];
__device__ __nv_bfloat16 g_Pl[(size_t)BATCH * SEQ * SEQ];

// ---------------------------------------------------------------------------
// Baseline-ISA helpers: ldmatrix / mma.sync / cp.async  (no 'a' features)
// ---------------------------------------------------------------------------
__device__ __forceinline__ uint32_t smem_to_u32(const void* p) {
    uint32_t a;
    asm("{ .reg .u64 t; cvta.to.shared.u64 t, %1; cvt.u32.u64 %0, t; }" : "=r"(a) : "l"(p));
    return a;
}
__device__ __forceinline__ void ldsm4(uint32_t* r, uint32_t addr) {
    asm volatile("ldmatrix.sync.aligned.m8n8.x4.shared.b16 {%0,%1,%2,%3}, [%4];"
                 : "=r"(r[0]), "=r"(r[1]), "=r"(r[2]), "=r"(r[3]) : "r"(addr));
}
__device__ __forceinline__ void mma_bf16(float* c, const uint32_t* a,
                                         uint32_t b0, uint32_t b1) {
    asm volatile("mma.sync.aligned.m16n8k16.row.col.f32.bf16.bf16.f32 "
                 "{%0,%1,%2,%3}, {%4,%5,%6,%7}, {%8,%9}, {%0,%1,%2,%3};"
                 : "+f"(c[0]), "+f"(c[1]), "+f"(c[2]), "+f"(c[3])
                 : "r"(a[0]), "r"(a[1]), "r"(a[2]), "r"(a[3]), "r"(b0), "r"(b1));
}
__device__ __forceinline__ void cp16(uint32_t dst, const void* src) {
    asm volatile("cp.async.cg.shared.global [%0], [%1], 16;" :: "r"(dst), "l"(src));
}
#define CP_COMMIT() asm volatile("cp.async.commit_group;" ::: "memory")
#define CP_WAIT2()  asm volatile("cp.async.wait_group 2;" ::: "memory")

__device__ __forceinline__ void split2(float a, __nv_bfloat16& h, __nv_bfloat16& l) {
    h = __float2bfloat16(a);
    l = __float2bfloat16(a - __bfloat162float(h));
}

// ---------------------------------------------------------------------------
// bf16-split HMMA GEMM:  C[M,N] = scale * (A[M,K] * B[N,K]^T) (+bias, relu)
// Block tile 128M x 256N, BK=32, 8 warps (2M x 4N) of 64x64 warp tiles.
// 3-stage cp.async pipeline. smem rows padded to 80B ((row*5)%8 permutation
// -> conflict-free ldmatrix phases).
// ---------------------------------------------------------------------------
#define ROWB   80
#define A_T    (128 * ROWB)            // 10240 B per A half-tile
#define B_T    (256 * ROWB)            // 20480 B per B half-tile
#define STAGEB (2 * A_T + 2 * B_T)     // 61440 B
#define NSTAGE 3
#define GEMM_DSMEM (NSTAGE * STAGEB)   // 184320 B

__device__ __forceinline__ void issue_stage(uint32_t sAddr,
    const __nv_bfloat16* pAh, const __nv_bfloat16* pAl,
    const __nv_bfloat16* pBh, const __nv_bfloat16* pBl,
    int lda, int ldb, int k0, int t)
{
    // 3072 x 16B transfers: A (2 x 128rows x 4ch) then B (2 x 256rows x 4ch)
    #pragma unroll
    for (int i = 0; i < 4; i++) {           // A halves
        const int idx  = t + i * 256;       // 0..1023
        const int half = idx >> 9;          // 0=Ah 1=Al
        const int r    = (idx & 511) >> 2;
        const int ch   = idx & 3;
        const __nv_bfloat16* src = (half ? pAl : pAh) + (size_t)r * lda + k0 + ch * 8;
        cp16(sAddr + half * A_T + r * ROWB + ch * 16, src);
    }
    #pragma unroll
    for (int i = 4; i < 12; i++) {          // B halves
        const int j    = t + (i - 4) * 256; // 0..2047
        const int half = j >> 10;           // 0=Bh 1=Bl
        const int r    = (j & 1023) >> 2;
        const int ch   = j & 3;
        const __nv_bfloat16* src = (half ? pBl : pBh) + (size_t)r * ldb + k0 + ch * 8;
        cp16(sAddr + 2 * A_T + half * B_T + r * ROWB + ch * 16, src);
    }
}

__global__ __launch_bounds__(256, 1)
void gemm_bs(const __nv_bfloat16* __restrict__ Ah, const __nv_bfloat16* __restrict__ Al,
             const __nv_bfloat16* __restrict__ Bh, const __nv_bfloat16* __restrict__ Bl,
             const float* __restrict__ bias,
             float* __restrict__ Cf,
             __nv_bfloat16* __restrict__ Ch, __nv_bfloat16* __restrict__ Cl,
             int M, int N, int K,
             size_t sA, size_t sB, size_t sC,
             float scale, int relu)
{
    extern __shared__ char smem[];
    const uint32_t sb = smem_to_u32(smem);

    const int t    = threadIdx.x;
    const int wid  = t >> 5;
    const int lane = t & 31;
    const int wm   = wid >> 2;          // 0..1 -> M (64-row slab)
    const int wn   = wid & 3;           // 0..3 -> N (64-col slab)

    const int z = blockIdx.z;
    const int rowBase = blockIdx.y * 128;
    const int colBase = blockIdx.x * 256;
    const int lda = K, ldb = K;

    const __nv_bfloat16* pAh = Ah + (size_t)z * sA + (size_t)rowBase * lda;
    const __nv_bfloat16* pAl = Al + (size_t)z * sA + (size_t)rowBase * lda;
    const __nv_bfloat16* pBh = Bh + (size_t)z * sB + (size_t)colBase * ldb;
    const __nv_bfloat16* pBl = Bl + (size_t)z * sB + (size_t)colBase * ldb;

    float acc[4][8][4];
    #pragma unroll
    for (int mi = 0; mi < 4; mi++)
        #pragma unroll
        for (int ni = 0; ni < 8; ni++)
            #pragma unroll
            for (int r = 0; r < 4; r++) acc[mi][ni][r] = 0.0f;

    const int nc = K / 32;

    issue_stage(sb,          pAh, pAl, pBh, pBl, lda, ldb,  0, t); CP_COMMIT();
    issue_stage(sb + STAGEB, pAh, pAl, pBh, pBl, lda, ldb, 32, t); CP_COMMIT();

    // per-thread ldmatrix source geometry: addr = base + (lane%16)*ROWB + (lane/16)*16
    const int lrow = lane & 15;
    const uint32_t cSel = ((lane >> 4) & 1) * 16;

    for (int c = 0; c < nc; c++) {
        // keep the group count constant: always commit (maybe-empty) group
        if (c + 2 < nc)
            issue_stage(sb + ((c + 2) % NSTAGE) * STAGEB, pAh, pAl, pBh, pBl,
                        lda, ldb, (c + 2) * 32, t);
        CP_COMMIT();
        CP_WAIT2();                // stage c complete
        __syncthreads();

        const uint32_t st = sb + (c % NSTAGE) * STAGEB;
        #pragma unroll
        for (int ks = 0; ks < 2; ks++) {
            const uint32_t cb = ks * 32 + cSel;
            uint32_t ah[4][4], al[4][4];
            #pragma unroll
            for (int mi = 0; mi < 4; mi++) {
                const uint32_t ra = (uint32_t)(wm * 64 + mi * 16 + lrow) * ROWB + cb;
                ldsm4(ah[mi], st + ra);
                ldsm4(al[mi], st + A_T + ra);
            }
            #pragma unroll
            for (int g = 0; g < 4; g++) {   // 16-col N group -> n8 blocks 2g, 2g+1
                const uint32_t rb = (uint32_t)(wn * 64 + g * 16 + lrow) * ROWB + cb;
                uint32_t qh[4], ql[4];
                ldsm4(qh, st + 2 * A_T + rb);
                ldsm4(ql, st + 2 * A_T + B_T + rb);
                #pragma unroll
                for (int mi = 0; mi < 4; mi++) {
                    mma_bf16(acc[mi][2*g],   ah[mi], qh[0], qh[2]);
                    mma_bf16(acc[mi][2*g],   ah[mi], ql[0], ql[2]);
                    mma_bf16(acc[mi][2*g],   al[mi], qh[0], qh[2]);
                    mma_bf16(acc[mi][2*g+1], ah[mi], qh[1], qh[3]);
                    mma_bf16(acc[mi][2*g+1], ah[mi], ql[1], ql[3]);
                    mma_bf16(acc[mi][2*g+1], al[mi], qh[1], qh[3]);
                }
            }
        }
        __syncthreads();
    }

    // ------------------------------ epilogue -------------------------------
    #pragma unroll
    for (int mi = 0; mi < 4; mi++) {
        #pragma unroll
        for (int rr = 0; rr < 2; rr++) {
            const int r = rowBase + wm * 64 + mi * 16 + rr * 8 + (lane >> 2);
            #pragma unroll
            for (int ni = 0; ni < 8; ni++) {
                const int cc = colBase + wn * 64 + ni * 8 + (lane & 3) * 2;
                float a = acc[mi][ni][rr * 2 + 0] * scale;
                float b = acc[mi][ni][rr * 2 + 1] * scale;
                if (bias) { a += bias[cc]; b += bias[cc + 1]; }
                if (relu) { a = fmaxf(a, 0.0f); b = fmaxf(b, 0.0f); }
                if (Cf) {
                    *(float2*)(Cf + (size_t)z * sC + (size_t)r * N + cc) = make_float2(a, b);
                } else {
                    __nv_bfloat16 hA, lA, hB, lB;
                    split2(a, hA, lA); split2(b, hB, lB);
                    *(__nv_bfloat162*)(Ch + (size_t)z * sC + (size_t)r * N + cc) =
                        __halves2bfloat162(hA, hB);
                    *(__nv_bfloat162*)(Cl + (size_t)z * sC + (size_t)r * N + cc) =
                        __halves2bfloat162(lA, lB);
                }
            }
        }
    }
}

// ---------------------------------------------------------------------------
// fp32 -> bf16 hi/lo elementwise split (for x)
// ---------------------------------------------------------------------------
__global__ __launch_bounds__(256)
void split_f32(const float* __restrict__ in, __nv_bfloat16* __restrict__ oh,
               __nv_bfloat16* __restrict__ ol, size_t n4)
{
    size_t i = (size_t)blockIdx.x * blockDim.x + threadIdx.x;
    if (i >= n4) return;
    float4 v = ((const float4*)in)[i];
    __nv_bfloat16 h0,l0,h1,l1,h2,l2,h3,l3;
    split2(v.x,h0,l0); split2(v.y,h1,l1); split2(v.z,h2,l2); split2(v.w,h3,l3);
    ((__nv_bfloat162*)oh)[2*i]   = __halves2bfloat162(h0,h1);
    ((__nv_bfloat162*)oh)[2*i+1] = __halves2bfloat162(h2,h3);
    ((__nv_bfloat162*)ol)[2*i]   = __halves2bfloat162(l0,l1);
    ((__nv_bfloat162*)ol)[2*i+1] = __halves2bfloat162(l2,l3);
}

// ---------------------------------------------------------------------------
// transpose + split: in fp32 [R,C] -> out bf16 hi/lo [C,R]   (z-batched)
// ---------------------------------------------------------------------------
__global__ __launch_bounds__(256)
void transpose_split(const float* __restrict__ in, __nv_bfloat16* __restrict__ oh,
                     __nv_bfloat16* __restrict__ ol, int R, int C,
                     size_t sIn, size_t sOut)
{
    __shared__ float tile[32][33];
    const int z = blockIdx.z;
    in += (size_t)z * sIn;  oh += (size_t)z * sOut;  ol += (size_t)z * sOut;
    const int c0 = blockIdx.x * 32, r0 = blockIdx.y * 32;
    const int tx = threadIdx.x & 31, ty = threadIdx.x >> 5;
    #pragma unroll
    for (int i = 0; i < 4; i++)
        tile[ty + i * 8][tx] = in[(size_t)(r0 + ty + i * 8) * C + c0 + tx];
    __syncthreads();
    #pragma unroll
    for (int i = 0; i < 4; i++) {
        const int ro = c0 + ty + i * 8;
        float v = tile[tx][ty + i * 8];
        __nv_bfloat16 h, l; split2(v, h, l);
        oh[(size_t)ro * R + r0 + tx] = h;
        ol[(size_t)ro * R + r0 + tx] = l;
    }
}

// ---------------------------------------------------------------------------
// Row softmax over 2048 cols; reads fp32 S, writes bf16 hi/lo splits of P.
// ---------------------------------------------------------------------------
__global__ __launch_bounds__(256)
void softmax_split(const float* __restrict__ S, __nv_bfloat16* __restrict__ Ph,
                   __nv_bfloat16* __restrict__ Pl)
{
    const size_t rowOff = (size_t)blockIdx.x * SEQ;
    const float* row = S + rowOff;
    const int t = threadIdx.x;
    __shared__ float red[256];

    float vals[8];
    *(float4*)&vals[0] = *(const float4*)&row[t * 8];
    *(float4*)&vals[4] = *(const float4*)&row[t * 8 + 4];

    float vmax = vals[0];
    #pragma unroll
    for (int i = 1; i < 8; i++) vmax = fmaxf(vmax, vals[i]);
    red[t] = vmax; __syncthreads();
    #pragma unroll
    for (int s = 128; s > 0; s >>= 1) { if (t < s) red[t] = fmaxf(red[t], red[t + s]); __syncthreads(); }
    const float m = red[0]; __syncthreads();

    float sum = 0.f;
    #pragma unroll
    for (int i = 0; i < 8; i++) { vals[i] = expf(vals[i] - m); sum += vals[i]; }
    red[t] = sum; __syncthreads();
    #pragma unroll
    for (int s = 128; s > 0; s >>= 1) { if (t < s) red[t] += red[t + s]; __syncthreads(); }
    const float inv = 1.0f / red[0];

    __nv_bfloat16* ph = Ph + rowOff + t * 8;
    __nv_bfloat16* pl = Pl + rowOff + t * 8;
    #pragma unroll
    for (int i = 0; i < 8; i += 2) {
        float a = vals[i] * inv, b = vals[i + 1] * inv;
        __nv_bfloat16 ah, al, bh, bl;
        split2(a, ah, al); split2(b, bh, bl);
        *(__nv_bfloat162*)(ph + i) = __halves2bfloat162(ah, bh);
        *(__nv_bfloat162*)(pl + i) = __halves2bfloat162(al, bl);
    }
}

// ---------------------------------------------------------------------------
extern "C" void kernel_launch(void* const* d_in, const int* in_sizes, int n_in,
                              void* d_out, int out_size)
{
    const float* x  = (const float*)d_in[0];
    const float* Wq = (const float*)d_in[1];
    const float* bq = (const float*)d_in[2];
    const float* Wk = (const float*)d_in[3];
    const float* bk = (const float*)d_in[4];
    const float* Wv = (const float*)d_in[5];
    const float* bv = (const float*)d_in[6];
    float* out = (float*)d_out;

    cudaFuncSetAttribute(gemm_bs, cudaFuncAttributeMaxDynamicSharedMemorySize, GEMM_DSMEM);

    __nv_bfloat16 *xh, *xl, *wqh, *wql, *wkh, *wkl, *wvh, *wvl;
    __nv_bfloat16 *qh, *ql, *kh, *kl, *vth, *vtl, *prh, *prl;
    float *V, *S;
    cudaGetSymbolAddress((void**)&xh,  g_xh);   cudaGetSymbolAddress((void**)&xl,  g_xl);
    cudaGetSymbolAddress((void**)&wqh, g_Wqt_h);cudaGetSymbolAddress((void**)&wql, g_Wqt_l);
    cudaGetSymbolAddress((void**)&wkh, g_Wkt_h);cudaGetSymbolAddress((void**)&wkl, g_Wkt_l);
    cudaGetSymbolAddress((void**)&wvh, g_Wvt_h);cudaGetSymbolAddress((void**)&wvl, g_Wvt_l);
    cudaGetSymbolAddress((void**)&qh,  g_Qh);   cudaGetSymbolAddress((void**)&ql,  g_Ql);
    cudaGetSymbolAddress((void**)&kh,  g_Kh);   cudaGetSymbolAddress((void**)&kl,  g_Kl);
    cudaGetSymbolAddress((void**)&V,   g_V);
    cudaGetSymbolAddress((void**)&vth, g_Vth);  cudaGetSymbolAddress((void**)&vtl, g_Vtl);
    cudaGetSymbolAddress((void**)&S,   g_S);
    cudaGetSymbolAddress((void**)&prh, g_Ph);   cudaGetSymbolAddress((void**)&prl, g_Pl);

    // 1) split x -> bf16 hi/lo
    {
        size_t n4 = (size_t)MTOT * DIM / 4;
        split_f32<<<(unsigned)((n4 + 255) / 256), 256>>>(x, xh, xl, n4);
    }
    // 2) transpose+split weights: W[D, E] -> Wt[E, D]
    {
        dim3 g(DIM / 32, DIM / 32, 1);
        transpose_split<<<g, 256>>>(Wq, wqh, wql, DIM, DIM, 0, 0);
        transpose_split<<<g, 256>>>(Wk, wkh, wkl, DIM, DIM, 0, 0);
        transpose_split<<<g, 256>>>(Wv, wvh, wvl, DIM, DIM, 0, 0);
    }
    // 3) projections: Q,K -> bf16 splits; V -> fp32 (for transpose)
    {
        dim3 g(DIM / 256, MTOT / 128, 1);
        gemm_bs<<<g, 256, GEMM_DSMEM>>>(xh, xl, wqh, wql, bq, nullptr, qh, ql,
                                        MTOT, DIM, DIM, 0, 0, 0, 1.0f, 1);
        gemm_bs<<<g, 256, GEMM_DSMEM>>>(xh, xl, wkh, wkl, bk, nullptr, kh, kl,
                                        MTOT, DIM, DIM, 0, 0, 0, 1.0f, 1);
        gemm_bs<<<g, 256, GEMM_DSMEM>>>(xh, xl, wvh, wvl, bv, V, nullptr, nullptr,
                                        MTOT, DIM, DIM, 0, 0, 0, 1.0f, 1);
    }
    // 4) transpose+split V per batch: [SEQ, DIM] -> [DIM, SEQ]
    {
        dim3 g(DIM / 32, SEQ / 32, BATCH);
        transpose_split<<<g, 256>>>(V, vth, vtl, SEQ, DIM,
                                    (size_t)SEQ * DIM, (size_t)DIM * SEQ);
    }
    // 5) scores = scale * Q K^T per batch (fp32 out)
    {
        const float scale = 1.0f / sqrtf((float)DIM);
        dim3 g(SEQ / 256, SEQ / 128, BATCH);
        gemm_bs<<<g, 256, GEMM_DSMEM>>>(qh, ql, kh, kl, nullptr, S, nullptr, nullptr,
                                        SEQ, SEQ, DIM,
                                        (size_t)SEQ * DIM, (size_t)SEQ * DIM,
                                        (size_t)SEQ * SEQ, scale, 0);
    }
    // 6) softmax -> P bf16 splits
    softmax_split<<<BATCH * SEQ, 256>>>(S, prh, prl);

    // 7) out = P V per batch (fp32 out): A = P [SEQ, SEQ], B = Vt [DIM, SEQ]
    {
        dim3 g(DIM / 256, SEQ / 128, BATCH);
        gemm_bs<<<g, 256, GEMM_DSMEM>>>(prh, prl, vth, vtl, nullptr, out, nullptr, nullptr,
                                        SEQ, DIM, SEQ,
                                        (size_t)SEQ * SEQ, (size_t)DIM * SEQ,
                                        (size_t)SEQ * DIM, 1.0f, 0);
    }
}

// round 5
// speedup vs baseline: 1.0470x; 1.0470x over previous
#include <cuda_runtime.h>
#include <cuda_bf16.h>
#include <math.h>
#include <stdint.h>

#define BATCH 8
#define SEQ   2048
#define DIM   512
#define MTOT  (BATCH*SEQ)   // 16384

// ---------------------------------------------------------------------------
// Device scratch (allocation-free rule: __device__ globals)
// ---------------------------------------------------------------------------
__device__ __nv_bfloat16 g_xh[MTOT * DIM], g_xl[MTOT * DIM];
__device__ __nv_bfloat16 g_Wqt_h[DIM * DIM], g_Wqt_l[DIM * DIM];
__device__ __nv_bfloat16 g_Wkt_h[DIM * DIM], g_Wkt_l[DIM * DIM];
__device__ __nv_bfloat16 g_Wvt_h[DIM * DIM], g_Wvt_l[DIM * DIM];
__device__ __nv_bfloat16 g_Qh[MTOT * DIM], g_Ql[MTOT * DIM];
__device__ __nv_bfloat16 g_Kh[MTOT * DIM], g_Kl[MTOT * DIM];
__device__ float         g_V[MTOT * DIM];
__device__ __nv_bfloat16 g_Vth[MTOT * DIM], g_Vtl[MTOT * DIM];  // [B][DIM][SEQ]
__device__ float         g_S [(size_t)BATCH * SEQ * SEQ];
__device__ __nv_bfloat16 g_Ph[(size_t)BATCH * SEQ * SEQ];
__device__ __nv_bfloat16 g_Pl[(size_t)BATCH * SEQ * SEQ];

// ---------------------------------------------------------------------------
// Baseline-ISA helpers: ldmatrix / mma.sync / cp.async  (no 'a' features)
// ---------------------------------------------------------------------------
__device__ __forceinline__ uint32_t smem_to_u32(const void* p) {
    uint32_t a;
    asm("{ .reg .u64 t; cvta.to.shared.u64 t, %1; cvt.u32.u64 %0, t; }" : "=r"(a) : "l"(p));
    return a;
}
__device__ __forceinline__ void ldsm4(uint32_t* r, uint32_t addr) {
    asm volatile("ldmatrix.sync.aligned.m8n8.x4.shared.b16 {%0,%1,%2,%3}, [%4];"
                 : "=r"(r[0]), "=r"(r[1]), "=r"(r[2]), "=r"(r[3]) : "r"(addr));
}
__device__ __forceinline__ void mma_bf16(float* c, const uint32_t* a,
                                         uint32_t b0, uint32_t b1) {
    asm volatile("mma.sync.aligned.m16n8k16.row.col.f32.bf16.bf16.f32 "
                 "{%0,%1,%2,%3}, {%4,%5,%6,%7}, {%8,%9}, {%0,%1,%2,%3};"
                 : "+f"(c[0]), "+f"(c[1]), "+f"(c[2]), "+f"(c[3])
                 : "r"(a[0]), "r"(a[1]), "r"(a[2]), "r"(a[3]), "r"(b0), "r"(b1));
}
__device__ __forceinline__ void cp16(uint32_t dst, const void* src) {
    asm volatile("cp.async.cg.shared.global [%0], [%1], 16;" :: "r"(dst), "l"(src));
}
#define CP_COMMIT() asm volatile("cp.async.commit_group;" ::: "memory")
#define CP_WAIT1()  asm volatile("cp.async.wait_group 1;" ::: "memory")

__device__ __forceinline__ void split2(float a, __nv_bfloat16& h, __nv_bfloat16& l) {
    h = __float2bfloat16(a);
    l = __float2bfloat16(a - __bfloat162float(h));
}

// ---------------------------------------------------------------------------
// bf16-split HMMA GEMM:  C[M,N] = scale * (A[M,K] * B[N,K]^T) (+bias, relu)
// Block tile 128M x 128N, BK=32, 4 warps (2M x 2N) of 64x64 warp tiles.
// 2-stage cp.async pipeline, 80KB smem -> 2 CTAs/SM.
// smem rows padded to 80B ((row*5)%8 permutation -> conflict-free ldmatrix).
// ---------------------------------------------------------------------------
#define ROWB   80
#define T_B    (128 * ROWB)                // 10240 B per half-tile (A or B)
#define STAGEB (4 * T_B)                   // Ah, Al, Bh, Bl = 40960 B
#define GEMM_DSMEM (2 * STAGEB)            // 81920 B

__device__ __forceinline__ void issue_stage(uint32_t sAddr,
    const __nv_bfloat16* pAh, const __nv_bfloat16* pAl,
    const __nv_bfloat16* pBh, const __nv_bfloat16* pBl,
    int lda, int ldb, int k0, int t)
{
    // 2048 x 16B transfers, 128 threads -> 16 per thread
    const __nv_bfloat16* base[4] = { pAh, pAl, pBh, pBl };
    const int ld2[4] = { lda, lda, ldb, ldb };
    #pragma unroll
    for (int i = 0; i < 16; i++) {
        const int j    = t + i * 128;       // 0..2047
        const int tile = j >> 9;            // 0..3
        const int r    = (j & 511) >> 2;    // 0..127
        const int ch   = j & 3;
        const __nv_bfloat16* src = base[tile] + (size_t)r * ld2[tile] + k0 + ch * 8;
        cp16(sAddr + tile * T_B + r * ROWB + ch * 16, src);
    }
}

__global__ __launch_bounds__(128, 2)
void gemm_bs(const __nv_bfloat16* __restrict__ Ah, const __nv_bfloat16* __restrict__ Al,
             const __nv_bfloat16* __restrict__ Bh, const __nv_bfloat16* __restrict__ Bl,
             const float* __restrict__ bias,
             float* __restrict__ Cf,
             __nv_bfloat16* __restrict__ Ch, __nv_bfloat16* __restrict__ Cl,
             int M, int N, int K,
             size_t sA, size_t sB, size_t sC,
             float scale, int relu)
{
    extern __shared__ char smem[];
    const uint32_t sb = smem_to_u32(smem);

    const int t    = threadIdx.x;
    const int wid  = t >> 5;
    const int lane = t & 31;
    const int wm   = wid >> 1;          // 0..1 -> M (64-row slab)
    const int wn   = wid & 1;           // 0..1 -> N (64-col slab)

    const int z = blockIdx.z;
    const int rowBase = blockIdx.y * 128;
    const int colBase = blockIdx.x * 128;
    const int lda = K, ldb = K;

    const __nv_bfloat16* pAh = Ah + (size_t)z * sA + (size_t)rowBase * lda;
    const __nv_bfloat16* pAl = Al + (size_t)z * sA + (size_t)rowBase * lda;
    const __nv_bfloat16* pBh = Bh + (size_t)z * sB + (size_t)colBase * ldb;
    const __nv_bfloat16* pBl = Bl + (size_t)z * sB + (size_t)colBase * ldb;

    float acc[4][8][4];
    #pragma unroll
    for (int mi = 0; mi < 4; mi++)
        #pragma unroll
        for (int ni = 0; ni < 8; ni++)
            #pragma unroll
            for (int r = 0; r < 4; r++) acc[mi][ni][r] = 0.0f;

    const int nc = K / 32;

    issue_stage(sb, pAh, pAl, pBh, pBl, lda, ldb, 0, t);
    CP_COMMIT();

    // per-thread ldmatrix source geometry
    const int lrow = lane & 15;
    const uint32_t cSel = ((lane >> 4) & 1) * 16;

    for (int c = 0; c < nc; c++) {
        __syncthreads();   // buffer (c+1)&1 free (previous compute done)
        if (c + 1 < nc)
            issue_stage(sb + ((c + 1) & 1) * STAGEB, pAh, pAl, pBh, pBl,
                        lda, ldb, (c + 1) * 32, t);
        CP_COMMIT();       // constant group count (maybe-empty group)
        CP_WAIT1();        // stage c complete
        __syncthreads();

        const uint32_t st = sb + (c & 1) * STAGEB;
        #pragma unroll
        for (int ks = 0; ks < 2; ks++) {
            const uint32_t cb = ks * 32 + cSel;
            uint32_t ah[4][4], al[4][4];
            #pragma unroll
            for (int mi = 0; mi < 4; mi++) {
                const uint32_t ra = (uint32_t)(wm * 64 + mi * 16 + lrow) * ROWB + cb;
                ldsm4(ah[mi], st + ra);
                ldsm4(al[mi], st + T_B + ra);
            }
            #pragma unroll
            for (int g = 0; g < 4; g++) {   // 16-col N group -> n8 blocks 2g, 2g+1
                const uint32_t rb = (uint32_t)(wn * 64 + g * 16 + lrow) * ROWB + cb;
                uint32_t qh[4], ql[4];
                ldsm4(qh, st + 2 * T_B + rb);
                ldsm4(ql, st + 3 * T_B + rb);
                #pragma unroll
                for (int mi = 0; mi < 4; mi++) {
                    mma_bf16(acc[mi][2*g],   ah[mi], qh[0], qh[2]);
                    mma_bf16(acc[mi][2*g],   ah[mi], ql[0], ql[2]);
                    mma_bf16(acc[mi][2*g],   al[mi], qh[0], qh[2]);
                    mma_bf16(acc[mi][2*g+1], ah[mi], qh[1], qh[3]);
                    mma_bf16(acc[mi][2*g+1], ah[mi], ql[1], ql[3]);
                    mma_bf16(acc[mi][2*g+1], al[mi], qh[1], qh[3]);
                }
            }
        }
    }

    // ------------------------------ epilogue -------------------------------
    #pragma unroll
    for (int mi = 0; mi < 4; mi++) {
        #pragma unroll
        for (int rr = 0; rr < 2; rr++) {
            const int r = rowBase + wm * 64 + mi * 16 + rr * 8 + (lane >> 2);
            #pragma unroll
            for (int ni = 0; ni < 8; ni++) {
                const int cc = colBase + wn * 64 + ni * 8 + (lane & 3) * 2;
                float a = acc[mi][ni][rr * 2 + 0] * scale;
                float b = acc[mi][ni][rr * 2 + 1] * scale;
                if (bias) { a += bias[cc]; b += bias[cc + 1]; }
                if (relu) { a = fmaxf(a, 0.0f); b = fmaxf(b, 0.0f); }
                if (Cf) {
                    *(float2*)(Cf + (size_t)z * sC + (size_t)r * N + cc) = make_float2(a, b);
                } else {
                    __nv_bfloat16 hA, lA, hB, lB;
                    split2(a, hA, lA); split2(b, hB, lB);
                    *(__nv_bfloat162*)(Ch + (size_t)z * sC + (size_t)r * N + cc) =
                        __halves2bfloat162(hA, hB);
                    *(__nv_bfloat162*)(Cl + (size_t)z * sC + (size_t)r * N + cc) =
                        __halves2bfloat162(lA, lB);
                }
            }
        }
    }
}

// ---------------------------------------------------------------------------
// fp32 -> bf16 hi/lo elementwise split (for x)
// ---------------------------------------------------------------------------
__global__ __launch_bounds__(256)
void split_f32(const float* __restrict__ in, __nv_bfloat16* __restrict__ oh,
               __nv_bfloat16* __restrict__ ol, size_t n4)
{
    size_t i = (size_t)blockIdx.x * blockDim.x + threadIdx.x;
    if (i >= n4) return;
    float4 v = ((const float4*)in)[i];
    __nv_bfloat16 h0,l0,h1,l1,h2,l2,h3,l3;
    split2(v.x,h0,l0); split2(v.y,h1,l1); split2(v.z,h2,l2); split2(v.w,h3,l3);
    ((__nv_bfloat162*)oh)[2*i]   = __halves2bfloat162(h0,h1);
    ((__nv_bfloat162*)oh)[2*i+1] = __halves2bfloat162(h2,h3);
    ((__nv_bfloat162*)ol)[2*i]   = __halves2bfloat162(l0,l1);
    ((__nv_bfloat162*)ol)[2*i+1] = __halves2bfloat162(l2,l3);
}

// ---------------------------------------------------------------------------
// transpose + split: in fp32 [R,C] -> out bf16 hi/lo [C,R]   (z-batched)
// ---------------------------------------------------------------------------
__global__ __launch_bounds__(256)
void transpose_split(const float* __restrict__ in, __nv_bfloat16* __restrict__ oh,
                     __nv_bfloat16* __restrict__ ol, int R, int C,
                     size_t sIn, size_t sOut)
{
    __shared__ float tile[32][33];
    const int z = blockIdx.z;
    in += (size_t)z * sIn;  oh += (size_t)z * sOut;  ol += (size_t)z * sOut;
    const int c0 = blockIdx.x * 32, r0 = blockIdx.y * 32;
    const int tx = threadIdx.x & 31, ty = threadIdx.x >> 5;
    #pragma unroll
    for (int i = 0; i < 4; i++)
        tile[ty + i * 8][tx] = in[(size_t)(r0 + ty + i * 8) * C + c0 + tx];
    __syncthreads();
    #pragma unroll
    for (int i = 0; i < 4; i++) {
        const int ro = c0 + ty + i * 8;
        float v = tile[tx][ty + i * 8];
        __nv_bfloat16 h, l; split2(v, h, l);
        oh[(size_t)ro * R + r0 + tx] = h;
        ol[(size_t)ro * R + r0 + tx] = l;
    }
}

// ---------------------------------------------------------------------------
// Row softmax over 2048 cols; reads fp32 S, writes bf16 hi/lo splits of P.
// ---------------------------------------------------------------------------
__global__ __launch_bounds__(256)
void softmax_split(const float* __restrict__ S, __nv_bfloat16* __restrict__ Ph,
                   __nv_bfloat16* __restrict__ Pl)
{
    const size_t rowOff = (size_t)blockIdx.x * SEQ;
    const float* row = S + rowOff;
    const int t = threadIdx.x;
    __shared__ float red[8];

    float vals[8];
    *(float4*)&vals[0] = *(const float4*)&row[t * 8];
    *(float4*)&vals[4] = *(const float4*)&row[t * 8 + 4];

    float vmax = vals[0];
    #pragma unroll
    for (int i = 1; i < 8; i++) vmax = fmaxf(vmax, vals[i]);
    #pragma unroll
    for (int o = 16; o > 0; o >>= 1)
        vmax = fmaxf(vmax, __shfl_xor_sync(0xffffffffu, vmax, o));
    if ((t & 31) == 0) red[t >> 5] = vmax;
    __syncthreads();
    float m = red[0];
    #pragma unroll
    for (int i = 1; i < 8; i++) m = fmaxf(m, red[i]);
    __syncthreads();

    float sum = 0.f;
    #pragma unroll
    for (int i = 0; i < 8; i++) { vals[i] = expf(vals[i] - m); sum += vals[i]; }
    #pragma unroll
    for (int o = 16; o > 0; o >>= 1)
        sum += __shfl_xor_sync(0xffffffffu, sum, o);
    if ((t & 31) == 0) red[t >> 5] = sum;
    __syncthreads();
    float tot = red[0];
    #pragma unroll
    for (int i = 1; i < 8; i++) tot += red[i];
    const float inv = 1.0f / tot;

    __nv_bfloat16* ph = Ph + rowOff + t * 8;
    __nv_bfloat16* pl = Pl + rowOff + t * 8;
    #pragma unroll
    for (int i = 0; i < 8; i += 2) {
        float a = vals[i] * inv, b = vals[i + 1] * inv;
        __nv_bfloat16 ah, al, bh, bl;
        split2(a, ah, al); split2(b, bh, bl);
        *(__nv_bfloat162*)(ph + i) = __halves2bfloat162(ah, bh);
        *(__nv_bfloat162*)(pl + i) = __halves2bfloat162(al, bl);
    }
}

// ---------------------------------------------------------------------------
extern "C" void kernel_launch(void* const* d_in, const int* in_sizes, int n_in,
                              void* d_out, int out_size)
{
    const float* x  = (const float*)d_in[0];
    const float* Wq = (const float*)d_in[1];
    const float* bq = (const float*)d_in[2];
    const float* Wk = (const float*)d_in[3];
    const float* bk = (const float*)d_in[4];
    const float* Wv = (const float*)d_in[5];
    const float* bv = (const float*)d_in[6];
    float* out = (float*)d_out;

    cudaFuncSetAttribute(gemm_bs, cudaFuncAttributeMaxDynamicSharedMemorySize, GEMM_DSMEM);

    __nv_bfloat16 *xh, *xl, *wqh, *wql, *wkh, *wkl, *wvh, *wvl;
    __nv_bfloat16 *qh, *ql, *kh, *kl, *vth, *vtl, *prh, *prl;
    float *V, *S;
    cudaGetSymbolAddress((void**)&xh,  g_xh);   cudaGetSymbolAddress((void**)&xl,  g_xl);
    cudaGetSymbolAddress((void**)&wqh, g_Wqt_h);cudaGetSymbolAddress((void**)&wql, g_Wqt_l);
    cudaGetSymbolAddress((void**)&wkh, g_Wkt_h);cudaGetSymbolAddress((void**)&wkl, g_Wkt_l);
    cudaGetSymbolAddress((void**)&wvh, g_Wvt_h);cudaGetSymbolAddress((void**)&wvl, g_Wvt_l);
    cudaGetSymbolAddress((void**)&qh,  g_Qh);   cudaGetSymbolAddress((void**)&ql,  g_Ql);
    cudaGetSymbolAddress((void**)&kh,  g_Kh);   cudaGetSymbolAddress((void**)&kl,  g_Kl);
    cudaGetSymbolAddress((void**)&V,   g_V);
    cudaGetSymbolAddress((void**)&vth, g_Vth);  cudaGetSymbolAddress((void**)&vtl, g_Vtl);
    cudaGetSymbolAddress((void**)&S,   g_S);
    cudaGetSymbolAddress((void**)&prh, g_Ph);   cudaGetSymbolAddress((void**)&prl, g_Pl);

    // 1) split x -> bf16 hi/lo
    {
        size_t n4 = (size_t)MTOT * DIM / 4;
        split_f32<<<(unsigned)((n4 + 255) / 256), 256>>>(x, xh, xl, n4);
    }
    // 2) transpose+split weights: W[D, E] -> Wt[E, D]
    {
        dim3 g(DIM / 32, DIM / 32, 1);
        transpose_split<<<g, 256>>>(Wq, wqh, wql, DIM, DIM, 0, 0);
        transpose_split<<<g, 256>>>(Wk, wkh, wkl, DIM, DIM, 0, 0);
        transpose_split<<<g, 256>>>(Wv, wvh, wvl, DIM, DIM, 0, 0);
    }
    // 3) projections: Q,K -> bf16 splits; V -> fp32 (for transpose)
    {
        dim3 g(DIM / 128, MTOT / 128, 1);
        gemm_bs<<<g, 128, GEMM_DSMEM>>>(xh, xl, wqh, wql, bq, nullptr, qh, ql,
                                        MTOT, DIM, DIM, 0, 0, 0, 1.0f, 1);
        gemm_bs<<<g, 128, GEMM_DSMEM>>>(xh, xl, wkh, wkl, bk, nullptr, kh, kl,
                                        MTOT, DIM, DIM, 0, 0, 0, 1.0f, 1);
        gemm_bs<<<g, 128, GEMM_DSMEM>>>(xh, xl, wvh, wvl, bv, V, nullptr, nullptr,
                                        MTOT, DIM, DIM, 0, 0, 0, 1.0f, 1);
    }
    // 4) transpose+split V per batch: [SEQ, DIM] -> [DIM, SEQ]
    {
        dim3 g(DIM / 32, SEQ / 32, BATCH);
        transpose_split<<<g, 256>>>(V, vth, vtl, SEQ, DIM,
                                    (size_t)SEQ * DIM, (size_t)DIM * SEQ);
    }
    // 5) scores = scale * Q K^T per batch (fp32 out)
    {
        const float scale = 1.0f / sqrtf((float)DIM);
        dim3 g(SEQ / 128, SEQ / 128, BATCH);
        gemm_bs<<<g, 128, GEMM_DSMEM>>>(qh, ql, kh, kl, nullptr, S, nullptr, nullptr,
                                        SEQ, SEQ, DIM,
                                        (size_t)SEQ * DIM, (size_t)SEQ * DIM,
                                        (size_t)SEQ * SEQ, scale, 0);
    }
    // 6) softmax -> P bf16 splits
    softmax_split<<<BATCH * SEQ, 256>>>(S, prh, prl);

    // 7) out = P V per batch (fp32 out): A = P [SEQ, SEQ], B = Vt [DIM, SEQ]
    {
        dim3 g(DIM / 128, SEQ / 128, BATCH);
        gemm_bs<<<g, 128, GEMM_DSMEM>>>(prh, prl, vth, vtl, nullptr, out, nullptr, nullptr,
                                        SEQ, DIM, SEQ,
                                        (size_t)SEQ * SEQ, (size_t)DIM * SEQ,
                                        (size_t)SEQ * DIM, 1.0f, 0);
    }
}

// round 6
// speedup vs baseline: 1.1640x; 1.1118x over previous
#include <cuda_runtime.h>
#include <cuda_bf16.h>
#include <math.h>
#include <stdint.h>

#define BATCH 8
#define SEQ   2048
#define DIM   512
#define MTOT  (BATCH*SEQ)   // 16384

// ---------------------------------------------------------------------------
// Device scratch (allocation-free rule: __device__ globals)
// ---------------------------------------------------------------------------
__device__ __nv_bfloat16 g_xh[MTOT * DIM], g_xl[MTOT * DIM];
__device__ __nv_bfloat16 g_Wqt_h[DIM * DIM], g_Wqt_l[DIM * DIM];
__device__ __nv_bfloat16 g_Wkt_h[DIM * DIM], g_Wkt_l[DIM * DIM];
__device__ __nv_bfloat16 g_Wvt_h[DIM * DIM], g_Wvt_l[DIM * DIM];
__device__ __nv_bfloat16 g_Qh[MTOT * DIM], g_Ql[MTOT * DIM];
__device__ __nv_bfloat16 g_Kh[MTOT * DIM], g_Kl[MTOT * DIM];
__device__ float         g_V[MTOT * DIM];
__device__ __nv_bfloat16 g_Vth[MTOT * DIM], g_Vtl[MTOT * DIM];  // [B][DIM][SEQ]
__device__ float         g_S [(size_t)BATCH * SEQ * SEQ];
__device__ __nv_bfloat16 g_Ph[(size_t)BATCH * SEQ * SEQ];
__device__ __nv_bfloat16 g_Pl[(size_t)BATCH * SEQ * SEQ];

// ---------------------------------------------------------------------------
// Baseline-ISA helpers: ldmatrix / mma.sync / cp.async  (no 'a' features)
// ---------------------------------------------------------------------------
__device__ __forceinline__ uint32_t smem_to_u32(const void* p) {
    uint32_t a;
    asm("{ .reg .u64 t; cvta.to.shared.u64 t, %1; cvt.u32.u64 %0, t; }" : "=r"(a) : "l"(p));
    return a;
}
__device__ __forceinline__ void ldsm4(uint32_t* r, uint32_t addr) {
    asm volatile("ldmatrix.sync.aligned.m8n8.x4.shared.b16 {%0,%1,%2,%3}, [%4];"
                 : "=r"(r[0]), "=r"(r[1]), "=r"(r[2]), "=r"(r[3]) : "r"(addr));
}
__device__ __forceinline__ void mma_bf16(float* c, const uint32_t* a,
                                         uint32_t b0, uint32_t b1) {
    asm volatile("mma.sync.aligned.m16n8k16.row.col.f32.bf16.bf16.f32 "
                 "{%0,%1,%2,%3}, {%4,%5,%6,%7}, {%8,%9}, {%0,%1,%2,%3};"
                 : "+f"(c[0]), "+f"(c[1]), "+f"(c[2]), "+f"(c[3])
                 : "r"(a[0]), "r"(a[1]), "r"(a[2]), "r"(a[3]), "r"(b0), "r"(b1));
}
__device__ __forceinline__ void cp16(uint32_t dst, const void* src) {
    asm volatile("cp.async.cg.shared.global [%0], [%1], 16;" :: "r"(dst), "l"(src));
}
#define CP_COMMIT() asm volatile("cp.async.commit_group;" ::: "memory")
#define CP_WAIT1()  asm volatile("cp.async.wait_group 1;" ::: "memory")

__device__ __forceinline__ void split2(float a, __nv_bfloat16& h, __nv_bfloat16& l) {
    h = __float2bfloat16(a);
    l = __float2bfloat16(a - __bfloat162float(h));
}

// ---------------------------------------------------------------------------
// bf16-split HMMA GEMM:  C[M,N] = scale * (A[M,K] * B[N,K]^T) (+bias, relu)
// Block tile 128M x 128N, BK=32, 4 warps (2M x 2N) of 64x64 warp tiles.
// 3-stage cp.async pipeline, single __syncthreads per chunk, 96KB smem
// -> 2 CTAs/SM. 64B rows with XOR swizzle (chunk ^= row&3): conflict-free
// for both cp.async stores and ldmatrix phases.
// ---------------------------------------------------------------------------
#define T_B    (128 * 64)                  // 8192 B per half-tile (A or B)
#define STAGEB (4 * T_B)                   // Ah, Al, Bh, Bl = 32768 B
#define NSTAGE 3
#define GEMM_DSMEM (NSTAGE * STAGEB)       // 98304 B

__device__ __forceinline__ void issue_stage(uint32_t sAddr,
    const __nv_bfloat16* pAh, const __nv_bfloat16* pAl,
    const __nv_bfloat16* pBh, const __nv_bfloat16* pBl,
    int lda, int ldb, int k0, int t)
{
    // 2048 x 16B transfers, 128 threads -> 16 per thread
    const __nv_bfloat16* base[4] = { pAh, pAl, pBh, pBl };
    const int ld2[4] = { lda, lda, ldb, ldb };
    #pragma unroll
    for (int i = 0; i < 16; i++) {
        const int j    = t + i * 128;       // 0..2047
        const int tile = j >> 9;            // 0..3
        const int r    = (j & 511) >> 2;    // 0..127
        const int ch   = j & 3;
        const __nv_bfloat16* src = base[tile] + (size_t)r * ld2[tile] + k0 + ch * 8;
        cp16(sAddr + tile * T_B + r * 64 + ((ch ^ (r & 3)) << 4), src);
    }
}

__global__ __launch_bounds__(128, 2)
void gemm_bs(const __nv_bfloat16* __restrict__ Ah, const __nv_bfloat16* __restrict__ Al,
             const __nv_bfloat16* __restrict__ Bh, const __nv_bfloat16* __restrict__ Bl,
             const float* __restrict__ bias,
             float* __restrict__ Cf,
             __nv_bfloat16* __restrict__ Ch, __nv_bfloat16* __restrict__ Cl,
             int M, int N, int K,
             size_t sA, size_t sB, size_t sC,
             float scale, int relu)
{
    extern __shared__ char smem[];
    const uint32_t sb = smem_to_u32(smem);

    const int t    = threadIdx.x;
    const int wid  = t >> 5;
    const int lane = t & 31;
    const int wm   = wid >> 1;          // 0..1 -> M (64-row slab)
    const int wn   = wid & 1;           // 0..1 -> N (64-col slab)

    const int z = blockIdx.z;
    const int rowBase = blockIdx.y * 128;
    const int colBase = blockIdx.x * 128;
    const int lda = K, ldb = K;

    const __nv_bfloat16* pAh = Ah + (size_t)z * sA + (size_t)rowBase * lda;
    const __nv_bfloat16* pAl = Al + (size_t)z * sA + (size_t)rowBase * lda;
    const __nv_bfloat16* pBh = Bh + (size_t)z * sB + (size_t)colBase * ldb;
    const __nv_bfloat16* pBl = Bl + (size_t)z * sB + (size_t)colBase * ldb;

    float acc[4][8][4];
    #pragma unroll
    for (int mi = 0; mi < 4; mi++)
        #pragma unroll
        for (int ni = 0; ni < 8; ni++)
            #pragma unroll
            for (int r = 0; r < 4; r++) acc[mi][ni][r] = 0.0f;

    const int nc = K / 32;

    issue_stage(sb,          pAh, pAl, pBh, pBl, lda, ldb,  0, t); CP_COMMIT();
    issue_stage(sb + STAGEB, pAh, pAl, pBh, pBl, lda, ldb, 32, t); CP_COMMIT();

    // per-thread ldmatrix source geometry
    const int lrow = lane & 15;
    const int cS   = (lane >> 4) & 1;   // 16B chunk select within 32B k-slice

    for (int c = 0; c < nc; c++) {
        CP_WAIT1();        // own groups: stage c complete (c+1 may be in flight)
        __syncthreads();   // all threads waited -> stage c fully visible;
                           // all warps done computing c-1 -> buffer (c+2)%3 free
        if (c + 2 < nc)
            issue_stage(sb + ((c + 2) % NSTAGE) * STAGEB, pAh, pAl, pBh, pBl,
                        lda, ldb, (c + 2) * 32, t);
        CP_COMMIT();       // constant group count (maybe-empty group)

        const uint32_t st = sb + (c % NSTAGE) * STAGEB;
        #pragma unroll
        for (int ks = 0; ks < 2; ks++) {
            const int chunk = ks * 2 + cS;
            uint32_t ah[4][4], al[4][4];
            #pragma unroll
            for (int mi = 0; mi < 4; mi++) {
                const int rowA = wm * 64 + mi * 16 + lrow;
                const uint32_t offA = (uint32_t)rowA * 64 + (uint32_t)((chunk ^ (rowA & 3)) << 4);
                ldsm4(ah[mi], st + offA);
                ldsm4(al[mi], st + T_B + offA);
            }
            #pragma unroll
            for (int g = 0; g < 4; g++) {   // 16-col N group -> n8 blocks 2g, 2g+1
                const int rowB = wn * 64 + g * 16 + lrow;
                const uint32_t offB = (uint32_t)rowB * 64 + (uint32_t)((chunk ^ (rowB & 3)) << 4);
                uint32_t qh[4], ql[4];
                ldsm4(qh, st + 2 * T_B + offB);
                ldsm4(ql, st + 3 * T_B + offB);
                #pragma unroll
                for (int mi = 0; mi < 4; mi++) {
                    mma_bf16(acc[mi][2*g],   ah[mi], qh[0], qh[2]);
                    mma_bf16(acc[mi][2*g],   ah[mi], ql[0], ql[2]);
                    mma_bf16(acc[mi][2*g],   al[mi], qh[0], qh[2]);
                    mma_bf16(acc[mi][2*g+1], ah[mi], qh[1], qh[3]);
                    mma_bf16(acc[mi][2*g+1], ah[mi], ql[1], ql[3]);
                    mma_bf16(acc[mi][2*g+1], al[mi], qh[1], qh[3]);
                }
            }
        }
    }

    // ------------------------------ epilogue -------------------------------
    #pragma unroll
    for (int mi = 0; mi < 4; mi++) {
        #pragma unroll
        for (int rr = 0; rr < 2; rr++) {
            const int r = rowBase + wm * 64 + mi * 16 + rr * 8 + (lane >> 2);
            #pragma unroll
            for (int ni = 0; ni < 8; ni++) {
                const int cc = colBase + wn * 64 + ni * 8 + (lane & 3) * 2;
                float a = acc[mi][ni][rr * 2 + 0] * scale;
                float b = acc[mi][ni][rr * 2 + 1] * scale;
                if (bias) { a += bias[cc]; b += bias[cc + 1]; }
                if (relu) { a = fmaxf(a, 0.0f); b = fmaxf(b, 0.0f); }
                if (Cf) {
                    *(float2*)(Cf + (size_t)z * sC + (size_t)r * N + cc) = make_float2(a, b);
                } else {
                    __nv_bfloat16 hA, lA, hB, lB;
                    split2(a, hA, lA); split2(b, hB, lB);
                    *(__nv_bfloat162*)(Ch + (size_t)z * sC + (size_t)r * N + cc) =
                        __halves2bfloat162(hA, hB);
                    *(__nv_bfloat162*)(Cl + (size_t)z * sC + (size_t)r * N + cc) =
                        __halves2bfloat162(lA, lB);
                }
            }
        }
    }
}

// ---------------------------------------------------------------------------
// fp32 -> bf16 hi/lo elementwise split (for x)
// ---------------------------------------------------------------------------
__global__ __launch_bounds__(256)
void split_f32(const float* __restrict__ in, __nv_bfloat16* __restrict__ oh,
               __nv_bfloat16* __restrict__ ol, size_t n4)
{
    size_t i = (size_t)blockIdx.x * blockDim.x + threadIdx.x;
    if (i >= n4) return;
    float4 v = ((const float4*)in)[i];
    __nv_bfloat16 h0,l0,h1,l1,h2,l2,h3,l3;
    split2(v.x,h0,l0); split2(v.y,h1,l1); split2(v.z,h2,l2); split2(v.w,h3,l3);
    ((__nv_bfloat162*)oh)[2*i]   = __halves2bfloat162(h0,h1);
    ((__nv_bfloat162*)oh)[2*i+1] = __halves2bfloat162(h2,h3);
    ((__nv_bfloat162*)ol)[2*i]   = __halves2bfloat162(l0,l1);
    ((__nv_bfloat162*)ol)[2*i+1] = __halves2bfloat162(l2,l3);
}

// ---------------------------------------------------------------------------
// transpose + split: in fp32 [R,C] -> out bf16 hi/lo [C,R]   (z-batched)
// ---------------------------------------------------------------------------
__global__ __launch_bounds__(256)
void transpose_split(const float* __restrict__ in, __nv_bfloat16* __restrict__ oh,
                     __nv_bfloat16* __restrict__ ol, int R, int C,
                     size_t sIn, size_t sOut)
{
    __shared__ float tile[32][33];
    const int z = blockIdx.z;
    in += (size_t)z * sIn;  oh += (size_t)z * sOut;  ol += (size_t)z * sOut;
    const int c0 = blockIdx.x * 32, r0 = blockIdx.y * 32;
    const int tx = threadIdx.x & 31, ty = threadIdx.x >> 5;
    #pragma unroll
    for (int i = 0; i < 4; i++)
        tile[ty + i * 8][tx] = in[(size_t)(r0 + ty + i * 8) * C + c0 + tx];
    __syncthreads();
    #pragma unroll
    for (int i = 0; i < 4; i++) {
        const int ro = c0 + ty + i * 8;
        float v = tile[tx][ty + i * 8];
        __nv_bfloat16 h, l; split2(v, h, l);
        oh[(size_t)ro * R + r0 + tx] = h;
        ol[(size_t)ro * R + r0 + tx] = l;
    }
}

// ---------------------------------------------------------------------------
// Row softmax over 2048 cols; reads fp32 S, writes bf16 hi/lo splits of P.
// ---------------------------------------------------------------------------
__global__ __launch_bounds__(256)
void softmax_split(const float* __restrict__ S, __nv_bfloat16* __restrict__ Ph,
                   __nv_bfloat16* __restrict__ Pl)
{
    const size_t rowOff = (size_t)blockIdx.x * SEQ;
    const float* row = S + rowOff;
    const int t = threadIdx.x;
    __shared__ float red[8];

    float vals[8];
    *(float4*)&vals[0] = *(const float4*)&row[t * 8];
    *(float4*)&vals[4] = *(const float4*)&row[t * 8 + 4];

    float vmax = vals[0];
    #pragma unroll
    for (int i = 1; i < 8; i++) vmax = fmaxf(vmax, vals[i]);
    #pragma unroll
    for (int o = 16; o > 0; o >>= 1)
        vmax = fmaxf(vmax, __shfl_xor_sync(0xffffffffu, vmax, o));
    if ((t & 31) == 0) red[t >> 5] = vmax;
    __syncthreads();
    float m = red[0];
    #pragma unroll
    for (int i = 1; i < 8; i++) m = fmaxf(m, red[i]);
    __syncthreads();

    float sum = 0.f;
    #pragma unroll
    for (int i = 0; i < 8; i++) { vals[i] = expf(vals[i] - m); sum += vals[i]; }
    #pragma unroll
    for (int o = 16; o > 0; o >>= 1)
        sum += __shfl_xor_sync(0xffffffffu, sum, o);
    if ((t & 31) == 0) red[t >> 5] = sum;
    __syncthreads();
    float tot = red[0];
    #pragma unroll
    for (int i = 1; i < 8; i++) tot += red[i];
    const float inv = 1.0f / tot;

    __nv_bfloat16* ph = Ph + rowOff + t * 8;
    __nv_bfloat16* pl = Pl + rowOff + t * 8;
    #pragma unroll
    for (int i = 0; i < 8; i += 2) {
        float a = vals[i] * inv, b = vals[i + 1] * inv;
        __nv_bfloat16 ah, al, bh, bl;
        split2(a, ah, al); split2(b, bh, bl);
        *(__nv_bfloat162*)(ph + i) = __halves2bfloat162(ah, bh);
        *(__nv_bfloat162*)(pl + i) = __halves2bfloat162(al, bl);
    }
}

// ---------------------------------------------------------------------------
extern "C" void kernel_launch(void* const* d_in, const int* in_sizes, int n_in,
                              void* d_out, int out_size)
{
    const float* x  = (const float*)d_in[0];
    const float* Wq = (const float*)d_in[1];
    const float* bq = (const float*)d_in[2];
    const float* Wk = (const float*)d_in[3];
    const float* bk = (const float*)d_in[4];
    const float* Wv = (const float*)d_in[5];
    const float* bv = (const float*)d_in[6];
    float* out = (float*)d_out;

    cudaFuncSetAttribute(gemm_bs, cudaFuncAttributeMaxDynamicSharedMemorySize, GEMM_DSMEM);

    __nv_bfloat16 *xh, *xl, *wqh, *wql, *wkh, *wkl, *wvh, *wvl;
    __nv_bfloat16 *qh, *ql, *kh, *kl, *vth, *vtl, *prh, *prl;
    float *V, *S;
    cudaGetSymbolAddress((void**)&xh,  g_xh);   cudaGetSymbolAddress((void**)&xl,  g_xl);
    cudaGetSymbolAddress((void**)&wqh, g_Wqt_h);cudaGetSymbolAddress((void**)&wql, g_Wqt_l);
    cudaGetSymbolAddress((void**)&wkh, g_Wkt_h);cudaGetSymbolAddress((void**)&wkl, g_Wkt_l);
    cudaGetSymbolAddress((void**)&wvh, g_Wvt_h);cudaGetSymbolAddress((void**)&wvl, g_Wvt_l);
    cudaGetSymbolAddress((void**)&qh,  g_Qh);   cudaGetSymbolAddress((void**)&ql,  g_Ql);
    cudaGetSymbolAddress((void**)&kh,  g_Kh);   cudaGetSymbolAddress((void**)&kl,  g_Kl);
    cudaGetSymbolAddress((void**)&V,   g_V);
    cudaGetSymbolAddress((void**)&vth, g_Vth);  cudaGetSymbolAddress((void**)&vtl, g_Vtl);
    cudaGetSymbolAddress((void**)&S,   g_S);
    cudaGetSymbolAddress((void**)&prh, g_Ph);   cudaGetSymbolAddress((void**)&prl, g_Pl);

    // 1) split x -> bf16 hi/lo
    {
        size_t n4 = (size_t)MTOT * DIM / 4;
        split_f32<<<(unsigned)((n4 + 255) / 256), 256>>>(x, xh, xl, n4);
    }
    // 2) transpose+split weights: W[D, E] -> Wt[E, D]
    {
        dim3 g(DIM / 32, DIM / 32, 1);
        transpose_split<<<g, 256>>>(Wq, wqh, wql, DIM, DIM, 0, 0);
        transpose_split<<<g, 256>>>(Wk, wkh, wkl, DIM, DIM, 0, 0);
        transpose_split<<<g, 256>>>(Wv, wvh, wvl, DIM, DIM, 0, 0);
    }
    // 3) projections: Q,K -> bf16 splits; V -> fp32 (for transpose)
    {
        dim3 g(DIM / 128, MTOT / 128, 1);
        gemm_bs<<<g, 128, GEMM_DSMEM>>>(xh, xl, wqh, wql, bq, nullptr, qh, ql,
                                        MTOT, DIM, DIM, 0, 0, 0, 1.0f, 1);
        gemm_bs<<<g, 128, GEMM_DSMEM>>>(xh, xl, wkh, wkl, bk, nullptr, kh, kl,
                                        MTOT, DIM, DIM, 0, 0, 0, 1.0f, 1);
        gemm_bs<<<g, 128, GEMM_DSMEM>>>(xh, xl, wvh, wvl, bv, V, nullptr, nullptr,
                                        MTOT, DIM, DIM, 0, 0, 0, 1.0f, 1);
    }
    // 4) transpose+split V per batch: [SEQ, DIM] -> [DIM, SEQ]
    {
        dim3 g(DIM / 32, SEQ / 32, BATCH);
        transpose_split<<<g, 256>>>(V, vth, vtl, SEQ, DIM,
                                    (size_t)SEQ * DIM, (size_t)DIM * SEQ);
    }
    // 5) scores = scale * Q K^T per batch (fp32 out)
    {
        const float scale = 1.0f / sqrtf((float)DIM);
        dim3 g(SEQ / 128, SEQ / 128, BATCH);
        gemm_bs<<<g, 128, GEMM_DSMEM>>>(qh, ql, kh, kl, nullptr, S, nullptr, nullptr,
                                        SEQ, SEQ, DIM,
                                        (size_t)SEQ * DIM, (size_t)SEQ * DIM,
                                        (size_t)SEQ * SEQ, scale, 0);
    }
    // 6) softmax -> P bf16 splits
    softmax_split<<<BATCH * SEQ, 256>>>(S, prh, prl);

    // 7) out = P V per batch (fp32 out): A = P [SEQ, SEQ], B = Vt [DIM, SEQ]
    {
        dim3 g(DIM / 128, SEQ / 128, BATCH);
        gemm_bs<<<g, 128, GEMM_DSMEM>>>(prh, prl, vth, vtl, nullptr, out, nullptr, nullptr,
                                        SEQ, DIM, SEQ,
                                        (size_t)SEQ * SEQ, (size_t)DIM * SEQ,
                                        (size_t)SEQ * DIM, 1.0f, 0);
    }
}

// round 7
// speedup vs baseline: 1.2573x; 1.0802x over previous
#include <cuda_runtime.h>
#include <cuda_bf16.h>
#include <math.h>
#include <stdint.h>

#define BATCH 8
#define SEQ   2048
#define DIM   512
#define MTOT  (BATCH*SEQ)   // 16384

// ---------------------------------------------------------------------------
// Device scratch (allocation-free rule: __device__ globals)
// ---------------------------------------------------------------------------
__device__ __nv_bfloat16 g_xh[MTOT * DIM], g_xl[MTOT * DIM];
__device__ __nv_bfloat16 g_Wqt_h[DIM * DIM], g_Wqt_l[DIM * DIM];
__device__ __nv_bfloat16 g_Wkt_h[DIM * DIM], g_Wkt_l[DIM * DIM];
__device__ __nv_bfloat16 g_Wvt_h[DIM * DIM], g_Wvt_l[DIM * DIM];
__device__ __nv_bfloat16 g_Qh[MTOT * DIM], g_Ql[MTOT * DIM];
__device__ __nv_bfloat16 g_Kh[MTOT * DIM], g_Kl[MTOT * DIM];
__device__ float         g_V[MTOT * DIM];
__device__ __nv_bfloat16 g_Vth[MTOT * DIM];                     // [B][DIM][SEQ]
__device__ float         g_S [(size_t)BATCH * SEQ * SEQ];
__device__ __nv_bfloat16 g_Ph[(size_t)BATCH * SEQ * SEQ];
__device__ __nv_bfloat16 g_Pl[(size_t)BATCH * SEQ * SEQ];

// ---------------------------------------------------------------------------
// Baseline-ISA helpers: ldmatrix / mma.sync / cp.async  (no 'a' features)
// ---------------------------------------------------------------------------
__device__ __forceinline__ uint32_t smem_to_u32(const void* p) {
    uint32_t a;
    asm("{ .reg .u64 t; cvta.to.shared.u64 t, %1; cvt.u32.u64 %0, t; }" : "=r"(a) : "l"(p));
    return a;
}
__device__ __forceinline__ void ldsm4(uint32_t* r, uint32_t addr) {
    asm volatile("ldmatrix.sync.aligned.m8n8.x4.shared.b16 {%0,%1,%2,%3}, [%4];"
                 : "=r"(r[0]), "=r"(r[1]), "=r"(r[2]), "=r"(r[3]) : "r"(addr));
}
__device__ __forceinline__ void mma_bf16(float* c, const uint32_t* a,
                                         uint32_t b0, uint32_t b1) {
    asm volatile("mma.sync.aligned.m16n8k16.row.col.f32.bf16.bf16.f32 "
                 "{%0,%1,%2,%3}, {%4,%5,%6,%7}, {%8,%9}, {%0,%1,%2,%3};"
                 : "+f"(c[0]), "+f"(c[1]), "+f"(c[2]), "+f"(c[3])
                 : "r"(a[0]), "r"(a[1]), "r"(a[2]), "r"(a[3]), "r"(b0), "r"(b1));
}
__device__ __forceinline__ void cp16(uint32_t dst, const void* src) {
    asm volatile("cp.async.cg.shared.global [%0], [%1], 16;" :: "r"(dst), "l"(src));
}
#define CP_COMMIT() asm volatile("cp.async.commit_group;" ::: "memory")
#define CP_WAIT1()  asm volatile("cp.async.wait_group 1;" ::: "memory")

__device__ __forceinline__ void split2(float a, __nv_bfloat16& h, __nv_bfloat16& l) {
    h = __float2bfloat16(a);
    l = __float2bfloat16(a - __bfloat162float(h));
}

// ---------------------------------------------------------------------------
// bf16-split HMMA GEMM:  C[M,N] = scale * (A[M,K] * B[N,K]^T) (+bias, relu)
// Block tile 128M x 128N, BK=32, 4 warps (2M x 2N) of 64x64 warp tiles.
// 3-stage cp.async pipeline, single __syncthreads per chunk, 2 CTAs/SM.
// 64B rows with XOR swizzle (chunk ^= row&3).
// BLO template: true = 3-term split (A hi/lo x B hi/lo minus lo*lo);
//               false = 2-term (A hi/lo x B hi only), B lo tile absent.
// ---------------------------------------------------------------------------
#define T_B    (128 * 64)                  // 8192 B per half-tile (A or B)
#define NSTAGE 3

template<bool BLO>
__device__ __forceinline__ void issue_stage(uint32_t sAddr,
    const __nv_bfloat16* pAh, const __nv_bfloat16* pAl,
    const __nv_bfloat16* pBh, const __nv_bfloat16* pBl,
    int lda, int ldb, int k0, int t)
{
    const int NT = BLO ? 4 : 3;
    const __nv_bfloat16* base[4] = { pAh, pAl, pBh, pBl };
    const int ld2[4] = { lda, lda, ldb, ldb };
    #pragma unroll
    for (int i = 0; i < NT * 4; i++) {      // NT*512 transfers / 128 threads
        const int j    = t + i * 128;
        const int tile = j >> 9;            // 0..NT-1
        const int r    = (j & 511) >> 2;    // 0..127
        const int ch   = j & 3;
        const __nv_bfloat16* src = base[tile] + (size_t)r * ld2[tile] + k0 + ch * 8;
        cp16(sAddr + tile * T_B + r * 64 + ((ch ^ (r & 3)) << 4), src);
    }
}

template<bool BLO>
__global__ __launch_bounds__(128, 2)
void gemm_bs(const __nv_bfloat16* __restrict__ Ah, const __nv_bfloat16* __restrict__ Al,
             const __nv_bfloat16* __restrict__ Bh, const __nv_bfloat16* __restrict__ Bl,
             const float* __restrict__ bias,
             float* __restrict__ Cf,
             __nv_bfloat16* __restrict__ Ch, __nv_bfloat16* __restrict__ Cl,
             int M, int N, int K,
             size_t sA, size_t sB, size_t sC,
             float scale, int relu)
{
    extern __shared__ char smem[];
    const uint32_t sb = smem_to_u32(smem);
    const uint32_t STAGEB = (BLO ? 4 : 3) * T_B;

    const int t    = threadIdx.x;
    const int wid  = t >> 5;
    const int lane = t & 31;
    const int wm   = wid >> 1;          // 0..1 -> M (64-row slab)
    const int wn   = wid & 1;           // 0..1 -> N (64-col slab)

    const int z = blockIdx.z;
    const int rowBase = blockIdx.y * 128;
    const int colBase = blockIdx.x * 128;
    const int lda = K, ldb = K;

    const __nv_bfloat16* pAh = Ah + (size_t)z * sA + (size_t)rowBase * lda;
    const __nv_bfloat16* pAl = Al + (size_t)z * sA + (size_t)rowBase * lda;
    const __nv_bfloat16* pBh = Bh + (size_t)z * sB + (size_t)colBase * ldb;
    const __nv_bfloat16* pBl = BLO ? (Bl + (size_t)z * sB + (size_t)colBase * ldb) : nullptr;

    float acc[4][8][4];
    #pragma unroll
    for (int mi = 0; mi < 4; mi++)
        #pragma unroll
        for (int ni = 0; ni < 8; ni++)
            #pragma unroll
            for (int r = 0; r < 4; r++) acc[mi][ni][r] = 0.0f;

    const int nc = K / 32;

    issue_stage<BLO>(sb,          pAh, pAl, pBh, pBl, lda, ldb,  0, t); CP_COMMIT();
    issue_stage<BLO>(sb + STAGEB, pAh, pAl, pBh, pBl, lda, ldb, 32, t); CP_COMMIT();

    const int lrow = lane & 15;
    const int cS   = (lane >> 4) & 1;   // 16B chunk select within 32B k-slice

    for (int c = 0; c < nc; c++) {
        CP_WAIT1();        // own groups: stage c complete (c+1 may be in flight)
        __syncthreads();   // stage c visible to all; buffer (c+2)%3 free
        if (c + 2 < nc)
            issue_stage<BLO>(sb + ((c + 2) % NSTAGE) * STAGEB, pAh, pAl, pBh, pBl,
                             lda, ldb, (c + 2) * 32, t);
        CP_COMMIT();       // constant group count (maybe-empty group)

        const uint32_t st = sb + (c % NSTAGE) * STAGEB;
        #pragma unroll
        for (int ks = 0; ks < 2; ks++) {
            const int chunk = ks * 2 + cS;
            uint32_t ah[4][4], al[4][4];
            #pragma unroll
            for (int mi = 0; mi < 4; mi++) {
                const int rowA = wm * 64 + mi * 16 + lrow;
                const uint32_t offA = (uint32_t)rowA * 64 + (uint32_t)((chunk ^ (rowA & 3)) << 4);
                ldsm4(ah[mi], st + offA);
                ldsm4(al[mi], st + T_B + offA);
            }
            #pragma unroll
            for (int g = 0; g < 4; g++) {   // 16-col N group -> n8 blocks 2g, 2g+1
                const int rowB = wn * 64 + g * 16 + lrow;
                const uint32_t offB = (uint32_t)rowB * 64 + (uint32_t)((chunk ^ (rowB & 3)) << 4);
                uint32_t qh[4], ql[4];
                ldsm4(qh, st + 2 * T_B + offB);
                if (BLO) ldsm4(ql, st + 3 * T_B + offB);
                #pragma unroll
                for (int mi = 0; mi < 4; mi++) {
                    mma_bf16(acc[mi][2*g],   ah[mi], qh[0], qh[2]);
                    mma_bf16(acc[mi][2*g],   al[mi], qh[0], qh[2]);
                    if (BLO) mma_bf16(acc[mi][2*g], ah[mi], ql[0], ql[2]);
                    mma_bf16(acc[mi][2*g+1], ah[mi], qh[1], qh[3]);
                    mma_bf16(acc[mi][2*g+1], al[mi], qh[1], qh[3]);
                    if (BLO) mma_bf16(acc[mi][2*g+1], ah[mi], ql[1], ql[3]);
                }
            }
        }
    }

    // ------------------------------ epilogue -------------------------------
    #pragma unroll
    for (int mi = 0; mi < 4; mi++) {
        #pragma unroll
        for (int rr = 0; rr < 2; rr++) {
            const int r = rowBase + wm * 64 + mi * 16 + rr * 8 + (lane >> 2);
            #pragma unroll
            for (int ni = 0; ni < 8; ni++) {
                const int cc = colBase + wn * 64 + ni * 8 + (lane & 3) * 2;
                float a = acc[mi][ni][rr * 2 + 0] * scale;
                float b = acc[mi][ni][rr * 2 + 1] * scale;
                if (bias) { a += bias[cc]; b += bias[cc + 1]; }
                if (relu) { a = fmaxf(a, 0.0f); b = fmaxf(b, 0.0f); }
                if (Cf) {
                    *(float2*)(Cf + (size_t)z * sC + (size_t)r * N + cc) = make_float2(a, b);
                } else {
                    __nv_bfloat16 hA, lA, hB, lB;
                    split2(a, hA, lA); split2(b, hB, lB);
                    *(__nv_bfloat162*)(Ch + (size_t)z * sC + (size_t)r * N + cc) =
                        __halves2bfloat162(hA, hB);
                    *(__nv_bfloat162*)(Cl + (size_t)z * sC + (size_t)r * N + cc) =
                        __halves2bfloat162(lA, lB);
                }
            }
        }
    }
}

// ---------------------------------------------------------------------------
// fp32 -> bf16 hi/lo elementwise split (for x)
// ---------------------------------------------------------------------------
__global__ __launch_bounds__(256)
void split_f32(const float* __restrict__ in, __nv_bfloat16* __restrict__ oh,
               __nv_bfloat16* __restrict__ ol, size_t n4)
{
    size_t i = (size_t)blockIdx.x * blockDim.x + threadIdx.x;
    if (i >= n4) return;
    float4 v = ((const float4*)in)[i];
    __nv_bfloat16 h0,l0,h1,l1,h2,l2,h3,l3;
    split2(v.x,h0,l0); split2(v.y,h1,l1); split2(v.z,h2,l2); split2(v.w,h3,l3);
    ((__nv_bfloat162*)oh)[2*i]   = __halves2bfloat162(h0,h1);
    ((__nv_bfloat162*)oh)[2*i+1] = __halves2bfloat162(h2,h3);
    ((__nv_bfloat162*)ol)[2*i]   = __halves2bfloat162(l0,l1);
    ((__nv_bfloat162*)ol)[2*i+1] = __halves2bfloat162(l2,l3);
}

// ---------------------------------------------------------------------------
// transpose + split: in fp32 [R,C] -> out bf16 hi (+ optional lo) [C,R]
// ---------------------------------------------------------------------------
__global__ __launch_bounds__(256)
void transpose_split(const float* __restrict__ in, __nv_bfloat16* __restrict__ oh,
                     __nv_bfloat16* __restrict__ ol, int R, int C,
                     size_t sIn, size_t sOut)
{
    __shared__ float tile[32][33];
    const int z = blockIdx.z;
    in += (size_t)z * sIn;  oh += (size_t)z * sOut;
    if (ol) ol += (size_t)z * sOut;
    const int c0 = blockIdx.x * 32, r0 = blockIdx.y * 32;
    const int tx = threadIdx.x & 31, ty = threadIdx.x >> 5;
    #pragma unroll
    for (int i = 0; i < 4; i++)
        tile[ty + i * 8][tx] = in[(size_t)(r0 + ty + i * 8) * C + c0 + tx];
    __syncthreads();
    #pragma unroll
    for (int i = 0; i < 4; i++) {
        const int ro = c0 + ty + i * 8;
        float v = tile[tx][ty + i * 8];
        __nv_bfloat16 h, l; split2(v, h, l);
        oh[(size_t)ro * R + r0 + tx] = h;
        if (ol) ol[(size_t)ro * R + r0 + tx] = l;
    }
}

// ---------------------------------------------------------------------------
// Row softmax over 2048 cols; reads fp32 S, writes bf16 hi/lo splits of P.
// ---------------------------------------------------------------------------
__global__ __launch_bounds__(256)
void softmax_split(const float* __restrict__ S, __nv_bfloat16* __restrict__ Ph,
                   __nv_bfloat16* __restrict__ Pl)
{
    const size_t rowOff = (size_t)blockIdx.x * SEQ;
    const float* row = S + rowOff;
    const int t = threadIdx.x;
    __shared__ float red[8];

    float vals[8];
    *(float4*)&vals[0] = *(const float4*)&row[t * 8];
    *(float4*)&vals[4] = *(const float4*)&row[t * 8 + 4];

    float vmax = vals[0];
    #pragma unroll
    for (int i = 1; i < 8; i++) vmax = fmaxf(vmax, vals[i]);
    #pragma unroll
    for (int o = 16; o > 0; o >>= 1)
        vmax = fmaxf(vmax, __shfl_xor_sync(0xffffffffu, vmax, o));
    if ((t & 31) == 0) red[t >> 5] = vmax;
    __syncthreads();
    float m = red[0];
    #pragma unroll
    for (int i = 1; i < 8; i++) m = fmaxf(m, red[i]);
    __syncthreads();

    float sum = 0.f;
    #pragma unroll
    for (int i = 0; i < 8; i++) { vals[i] = expf(vals[i] - m); sum += vals[i]; }
    #pragma unroll
    for (int o = 16; o > 0; o >>= 1)
        sum += __shfl_xor_sync(0xffffffffu, sum, o);
    if ((t & 31) == 0) red[t >> 5] = sum;
    __syncthreads();
    float tot = red[0];
    #pragma unroll
    for (int i = 1; i < 8; i++) tot += red[i];
    const float inv = 1.0f / tot;

    __nv_bfloat16* ph = Ph + rowOff + t * 8;
    __nv_bfloat16* pl = Pl + rowOff + t * 8;
    #pragma unroll
    for (int i = 0; i < 8; i += 2) {
        float a = vals[i] * inv, b = vals[i + 1] * inv;
        __nv_bfloat16 ah, al, bh, bl;
        split2(a, ah, al); split2(b, bh, bl);
        *(__nv_bfloat162*)(ph + i) = __halves2bfloat162(ah, bh);
        *(__nv_bfloat162*)(pl + i) = __halves2bfloat162(al, bl);
    }
}

// ---------------------------------------------------------------------------
extern "C" void kernel_launch(void* const* d_in, const int* in_sizes, int n_in,
                              void* d_out, int out_size)
{
    const float* x  = (const float*)d_in[0];
    const float* Wq = (const float*)d_in[1];
    const float* bq = (const float*)d_in[2];
    const float* Wk = (const float*)d_in[3];
    const float* bk = (const float*)d_in[4];
    const float* Wv = (const float*)d_in[5];
    const float* bv = (const float*)d_in[6];
    float* out = (float*)d_out;

    const int DSMEM4 = NSTAGE * 4 * T_B;   // 98304 B (3-term)
    const int DSMEM3 = NSTAGE * 3 * T_B;   // 73728 B (2-term)
    cudaFuncSetAttribute(gemm_bs<true>,  cudaFuncAttributeMaxDynamicSharedMemorySize, DSMEM4);
    cudaFuncSetAttribute(gemm_bs<false>, cudaFuncAttributeMaxDynamicSharedMemorySize, DSMEM3);

    __nv_bfloat16 *xh, *xl, *wqh, *wql, *wkh, *wkl, *wvh, *wvl;
    __nv_bfloat16 *qh, *ql, *kh, *kl, *vth, *prh, *prl;
    float *V, *S;
    cudaGetSymbolAddress((void**)&xh,  g_xh);   cudaGetSymbolAddress((void**)&xl,  g_xl);
    cudaGetSymbolAddress((void**)&wqh, g_Wqt_h);cudaGetSymbolAddress((void**)&wql, g_Wqt_l);
    cudaGetSymbolAddress((void**)&wkh, g_Wkt_h);cudaGetSymbolAddress((void**)&wkl, g_Wkt_l);
    cudaGetSymbolAddress((void**)&wvh, g_Wvt_h);cudaGetSymbolAddress((void**)&wvl, g_Wvt_l);
    cudaGetSymbolAddress((void**)&qh,  g_Qh);   cudaGetSymbolAddress((void**)&ql,  g_Ql);
    cudaGetSymbolAddress((void**)&kh,  g_Kh);   cudaGetSymbolAddress((void**)&kl,  g_Kl);
    cudaGetSymbolAddress((void**)&V,   g_V);
    cudaGetSymbolAddress((void**)&vth, g_Vth);
    cudaGetSymbolAddress((void**)&S,   g_S);
    cudaGetSymbolAddress((void**)&prh, g_Ph);   cudaGetSymbolAddress((void**)&prl, g_Pl);

    // 1) split x -> bf16 hi/lo
    {
        size_t n4 = (size_t)MTOT * DIM / 4;
        split_f32<<<(unsigned)((n4 + 255) / 256), 256>>>(x, xh, xl, n4);
    }
    // 2) transpose+split weights: W[D, E] -> Wt[E, D]
    {
        dim3 g(DIM / 32, DIM / 32, 1);
        transpose_split<<<g, 256>>>(Wq, wqh, wql, DIM, DIM, 0, 0);
        transpose_split<<<g, 256>>>(Wk, wkh, wkl, DIM, DIM, 0, 0);
        transpose_split<<<g, 256>>>(Wv, wvh, wvl, DIM, DIM, 0, 0);
    }
    // 3) projections: Q,K -> bf16 splits; V -> fp32 (for transpose)
    {
        dim3 g(DIM / 128, MTOT / 128, 1);
        gemm_bs<true><<<g, 128, DSMEM4>>>(xh, xl, wqh, wql, bq, nullptr, qh, ql,
                                          MTOT, DIM, DIM, 0, 0, 0, 1.0f, 1);
        gemm_bs<true><<<g, 128, DSMEM4>>>(xh, xl, wkh, wkl, bk, nullptr, kh, kl,
                                          MTOT, DIM, DIM, 0, 0, 0, 1.0f, 1);
        gemm_bs<true><<<g, 128, DSMEM4>>>(xh, xl, wvh, wvl, bv, V, nullptr, nullptr,
                                          MTOT, DIM, DIM, 0, 0, 0, 1.0f, 1);
    }
    // 4) transpose V per batch: [SEQ, DIM] -> [DIM, SEQ], bf16 hi only
    {
        dim3 g(DIM / 32, SEQ / 32, BATCH);
        transpose_split<<<g, 256>>>(V, vth, nullptr, SEQ, DIM,
                                    (size_t)SEQ * DIM, (size_t)DIM * SEQ);
    }
    // 5) scores = scale * Q K^T per batch (fp32 out), 3-term
    {
        const float scale = 1.0f / sqrtf((float)DIM);
        dim3 g(SEQ / 128, SEQ / 128, BATCH);
        gemm_bs<true><<<g, 128, DSMEM4>>>(qh, ql, kh, kl, nullptr, S, nullptr, nullptr,
                                          SEQ, SEQ, DIM,
                                          (size_t)SEQ * DIM, (size_t)SEQ * DIM,
                                          (size_t)SEQ * SEQ, scale, 0);
    }
    // 6) softmax -> P bf16 splits
    softmax_split<<<BATCH * SEQ, 256>>>(S, prh, prl);

    // 7) out = P V per batch (fp32 out), 2-term: A = P split, B = Vt hi only
    {
        dim3 g(DIM / 128, SEQ / 128, BATCH);
        gemm_bs<false><<<g, 128, DSMEM3>>>(prh, prl, vth, nullptr, nullptr, out,
                                           nullptr, nullptr,
                                           SEQ, DIM, SEQ,
                                           (size_t)SEQ * SEQ, (size_t)DIM * SEQ,
                                           (size_t)SEQ * DIM, 1.0f, 0);
    }
}

// round 8
// speedup vs baseline: 1.3519x; 1.0752x over previous
#include <cuda_runtime.h>
#include <cuda_bf16.h>
#include <math.h>
#include <stdint.h>

#define BATCH 8
#define SEQ   2048
#define DIM   512
#define MTOT  (BATCH*SEQ)   // 16384

// ---------------------------------------------------------------------------
// Device scratch (allocation-free rule: __device__ globals)
// ---------------------------------------------------------------------------
__device__ __nv_bfloat16 g_xh[MTOT * DIM], g_xl[MTOT * DIM];
__device__ __nv_bfloat16 g_Wqt_h[DIM * DIM], g_Wqt_l[DIM * DIM];
__device__ __nv_bfloat16 g_Wkt_h[DIM * DIM], g_Wkt_l[DIM * DIM];
__device__ __nv_bfloat16 g_Wvt_h[DIM * DIM], g_Wvt_l[DIM * DIM];
__device__ __nv_bfloat16 g_Qh[MTOT * DIM], g_Ql[MTOT * DIM];
__device__ __nv_bfloat16 g_Kh[MTOT * DIM], g_Kl[MTOT * DIM];
__device__ __nv_bfloat16 g_Vh[MTOT * DIM], g_Vl[MTOT * DIM];   // row-major V split
__device__ __nv_bfloat16 g_Vth[MTOT * DIM];                     // [B][DIM][SEQ]
__device__ float         g_S [(size_t)BATCH * SEQ * SEQ];
__device__ __nv_bfloat16 g_Ph[(size_t)BATCH * SEQ * SEQ];
__device__ __nv_bfloat16 g_Pl[(size_t)BATCH * SEQ * SEQ];

// ---------------------------------------------------------------------------
// Baseline-ISA helpers: ldmatrix / mma.sync / cp.async  (no 'a' features)
// ---------------------------------------------------------------------------
__device__ __forceinline__ uint32_t smem_to_u32(const void* p) {
    uint32_t a;
    asm("{ .reg .u64 t; cvta.to.shared.u64 t, %1; cvt.u32.u64 %0, t; }" : "=r"(a) : "l"(p));
    return a;
}
__device__ __forceinline__ void ldsm4(uint32_t* r, uint32_t addr) {
    asm volatile("ldmatrix.sync.aligned.m8n8.x4.shared.b16 {%0,%1,%2,%3}, [%4];"
                 : "=r"(r[0]), "=r"(r[1]), "=r"(r[2]), "=r"(r[3]) : "r"(addr));
}
__device__ __forceinline__ void mma_bf16(float* c, const uint32_t* a,
                                         uint32_t b0, uint32_t b1) {
    asm volatile("mma.sync.aligned.m16n8k16.row.col.f32.bf16.bf16.f32 "
                 "{%0,%1,%2,%3}, {%4,%5,%6,%7}, {%8,%9}, {%0,%1,%2,%3};"
                 : "+f"(c[0]), "+f"(c[1]), "+f"(c[2]), "+f"(c[3])
                 : "r"(a[0]), "r"(a[1]), "r"(a[2]), "r"(a[3]), "r"(b0), "r"(b1));
}
__device__ __forceinline__ void cp16(uint32_t dst, const void* src) {
    asm volatile("cp.async.cg.shared.global [%0], [%1], 16;" :: "r"(dst), "l"(src));
}
#define CP_COMMIT() asm volatile("cp.async.commit_group;" ::: "memory")
#define CP_WAIT1()  asm volatile("cp.async.wait_group 1;" ::: "memory")

__device__ __forceinline__ void split2(float a, __nv_bfloat16& h, __nv_bfloat16& l) {
    h = __float2bfloat16(a);
    l = __float2bfloat16(a - __bfloat162float(h));
}

// Bank-conflict-free swizzle for 64B rows:
// 16B-group within a 128B bank cycle = (row&1)*4 + (chunk ^ ((row>>1)&3)),
// distinct across any 8-row-aligned ldmatrix phase.
#define SWZ(r, ch) ((uint32_t)(r) * 64u + (uint32_t)((((ch) ^ (((r) >> 1) & 3)) & 3) << 4))

// ---------------------------------------------------------------------------
// bf16-split HMMA GEMM mainloop (macro-shared between generic + projection
// kernels). Block tile 128x128, BK=32, 4 warps of 64x64 tiles, 3-stage
// cp.async pipeline, single __syncthreads per chunk, 2 CTAs/SM.
// ---------------------------------------------------------------------------
#define T_B    (128 * 64)                  // 8192 B per half-tile (A or B)
#define NSTAGE 3

template<bool BLO>
__device__ __forceinline__ void issue_stage(uint32_t sAddr,
    const __nv_bfloat16* pAh, const __nv_bfloat16* pAl,
    const __nv_bfloat16* pBh, const __nv_bfloat16* pBl,
    int lda, int ldb, int k0, int t)
{
    const int NT = BLO ? 4 : 3;
    const __nv_bfloat16* base[4] = { pAh, pAl, pBh, pBl };
    const int ld2[4] = { lda, lda, ldb, ldb };
    #pragma unroll
    for (int i = 0; i < NT * 4; i++) {      // NT*512 transfers / 128 threads
        const int j    = t + i * 128;
        const int tile = j >> 9;            // 0..NT-1
        const int r    = (j & 511) >> 2;    // 0..127
        const int ch   = j & 3;
        const __nv_bfloat16* src = base[tile] + (size_t)r * ld2[tile] + k0 + ch * 8;
        cp16(sAddr + tile * T_B + SWZ(r, ch), src);
    }
}

// Mainloop body: declares/updates acc[4][8][4] from (pAh,pAl,pBh,pBl).
#define GEMM_MAINLOOP(BLOV)                                                         \
    float acc[4][8][4];                                                             \
    _Pragma("unroll")                                                               \
    for (int mi = 0; mi < 4; mi++)                                                  \
        _Pragma("unroll")                                                           \
        for (int ni = 0; ni < 8; ni++)                                              \
            _Pragma("unroll")                                                       \
            for (int r = 0; r < 4; r++) acc[mi][ni][r] = 0.0f;                      \
    const uint32_t STAGEB = (BLOV ? 4 : 3) * T_B;                                   \
    const int nc = K / 32;                                                          \
    issue_stage<BLOV>(sb,          pAh, pAl, pBh, pBl, lda, ldb,  0, t); CP_COMMIT();\
    issue_stage<BLOV>(sb + STAGEB, pAh, pAl, pBh, pBl, lda, ldb, 32, t); CP_COMMIT();\
    const int lrow = lane & 15;                                                     \
    const int cS   = (lane >> 4) & 1;                                               \
    for (int c = 0; c < nc; c++) {                                                  \
        CP_WAIT1();                                                                 \
        __syncthreads();                                                            \
        if (c + 2 < nc)                                                             \
            issue_stage<BLOV>(sb + ((c + 2) % NSTAGE) * STAGEB, pAh, pAl, pBh, pBl, \
                              lda, ldb, (c + 2) * 32, t);                           \
        CP_COMMIT();                                                                \
        const uint32_t st = sb + (c % NSTAGE) * STAGEB;                             \
        _Pragma("unroll")                                                           \
        for (int ks = 0; ks < 2; ks++) {                                            \
            const int chunk = ks * 2 + cS;                                          \
            uint32_t ah[4][4], al[4][4];                                            \
            _Pragma("unroll")                                                       \
            for (int mi = 0; mi < 4; mi++) {                                        \
                const int rowA = wm * 64 + mi * 16 + lrow;                          \
                const uint32_t offA = SWZ(rowA, chunk);                             \
                ldsm4(ah[mi], st + offA);                                           \
                ldsm4(al[mi], st + T_B + offA);                                     \
            }                                                                       \
            _Pragma("unroll")                                                       \
            for (int g = 0; g < 4; g++) {                                           \
                const int rowB = wn * 64 + g * 16 + lrow;                           \
                const uint32_t offB = SWZ(rowB, chunk);                             \
                uint32_t qh[4], ql[4];                                              \
                ldsm4(qh, st + 2 * T_B + offB);                                     \
                if (BLOV) ldsm4(ql, st + 3 * T_B + offB);                           \
                _Pragma("unroll")                                                   \
                for (int mi = 0; mi < 4; mi++) {                                    \
                    mma_bf16(acc[mi][2*g],   ah[mi], qh[0], qh[2]);                 \
                    mma_bf16(acc[mi][2*g],   al[mi], qh[0], qh[2]);                 \
                    if (BLOV) mma_bf16(acc[mi][2*g], ah[mi], ql[0], ql[2]);         \
                    mma_bf16(acc[mi][2*g+1], ah[mi], qh[1], qh[3]);                 \
                    mma_bf16(acc[mi][2*g+1], al[mi], qh[1], qh[3]);                 \
                    if (BLOV) mma_bf16(acc[mi][2*g+1], ah[mi], ql[1], ql[3]);       \
                }                                                                   \
            }                                                                       \
        }                                                                           \
    }

// ---------------------------------------------------------------------------
// Generic GEMM (scores: 3-term fp32 out; PV: 2-term fp32 out)
// ---------------------------------------------------------------------------
template<bool BLO>
__global__ __launch_bounds__(128, 2)
void gemm_bs(const __nv_bfloat16* __restrict__ Ah, const __nv_bfloat16* __restrict__ Al,
             const __nv_bfloat16* __restrict__ Bh, const __nv_bfloat16* __restrict__ Bl,
             float* __restrict__ Cf,
             int M, int N, int K,
             size_t sA, size_t sB, size_t sC, float scale)
{
    extern __shared__ char smem[];
    const uint32_t sb = smem_to_u32(smem);
    const int t    = threadIdx.x;
    const int wid  = t >> 5;
    const int lane = t & 31;
    const int wm   = wid >> 1;
    const int wn   = wid & 1;

    const int z = blockIdx.z;
    const int rowBase = blockIdx.y * 128;
    const int colBase = blockIdx.x * 128;
    const int lda = K, ldb = K;

    const __nv_bfloat16* pAh = Ah + (size_t)z * sA + (size_t)rowBase * lda;
    const __nv_bfloat16* pAl = Al + (size_t)z * sA + (size_t)rowBase * lda;
    const __nv_bfloat16* pBh = Bh + (size_t)z * sB + (size_t)colBase * ldb;
    const __nv_bfloat16* pBl = BLO ? (Bl + (size_t)z * sB + (size_t)colBase * ldb) : nullptr;

    GEMM_MAINLOOP(BLO)

    #pragma unroll
    for (int mi = 0; mi < 4; mi++)
        #pragma unroll
        for (int rr = 0; rr < 2; rr++) {
            const int r = rowBase + wm * 64 + mi * 16 + rr * 8 + (lane >> 2);
            #pragma unroll
            for (int ni = 0; ni < 8; ni++) {
                const int cc = colBase + wn * 64 + ni * 8 + (lane & 3) * 2;
                float a = acc[mi][ni][rr * 2 + 0] * scale;
                float b = acc[mi][ni][rr * 2 + 1] * scale;
                *(float2*)(Cf + (size_t)z * sC + (size_t)r * N + cc) = make_float2(a, b);
            }
        }
}

// ---------------------------------------------------------------------------
// Merged QKV projection: grid.z selects (W, bias, output-split) triple.
// A = x splits; output = relu(x W + b) as bf16 hi/lo splits.
// ---------------------------------------------------------------------------
__global__ __launch_bounds__(128, 2)
void proj_gemm(const float* __restrict__ bq, const float* __restrict__ bk,
               const float* __restrict__ bv)
{
    extern __shared__ char smem[];
    const uint32_t sb = smem_to_u32(smem);
    const int t    = threadIdx.x;
    const int wid  = t >> 5;
    const int lane = t & 31;
    const int wm   = wid >> 1;
    const int wn   = wid & 1;

    const int z = blockIdx.z;                 // 0=Q 1=K 2=V
    const int rowBase = blockIdx.y * 128;
    const int colBase = blockIdx.x * 128;
    const int K = DIM, N = DIM;
    const int lda = K, ldb = K;

    const __nv_bfloat16* pAh = g_xh + (size_t)rowBase * lda;
    const __nv_bfloat16* pAl = g_xl + (size_t)rowBase * lda;
    const __nv_bfloat16* Wh = (z == 0) ? g_Wqt_h : (z == 1) ? g_Wkt_h : g_Wvt_h;
    const __nv_bfloat16* Wl = (z == 0) ? g_Wqt_l : (z == 1) ? g_Wkt_l : g_Wvt_l;
    const float* bias = (z == 0) ? bq : (z == 1) ? bk : bv;
    __nv_bfloat16* Ch = (z == 0) ? g_Qh : (z == 1) ? g_Kh : g_Vh;
    __nv_bfloat16* Cl = (z == 0) ? g_Ql : (z == 1) ? g_Kl : g_Vl;
    const __nv_bfloat16* pBh = Wh + (size_t)colBase * ldb;
    const __nv_bfloat16* pBl = Wl + (size_t)colBase * ldb;

    GEMM_MAINLOOP(true)

    #pragma unroll
    for (int mi = 0; mi < 4; mi++)
        #pragma unroll
        for (int rr = 0; rr < 2; rr++) {
            const int r = rowBase + wm * 64 + mi * 16 + rr * 8 + (lane >> 2);
            #pragma unroll
            for (int ni = 0; ni < 8; ni++) {
                const int cc = colBase + wn * 64 + ni * 8 + (lane & 3) * 2;
                float a = acc[mi][ni][rr * 2 + 0] + bias[cc];
                float b = acc[mi][ni][rr * 2 + 1] + bias[cc + 1];
                a = fmaxf(a, 0.0f); b = fmaxf(b, 0.0f);
                __nv_bfloat16 hA, lA, hB, lB;
                split2(a, hA, lA); split2(b, hB, lB);
                *(__nv_bfloat162*)(Ch + (size_t)r * N + cc) = __halves2bfloat162(hA, hB);
                *(__nv_bfloat162*)(Cl + (size_t)r * N + cc) = __halves2bfloat162(lA, lB);
            }
        }
}

// ---------------------------------------------------------------------------
// fp32 -> bf16 hi/lo elementwise split (for x)
// ---------------------------------------------------------------------------
__global__ __launch_bounds__(256)
void split_f32(const float* __restrict__ in, __nv_bfloat16* __restrict__ oh,
               __nv_bfloat16* __restrict__ ol, size_t n4)
{
    size_t i = (size_t)blockIdx.x * blockDim.x + threadIdx.x;
    if (i >= n4) return;
    float4 v = ((const float4*)in)[i];
    __nv_bfloat16 h0,l0,h1,l1,h2,l2,h3,l3;
    split2(v.x,h0,l0); split2(v.y,h1,l1); split2(v.z,h2,l2); split2(v.w,h3,l3);
    ((__nv_bfloat162*)oh)[2*i]   = __halves2bfloat162(h0,h1);
    ((__nv_bfloat162*)oh)[2*i+1] = __halves2bfloat162(h2,h3);
    ((__nv_bfloat162*)ol)[2*i]   = __halves2bfloat162(l0,l1);
    ((__nv_bfloat162*)ol)[2*i+1] = __halves2bfloat162(l2,l3);
}

// ---------------------------------------------------------------------------
// transpose + split: in fp32 [R,C] -> out bf16 hi/lo [C,R] (weights)
// ---------------------------------------------------------------------------
__global__ __launch_bounds__(256)
void transpose_split(const float* __restrict__ in, __nv_bfloat16* __restrict__ oh,
                     __nv_bfloat16* __restrict__ ol, int R, int C)
{
    __shared__ float tile[32][33];
    const int c0 = blockIdx.x * 32, r0 = blockIdx.y * 32;
    const int tx = threadIdx.x & 31, ty = threadIdx.x >> 5;
    #pragma unroll
    for (int i = 0; i < 4; i++)
        tile[ty + i * 8][tx] = in[(size_t)(r0 + ty + i * 8) * C + c0 + tx];
    __syncthreads();
    #pragma unroll
    for (int i = 0; i < 4; i++) {
        const int ro = c0 + ty + i * 8;
        float v = tile[tx][ty + i * 8];
        __nv_bfloat16 h, l; split2(v, h, l);
        oh[(size_t)ro * R + r0 + tx] = h;
        ol[(size_t)ro * R + r0 + tx] = l;
    }
}

// ---------------------------------------------------------------------------
// bf16 transpose (V): in [SEQ,DIM] per batch -> out [DIM,SEQ]
// ---------------------------------------------------------------------------
__global__ __launch_bounds__(256)
void transpose_bf16(const __nv_bfloat16* __restrict__ in, __nv_bfloat16* __restrict__ out)
{
    __shared__ __nv_bfloat16 tile[32][33];
    const int z = blockIdx.z;
    in  += (size_t)z * SEQ * DIM;
    out += (size_t)z * DIM * SEQ;
    const int c0 = blockIdx.x * 32, r0 = blockIdx.y * 32;
    const int tx = threadIdx.x & 31, ty = threadIdx.x >> 5;
    #pragma unroll
    for (int i = 0; i < 4; i++)
        tile[ty + i * 8][tx] = in[(size_t)(r0 + ty + i * 8) * DIM + c0 + tx];
    __syncthreads();
    #pragma unroll
    for (int i = 0; i < 4; i++)
        out[(size_t)(c0 + ty + i * 8) * SEQ + r0 + tx] = tile[tx][ty + i * 8];
}

// ---------------------------------------------------------------------------
// Row softmax over 2048 cols; reads fp32 S, writes bf16 hi/lo splits of P.
// ---------------------------------------------------------------------------
__global__ __launch_bounds__(256)
void softmax_split(const float* __restrict__ S, __nv_bfloat16* __restrict__ Ph,
                   __nv_bfloat16* __restrict__ Pl)
{
    const size_t rowOff = (size_t)blockIdx.x * SEQ;
    const float* row = S + rowOff;
    const int t = threadIdx.x;
    __shared__ float red[8];

    float vals[8];
    *(float4*)&vals[0] = *(const float4*)&row[t * 8];
    *(float4*)&vals[4] = *(const float4*)&row[t * 8 + 4];

    float vmax = vals[0];
    #pragma unroll
    for (int i = 1; i < 8; i++) vmax = fmaxf(vmax, vals[i]);
    #pragma unroll
    for (int o = 16; o > 0; o >>= 1)
        vmax = fmaxf(vmax, __shfl_xor_sync(0xffffffffu, vmax, o));
    if ((t & 31) == 0) red[t >> 5] = vmax;
    __syncthreads();
    float m = red[0];
    #pragma unroll
    for (int i = 1; i < 8; i++) m = fmaxf(m, red[i]);
    __syncthreads();

    float sum = 0.f;
    #pragma unroll
    for (int i = 0; i < 8; i++) { vals[i] = __expf(vals[i] - m); sum += vals[i]; }
    #pragma unroll
    for (int o = 16; o > 0; o >>= 1)
        sum += __shfl_xor_sync(0xffffffffu, sum, o);
    if ((t & 31) == 0) red[t >> 5] = sum;
    __syncthreads();
    float tot = red[0];
    #pragma unroll
    for (int i = 1; i < 8; i++) tot += red[i];
    const float inv = 1.0f / tot;

    __nv_bfloat16* ph = Ph + rowOff + t * 8;
    __nv_bfloat16* pl = Pl + rowOff + t * 8;
    #pragma unroll
    for (int i = 0; i < 8; i += 2) {
        float a = vals[i] * inv, b = vals[i + 1] * inv;
        __nv_bfloat16 ah, al, bh, bl;
        split2(a, ah, al); split2(b, bh, bl);
        *(__nv_bfloat162*)(ph + i) = __halves2bfloat162(ah, bh);
        *(__nv_bfloat162*)(pl + i) = __halves2bfloat162(al, bl);
    }
}

// ---------------------------------------------------------------------------
extern "C" void kernel_launch(void* const* d_in, const int* in_sizes, int n_in,
                              void* d_out, int out_size)
{
    const float* x  = (const float*)d_in[0];
    const float* Wq = (const float*)d_in[1];
    const float* bq = (const float*)d_in[2];
    const float* Wk = (const float*)d_in[3];
    const float* bk = (const float*)d_in[4];
    const float* Wv = (const float*)d_in[5];
    const float* bv = (const float*)d_in[6];
    float* out = (float*)d_out;

    const int DSMEM4 = NSTAGE * 4 * T_B;   // 98304 B (3-term)
    const int DSMEM3 = NSTAGE * 3 * T_B;   // 73728 B (2-term)
    cudaFuncSetAttribute(gemm_bs<true>,  cudaFuncAttributeMaxDynamicSharedMemorySize, DSMEM4);
    cudaFuncSetAttribute(gemm_bs<false>, cudaFuncAttributeMaxDynamicSharedMemorySize, DSMEM3);
    cudaFuncSetAttribute(proj_gemm,      cudaFuncAttributeMaxDynamicSharedMemorySize, DSMEM4);

    __nv_bfloat16 *xh, *xl, *wqh, *wql, *wkh, *wkl, *wvh, *wvl;
    __nv_bfloat16 *qh, *ql, *kh, *kl, *vh, *vth, *prh, *prl;
    float *S;
    cudaGetSymbolAddress((void**)&xh,  g_xh);   cudaGetSymbolAddress((void**)&xl,  g_xl);
    cudaGetSymbolAddress((void**)&wqh, g_Wqt_h);cudaGetSymbolAddress((void**)&wql, g_Wqt_l);
    cudaGetSymbolAddress((void**)&wkh, g_Wkt_h);cudaGetSymbolAddress((void**)&wkl, g_Wkt_l);
    cudaGetSymbolAddress((void**)&wvh, g_Wvt_h);cudaGetSymbolAddress((void**)&wvl, g_Wvt_l);
    cudaGetSymbolAddress((void**)&qh,  g_Qh);   cudaGetSymbolAddress((void**)&ql,  g_Ql);
    cudaGetSymbolAddress((void**)&kh,  g_Kh);   cudaGetSymbolAddress((void**)&kl,  g_Kl);
    cudaGetSymbolAddress((void**)&vh,  g_Vh);
    cudaGetSymbolAddress((void**)&vth, g_Vth);
    cudaGetSymbolAddress((void**)&S,   g_S);
    cudaGetSymbolAddress((void**)&prh, g_Ph);   cudaGetSymbolAddress((void**)&prl, g_Pl);

    // 1) split x -> bf16 hi/lo
    {
        size_t n4 = (size_t)MTOT * DIM / 4;
        split_f32<<<(unsigned)((n4 + 255) / 256), 256>>>(x, xh, xl, n4);
    }
    // 2) transpose+split weights: W[D, E] -> Wt[E, D]
    {
        dim3 g(DIM / 32, DIM / 32, 1);
        transpose_split<<<g, 256>>>(Wq, wqh, wql, DIM, DIM);
        transpose_split<<<g, 256>>>(Wk, wkh, wkl, DIM, DIM);
        transpose_split<<<g, 256>>>(Wv, wvh, wvl, DIM, DIM);
    }
    // 3) merged QKV projections (one launch, z selects target)
    {
        dim3 g(DIM / 128, MTOT / 128, 3);
        proj_gemm<<<g, 128, DSMEM4>>>(bq, bk, bv);
    }
    // 4) transpose V (bf16 hi) per batch: [SEQ, DIM] -> [DIM, SEQ]
    {
        dim3 g(DIM / 32, SEQ / 32, BATCH);
        transpose_bf16<<<g, 256>>>(vh, vth);
    }
    // 5) scores = scale * Q K^T per batch (fp32 out), 3-term
    {
        const float scale = 1.0f / sqrtf((float)DIM);
        dim3 g(SEQ / 128, SEQ / 128, BATCH);
        gemm_bs<true><<<g, 128, DSMEM4>>>(qh, ql, kh, kl, S,
                                          SEQ, SEQ, DIM,
                                          (size_t)SEQ * DIM, (size_t)SEQ * DIM,
                                          (size_t)SEQ * SEQ, scale);
    }
    // 6) softmax -> P bf16 splits
    softmax_split<<<BATCH * SEQ, 256>>>(S, prh, prl);

    // 7) out = P V per batch (fp32 out), 2-term: A = P split, B = Vt hi only
    {
        dim3 g(DIM / 128, SEQ / 128, BATCH);
        gemm_bs<false><<<g, 128, DSMEM3>>>(prh, prl, vth, nullptr, out,
                                           SEQ, DIM, SEQ,
                                           (size_t)SEQ * SEQ, (size_t)DIM * SEQ,
                                           (size_t)SEQ * DIM, 1.0f);
    }
}

// round 9
// speedup vs baseline: 1.6511x; 1.2213x over previous
#include <cuda_runtime.h>
#include <cuda_bf16.h>
#include <math.h>
#include <stdint.h>

#define BATCH 8
#define SEQ   2048
#define DIM   512
#define MTOT  (BATCH*SEQ)   // 16384

// ---------------------------------------------------------------------------
// Device scratch (allocation-free rule: __device__ globals)
// ---------------------------------------------------------------------------
__device__ __nv_bfloat16 g_xh[MTOT * DIM], g_xl[MTOT * DIM];
__device__ __nv_bfloat16 g_Wqt_h[DIM * DIM];
__device__ __nv_bfloat16 g_Wkt_h[DIM * DIM];
__device__ __nv_bfloat16 g_Wvt_h[DIM * DIM];
__device__ __nv_bfloat16 g_Qh[MTOT * DIM], g_Ql[MTOT * DIM];
__device__ __nv_bfloat16 g_Kh[MTOT * DIM];
__device__ __nv_bfloat16 g_Vh[MTOT * DIM];                      // row-major V hi
__device__ __nv_bfloat16 g_Vth[MTOT * DIM];                     // [B][DIM][SEQ]
__device__ float         g_S [(size_t)BATCH * SEQ * SEQ];
__device__ __nv_bfloat16 g_Ph[(size_t)BATCH * SEQ * SEQ];
__device__ __nv_bfloat16 g_Pl[(size_t)BATCH * SEQ * SEQ];

// ---------------------------------------------------------------------------
// Baseline-ISA helpers: ldmatrix / mma.sync / cp.async  (no 'a' features)
// ---------------------------------------------------------------------------
__device__ __forceinline__ uint32_t smem_to_u32(const void* p) {
    uint32_t a;
    asm("{ .reg .u64 t; cvta.to.shared.u64 t, %1; cvt.u32.u64 %0, t; }" : "=r"(a) : "l"(p));
    return a;
}
__device__ __forceinline__ void ldsm4(uint32_t* r, uint32_t addr) {
    asm volatile("ldmatrix.sync.aligned.m8n8.x4.shared.b16 {%0,%1,%2,%3}, [%4];"
                 : "=r"(r[0]), "=r"(r[1]), "=r"(r[2]), "=r"(r[3]) : "r"(addr));
}
__device__ __forceinline__ void mma_bf16(float* c, const uint32_t* a,
                                         uint32_t b0, uint32_t b1) {
    asm volatile("mma.sync.aligned.m16n8k16.row.col.f32.bf16.bf16.f32 "
                 "{%0,%1,%2,%3}, {%4,%5,%6,%7}, {%8,%9}, {%0,%1,%2,%3};"
                 : "+f"(c[0]), "+f"(c[1]), "+f"(c[2]), "+f"(c[3])
                 : "r"(a[0]), "r"(a[1]), "r"(a[2]), "r"(a[3]), "r"(b0), "r"(b1));
}
__device__ __forceinline__ void cp16(uint32_t dst, const void* src) {
    asm volatile("cp.async.cg.shared.global [%0], [%1], 16;" :: "r"(dst), "l"(src));
}
#define CP_COMMIT() asm volatile("cp.async.commit_group;" ::: "memory")
#define CP_WAIT1()  asm volatile("cp.async.wait_group 1;" ::: "memory")

__device__ __forceinline__ void split2(float a, __nv_bfloat16& h, __nv_bfloat16& l) {
    h = __float2bfloat16(a);
    l = __float2bfloat16(a - __bfloat162float(h));
}

// Bank-conflict-free swizzle for 64B rows:
// 16B-group within a 128B bank cycle = (row&1)*4 + (chunk ^ ((row>>1)&3)),
// distinct across any 8-row-aligned ldmatrix phase.
#define SWZ(r, ch) ((uint32_t)(r) * 64u + (uint32_t)((((ch) ^ (((r) >> 1) & 3)) & 3) << 4))

// ---------------------------------------------------------------------------
// 2-term bf16-split HMMA GEMM:  C = scale * ((Ah+Al) x Bh^T)
// Block tile 128x128, BK=32, 4 warps (2Mx2N) of 64x64 tiles.
// 3 smem tiles per stage (Ah, Al, Bh), 3-stage cp.async pipeline,
// single __syncthreads per chunk, 72KB smem -> 2 CTAs/SM.
// ---------------------------------------------------------------------------
#define T_B    (128 * 64)                  // 8192 B per tile
#define STAGEB (3 * T_B)                   // 24576 B
#define NSTAGE 3
#define GEMM_DSMEM (NSTAGE * STAGEB)       // 73728 B

__device__ __forceinline__ void issue_stage(uint32_t sAddr,
    const __nv_bfloat16* pAh, const __nv_bfloat16* pAl,
    const __nv_bfloat16* pBh,
    int lda, int ldb, int k0, int t)
{
    const __nv_bfloat16* base[3] = { pAh, pAl, pBh };
    const int ld2[3] = { lda, lda, ldb };
    #pragma unroll
    for (int i = 0; i < 12; i++) {          // 1536 x 16B transfers / 128 thr
        const int j    = t + i * 128;
        const int tile = j >> 9;            // 0..2
        const int r    = (j & 511) >> 2;    // 0..127
        const int ch   = j & 3;
        const __nv_bfloat16* src = base[tile] + (size_t)r * ld2[tile] + k0 + ch * 8;
        cp16(sAddr + tile * T_B + SWZ(r, ch), src);
    }
}

// Mainloop body: declares/updates acc[4][8][4] from (pAh,pAl,pBh).
#define GEMM_MAINLOOP()                                                             \
    float acc[4][8][4];                                                             \
    _Pragma("unroll")                                                               \
    for (int mi = 0; mi < 4; mi++)                                                  \
        _Pragma("unroll")                                                           \
        for (int ni = 0; ni < 8; ni++)                                              \
            _Pragma("unroll")                                                       \
            for (int r = 0; r < 4; r++) acc[mi][ni][r] = 0.0f;                      \
    const int nc = K / 32;                                                          \
    issue_stage(sb,          pAh, pAl, pBh, lda, ldb,  0, t); CP_COMMIT();          \
    issue_stage(sb + STAGEB, pAh, pAl, pBh, lda, ldb, 32, t); CP_COMMIT();          \
    const int lrow = lane & 15;                                                     \
    const int cS   = (lane >> 4) & 1;                                               \
    for (int c = 0; c < nc; c++) {                                                  \
        CP_WAIT1();                                                                 \
        __syncthreads();                                                            \
        if (c + 2 < nc)                                                             \
            issue_stage(sb + ((c + 2) % NSTAGE) * STAGEB, pAh, pAl, pBh,            \
                        lda, ldb, (c + 2) * 32, t);                                 \
        CP_COMMIT();                                                                \
        const uint32_t st = sb + (c % NSTAGE) * STAGEB;                             \
        _Pragma("unroll")                                                           \
        for (int ks = 0; ks < 2; ks++) {                                            \
            const int chunk = ks * 2 + cS;                                          \
            uint32_t ah[4][4], al[4][4];                                            \
            _Pragma("unroll")                                                       \
            for (int mi = 0; mi < 4; mi++) {                                        \
                const int rowA = wm * 64 + mi * 16 + lrow;                          \
                const uint32_t offA = SWZ(rowA, chunk);                             \
                ldsm4(ah[mi], st + offA);                                           \
                ldsm4(al[mi], st + T_B + offA);                                     \
            }                                                                       \
            _Pragma("unroll")                                                       \
            for (int g = 0; g < 4; g++) {                                           \
                const int rowB = wn * 64 + g * 16 + lrow;                           \
                const uint32_t offB = SWZ(rowB, chunk);                             \
                uint32_t qh[4];                                                     \
                ldsm4(qh, st + 2 * T_B + offB);                                     \
                _Pragma("unroll")                                                   \
                for (int mi = 0; mi < 4; mi++) {                                    \
                    mma_bf16(acc[mi][2*g],   ah[mi], qh[0], qh[2]);                 \
                    mma_bf16(acc[mi][2*g],   al[mi], qh[0], qh[2]);                 \
                    mma_bf16(acc[mi][2*g+1], ah[mi], qh[1], qh[3]);                 \
                    mma_bf16(acc[mi][2*g+1], al[mi], qh[1], qh[3]);                 \
                }                                                                   \
            }                                                                       \
        }                                                                           \
    }

// ---------------------------------------------------------------------------
// Generic GEMM with fp32 output (scores, PV)
// ---------------------------------------------------------------------------
__global__ __launch_bounds__(128, 2)
void gemm_bs(const __nv_bfloat16* __restrict__ Ah, const __nv_bfloat16* __restrict__ Al,
             const __nv_bfloat16* __restrict__ Bh,
             float* __restrict__ Cf,
             int M, int N, int K,
             size_t sA, size_t sB, size_t sC, float scale)
{
    extern __shared__ char smem[];
    const uint32_t sb = smem_to_u32(smem);
    const int t    = threadIdx.x;
    const int wid  = t >> 5;
    const int lane = t & 31;
    const int wm   = wid >> 1;
    const int wn   = wid & 1;

    const int z = blockIdx.z;
    const int rowBase = blockIdx.y * 128;
    const int colBase = blockIdx.x * 128;
    const int lda = K, ldb = K;

    const __nv_bfloat16* pAh = Ah + (size_t)z * sA + (size_t)rowBase * lda;
    const __nv_bfloat16* pAl = Al + (size_t)z * sA + (size_t)rowBase * lda;
    const __nv_bfloat16* pBh = Bh + (size_t)z * sB + (size_t)colBase * ldb;

    GEMM_MAINLOOP()

    #pragma unroll
    for (int mi = 0; mi < 4; mi++)
        #pragma unroll
        for (int rr = 0; rr < 2; rr++) {
            const int r = rowBase + wm * 64 + mi * 16 + rr * 8 + (lane >> 2);
            #pragma unroll
            for (int ni = 0; ni < 8; ni++) {
                const int cc = colBase + wn * 64 + ni * 8 + (lane & 3) * 2;
                float a = acc[mi][ni][rr * 2 + 0] * scale;
                float b = acc[mi][ni][rr * 2 + 1] * scale;
                *(float2*)(Cf + (size_t)z * sC + (size_t)r * N + cc) = make_float2(a, b);
            }
        }
}

// ---------------------------------------------------------------------------
// Merged QKV projection: grid.z selects (W, bias, output) triple.
// out = relu(x W + b); Q -> bf16 hi/lo splits; K, V -> bf16 hi only.
// ---------------------------------------------------------------------------
__global__ __launch_bounds__(128, 2)
void proj_gemm(const float* __restrict__ bq, const float* __restrict__ bk,
               const float* __restrict__ bv)
{
    extern __shared__ char smem[];
    const uint32_t sb = smem_to_u32(smem);
    const int t    = threadIdx.x;
    const int wid  = t >> 5;
    const int lane = t & 31;
    const int wm   = wid >> 1;
    const int wn   = wid & 1;

    const int z = blockIdx.z;                 // 0=Q 1=K 2=V
    const int rowBase = blockIdx.y * 128;
    const int colBase = blockIdx.x * 128;
    const int K = DIM, N = DIM;
    const int lda = K, ldb = K;

    const __nv_bfloat16* pAh = g_xh + (size_t)rowBase * lda;
    const __nv_bfloat16* pAl = g_xl + (size_t)rowBase * lda;
    const __nv_bfloat16* Wh = (z == 0) ? g_Wqt_h : (z == 1) ? g_Wkt_h : g_Wvt_h;
    const float* bias = (z == 0) ? bq : (z == 1) ? bk : bv;
    const __nv_bfloat16* pBh = Wh + (size_t)colBase * ldb;

    GEMM_MAINLOOP()

    __nv_bfloat16* Ch = (z == 0) ? g_Qh : (z == 1) ? g_Kh : g_Vh;

    #pragma unroll
    for (int mi = 0; mi < 4; mi++)
        #pragma unroll
        for (int rr = 0; rr < 2; rr++) {
            const int r = rowBase + wm * 64 + mi * 16 + rr * 8 + (lane >> 2);
            #pragma unroll
            for (int ni = 0; ni < 8; ni++) {
                const int cc = colBase + wn * 64 + ni * 8 + (lane & 3) * 2;
                float a = acc[mi][ni][rr * 2 + 0] + bias[cc];
                float b = acc[mi][ni][rr * 2 + 1] + bias[cc + 1];
                a = fmaxf(a, 0.0f); b = fmaxf(b, 0.0f);
                __nv_bfloat16 hA, lA, hB, lB;
                split2(a, hA, lA); split2(b, hB, lB);
                *(__nv_bfloat162*)(Ch + (size_t)r * N + cc) = __halves2bfloat162(hA, hB);
                if (z == 0)
                    *(__nv_bfloat162*)(g_Ql + (size_t)r * N + cc) = __halves2bfloat162(lA, lB);
            }
        }
}

// ---------------------------------------------------------------------------
// fp32 -> bf16 hi/lo elementwise split (for x)
// ---------------------------------------------------------------------------
__global__ __launch_bounds__(256)
void split_f32(const float* __restrict__ in, __nv_bfloat16* __restrict__ oh,
               __nv_bfloat16* __restrict__ ol, size_t n4)
{
    size_t i = (size_t)blockIdx.x * blockDim.x + threadIdx.x;
    if (i >= n4) return;
    float4 v = ((const float4*)in)[i];
    __nv_bfloat16 h0,l0,h1,l1,h2,l2,h3,l3;
    split2(v.x,h0,l0); split2(v.y,h1,l1); split2(v.z,h2,l2); split2(v.w,h3,l3);
    ((__nv_bfloat162*)oh)[2*i]   = __halves2bfloat162(h0,h1);
    ((__nv_bfloat162*)oh)[2*i+1] = __halves2bfloat162(h2,h3);
    ((__nv_bfloat162*)ol)[2*i]   = __halves2bfloat162(l0,l1);
    ((__nv_bfloat162*)ol)[2*i+1] = __halves2bfloat162(l2,l3);
}

// ---------------------------------------------------------------------------
// transpose fp32 [R,C] -> bf16 hi [C,R] (weights)
// ---------------------------------------------------------------------------
__global__ __launch_bounds__(256)
void transpose_h(const float* __restrict__ in, __nv_bfloat16* __restrict__ oh,
                 int R, int C)
{
    __shared__ float tile[32][33];
    const int c0 = blockIdx.x * 32, r0 = blockIdx.y * 32;
    const int tx = threadIdx.x & 31, ty = threadIdx.x >> 5;
    #pragma unroll
    for (int i = 0; i < 4; i++)
        tile[ty + i * 8][tx] = in[(size_t)(r0 + ty + i * 8) * C + c0 + tx];
    __syncthreads();
    #pragma unroll
    for (int i = 0; i < 4; i++) {
        const int ro = c0 + ty + i * 8;
        oh[(size_t)ro * R + r0 + tx] = __float2bfloat16(tile[tx][ty + i * 8]);
    }
}

// ---------------------------------------------------------------------------
// bf16 transpose (V): in [SEQ,DIM] per batch -> out [DIM,SEQ]
// ---------------------------------------------------------------------------
__global__ __launch_bounds__(256)
void transpose_bf16(const __nv_bfloat16* __restrict__ in, __nv_bfloat16* __restrict__ out)
{
    __shared__ __nv_bfloat16 tile[32][33];
    const int z = blockIdx.z;
    in  += (size_t)z * SEQ * DIM;
    out += (size_t)z * DIM * SEQ;
    const int c0 = blockIdx.x * 32, r0 = blockIdx.y * 32;
    const int tx = threadIdx.x & 31, ty = threadIdx.x >> 5;
    #pragma unroll
    for (int i = 0; i < 4; i++)
        tile[ty + i * 8][tx] = in[(size_t)(r0 + ty + i * 8) * DIM + c0 + tx];
    __syncthreads();
    #pragma unroll
    for (int i = 0; i < 4; i++)
        out[(size_t)(c0 + ty + i * 8) * SEQ + r0 + tx] = tile[tx][ty + i * 8];
}

// ---------------------------------------------------------------------------
// Row softmax over 2048 cols; reads fp32 S, writes bf16 hi/lo splits of P.
// ---------------------------------------------------------------------------
__global__ __launch_bounds__(256)
void softmax_split(const float* __restrict__ S, __nv_bfloat16* __restrict__ Ph,
                   __nv_bfloat16* __restrict__ Pl)
{
    const size_t rowOff = (size_t)blockIdx.x * SEQ;
    const float* row = S + rowOff;
    const int t = threadIdx.x;
    __shared__ float red[8];

    float vals[8];
    *(float4*)&vals[0] = *(const float4*)&row[t * 8];
    *(float4*)&vals[4] = *(const float4*)&row[t * 8 + 4];

    float vmax = vals[0];
    #pragma unroll
    for (int i = 1; i < 8; i++) vmax = fmaxf(vmax, vals[i]);
    #pragma unroll
    for (int o = 16; o > 0; o >>= 1)
        vmax = fmaxf(vmax, __shfl_xor_sync(0xffffffffu, vmax, o));
    if ((t & 31) == 0) red[t >> 5] = vmax;
    __syncthreads();
    float m = red[0];
    #pragma unroll
    for (int i = 1; i < 8; i++) m = fmaxf(m, red[i]);
    __syncthreads();

    float sum = 0.f;
    #pragma unroll
    for (int i = 0; i < 8; i++) { vals[i] = __expf(vals[i] - m); sum += vals[i]; }
    #pragma unroll
    for (int o = 16; o > 0; o >>= 1)
        sum += __shfl_xor_sync(0xffffffffu, sum, o);
    if ((t & 31) == 0) red[t >> 5] = sum;
    __syncthreads();
    float tot = red[0];
    #pragma unroll
    for (int i = 1; i < 8; i++) tot += red[i];
    const float inv = 1.0f / tot;

    __nv_bfloat16* ph = Ph + rowOff + t * 8;
    __nv_bfloat16* pl = Pl + rowOff + t * 8;
    #pragma unroll
    for (int i = 0; i < 8; i += 2) {
        float a = vals[i] * inv, b = vals[i + 1] * inv;
        __nv_bfloat16 ah, al, bh, bl;
        split2(a, ah, al); split2(b, bh, bl);
        *(__nv_bfloat162*)(ph + i) = __halves2bfloat162(ah, bh);
        *(__nv_bfloat162*)(pl + i) = __halves2bfloat162(al, bl);
    }
}

// ---------------------------------------------------------------------------
extern "C" void kernel_launch(void* const* d_in, const int* in_sizes, int n_in,
                              void* d_out, int out_size)
{
    const float* x  = (const float*)d_in[0];
    const float* Wq = (const float*)d_in[1];
    const float* bq = (const float*)d_in[2];
    const float* Wk = (const float*)d_in[3];
    const float* bk = (const float*)d_in[4];
    const float* Wv = (const float*)d_in[5];
    const float* bv = (const float*)d_in[6];
    float* out = (float*)d_out;

    cudaFuncSetAttribute(gemm_bs,   cudaFuncAttributeMaxDynamicSharedMemorySize, GEMM_DSMEM);
    cudaFuncSetAttribute(proj_gemm, cudaFuncAttributeMaxDynamicSharedMemorySize, GEMM_DSMEM);

    __nv_bfloat16 *xh, *xl, *wqh, *wkh, *wvh;
    __nv_bfloat16 *qh, *ql, *kh, *vh, *vth, *prh, *prl;
    float *S;
    cudaGetSymbolAddress((void**)&xh,  g_xh);   cudaGetSymbolAddress((void**)&xl,  g_xl);
    cudaGetSymbolAddress((void**)&wqh, g_Wqt_h);
    cudaGetSymbolAddress((void**)&wkh, g_Wkt_h);
    cudaGetSymbolAddress((void**)&wvh, g_Wvt_h);
    cudaGetSymbolAddress((void**)&qh,  g_Qh);   cudaGetSymbolAddress((void**)&ql,  g_Ql);
    cudaGetSymbolAddress((void**)&kh,  g_Kh);
    cudaGetSymbolAddress((void**)&vh,  g_Vh);
    cudaGetSymbolAddress((void**)&vth, g_Vth);
    cudaGetSymbolAddress((void**)&S,   g_S);
    cudaGetSymbolAddress((void**)&prh, g_Ph);   cudaGetSymbolAddress((void**)&prl, g_Pl);

    // 1) split x -> bf16 hi/lo
    {
        size_t n4 = (size_t)MTOT * DIM / 4;
        split_f32<<<(unsigned)((n4 + 255) / 256), 256>>>(x, xh, xl, n4);
    }
    // 2) transpose weights (hi only): W[D, E] -> Wt[E, D]
    {
        dim3 g(DIM / 32, DIM / 32, 1);
        transpose_h<<<g, 256>>>(Wq, wqh, DIM, DIM);
        transpose_h<<<g, 256>>>(Wk, wkh, DIM, DIM);
        transpose_h<<<g, 256>>>(Wv, wvh, DIM, DIM);
    }
    // 3) merged QKV projections (one launch, z selects target)
    {
        dim3 g(DIM / 128, MTOT / 128, 3);
        proj_gemm<<<g, 128, GEMM_DSMEM>>>(bq, bk, bv);
    }
    // 4) transpose V (bf16 hi) per batch: [SEQ, DIM] -> [DIM, SEQ]
    {
        dim3 g(DIM / 32, SEQ / 32, BATCH);
        transpose_bf16<<<g, 256>>>(vh, vth);
    }
    // 5) scores = scale * Q K^T per batch (fp32 out), 2-term
    {
        const float scale = 1.0f / sqrtf((float)DIM);
        dim3 g(SEQ / 128, SEQ / 128, BATCH);
        gemm_bs<<<g, 128, GEMM_DSMEM>>>(qh, ql, kh, S,
                                        SEQ, SEQ, DIM,
                                        (size_t)SEQ * DIM, (size_t)SEQ * DIM,
                                        (size_t)SEQ * SEQ, scale);
    }
    // 6) softmax -> P bf16 splits
    softmax_split<<<BATCH * SEQ, 256>>>(S, prh, prl);

    // 7) out = P V per batch (fp32 out), 2-term: A = P split, B = Vt hi
    {
        dim3 g(DIM / 128, SEQ / 128, BATCH);
        gemm_bs<<<g, 128, GEMM_DSMEM>>>(prh, prl, vth, out,
                                        SEQ, DIM, SEQ,
                                        (size_t)SEQ * SEQ, (size_t)DIM * SEQ,
                                        (size_t)SEQ * DIM, 1.0f);
    }
}

// round 10
// speedup vs baseline: 2.1643x; 1.3108x over previous
#include <cuda_runtime.h>
#include <cuda_bf16.h>
#include <math.h>
#include <stdint.h>

#define BATCH 8
#define SEQ   2048
#define DIM   512
#define MTOT  (BATCH*SEQ)   // 16384

// ---------------------------------------------------------------------------
// Device scratch (allocation-free rule: __device__ globals)
// ---------------------------------------------------------------------------
__device__ __nv_bfloat16 g_xh[MTOT * DIM], g_xl[MTOT * DIM];
__device__ __nv_bfloat16 g_Wqt_h[DIM * DIM];
__device__ __nv_bfloat16 g_Wkt_h[DIM * DIM];
__device__ __nv_bfloat16 g_Wvt_h[DIM * DIM];
__device__ __nv_bfloat16 g_Qh[MTOT * DIM], g_Ql[MTOT * DIM];
__device__ __nv_bfloat16 g_Kh[MTOT * DIM];
__device__ __nv_bfloat16 g_Vh[MTOT * DIM];                      // row-major V hi
__device__ __nv_bfloat16 g_Vth[MTOT * DIM];                     // [B][DIM][SEQ]
__device__ __nv_bfloat16 g_Ph[(size_t)BATCH * SEQ * SEQ];       // unnormalized exp
__device__ float         g_rpart[(size_t)MTOT * 32];            // partial row sums
__device__ float         g_rinv[MTOT];                          // 1/rowsum

// ---------------------------------------------------------------------------
// Baseline-ISA helpers: ldmatrix / mma.sync / cp.async  (no 'a' features)
// ---------------------------------------------------------------------------
__device__ __forceinline__ uint32_t smem_to_u32(const void* p) {
    uint32_t a;
    asm("{ .reg .u64 t; cvta.to.shared.u64 t, %1; cvt.u32.u64 %0, t; }" : "=r"(a) : "l"(p));
    return a;
}
__device__ __forceinline__ void ldsm4(uint32_t* r, uint32_t addr) {
    asm volatile("ldmatrix.sync.aligned.m8n8.x4.shared.b16 {%0,%1,%2,%3}, [%4];"
                 : "=r"(r[0]), "=r"(r[1]), "=r"(r[2]), "=r"(r[3]) : "r"(addr));
}
__device__ __forceinline__ void mma_bf16(float* c, const uint32_t* a,
                                         uint32_t b0, uint32_t b1) {
    asm volatile("mma.sync.aligned.m16n8k16.row.col.f32.bf16.bf16.f32 "
                 "{%0,%1,%2,%3}, {%4,%5,%6,%7}, {%8,%9}, {%0,%1,%2,%3};"
                 : "+f"(c[0]), "+f"(c[1]), "+f"(c[2]), "+f"(c[3])
                 : "r"(a[0]), "r"(a[1]), "r"(a[2]), "r"(a[3]), "r"(b0), "r"(b1));
}
__device__ __forceinline__ void cp16(uint32_t dst, const void* src) {
    asm volatile("cp.async.cg.shared.global [%0], [%1], 16;" :: "r"(dst), "l"(src));
}
#define CP_COMMIT() asm volatile("cp.async.commit_group;" ::: "memory")
#define CP_WAIT1()  asm volatile("cp.async.wait_group 1;" ::: "memory")

__device__ __forceinline__ void split2(float a, __nv_bfloat16& h, __nv_bfloat16& l) {
    h = __float2bfloat16(a);
    l = __float2bfloat16(a - __bfloat162float(h));
}

// Bank-conflict-free swizzle for 64B rows.
#define SWZ(r, ch) ((uint32_t)(r) * 64u + (uint32_t)((((ch) ^ (((r) >> 1) & 3)) & 3) << 4))

// ---------------------------------------------------------------------------
// bf16-split HMMA GEMM mainloop. Block tile 128x128, BK=32, 4 warps (2Mx2N)
// of 64x64 tiles, 3-stage cp.async pipeline, single __syncthreads per chunk.
// ALO=true : 3 smem tiles (Ah, Al, Bh), 2-term MMA.
// ALO=false: 2 smem tiles (Ah, Bh), 1-term MMA.
// ---------------------------------------------------------------------------
#define T_B    (128 * 64)                  // 8192 B per tile
#define NSTAGE 3

template<bool ALO>
__device__ __forceinline__ void issue_stage(uint32_t sAddr,
    const __nv_bfloat16* pAh, const __nv_bfloat16* pAl,
    const __nv_bfloat16* pBh,
    int lda, int ldb, int k0, int t)
{
    const int NT = ALO ? 3 : 2;
    const __nv_bfloat16* base[3] = { pAh, ALO ? pAl : pBh, pBh };
    const int ld2[3] = { lda, ALO ? lda : ldb, ldb };
    #pragma unroll
    for (int i = 0; i < NT * 4; i++) {      // NT*512 x 16B transfers / 128 thr
        const int j    = t + i * 128;
        const int tile = j >> 9;            // 0..NT-1
        const int r    = (j & 511) >> 2;    // 0..127
        const int ch   = j & 3;
        const __nv_bfloat16* src = base[tile] + (size_t)r * ld2[tile] + k0 + ch * 8;
        cp16(sAddr + tile * T_B + SWZ(r, ch), src);
    }
}

template<bool ALO>
__device__ __forceinline__ void gemm_mainloop(uint32_t sb,
    const __nv_bfloat16* pAh, const __nv_bfloat16* pAl,
    const __nv_bfloat16* pBh,
    int lda, int ldb, int K, int t, int wm, int wn, int lane,
    float acc[4][8][4])
{
    const uint32_t STAGEB = (ALO ? 3 : 2) * T_B;
    const uint32_t BOFF   = (ALO ? 2 : 1) * T_B;
    const int nc = K / 32;

    issue_stage<ALO>(sb,          pAh, pAl, pBh, lda, ldb,  0, t); CP_COMMIT();
    issue_stage<ALO>(sb + STAGEB, pAh, pAl, pBh, lda, ldb, 32, t); CP_COMMIT();

    const int lrow = lane & 15;
    const int cS   = (lane >> 4) & 1;

    for (int c = 0; c < nc; c++) {
        CP_WAIT1();
        __syncthreads();
        if (c + 2 < nc)
            issue_stage<ALO>(sb + ((c + 2) % NSTAGE) * STAGEB, pAh, pAl, pBh,
                             lda, ldb, (c + 2) * 32, t);
        CP_COMMIT();

        const uint32_t st = sb + (c % NSTAGE) * STAGEB;
        #pragma unroll
        for (int ks = 0; ks < 2; ks++) {
            const int chunk = ks * 2 + cS;
            uint32_t ah[4][4], al[4][4];
            #pragma unroll
            for (int mi = 0; mi < 4; mi++) {
                const int rowA = wm * 64 + mi * 16 + lrow;
                const uint32_t offA = SWZ(rowA, chunk);
                ldsm4(ah[mi], st + offA);
                if (ALO) ldsm4(al[mi], st + T_B + offA);
            }
            #pragma unroll
            for (int g = 0; g < 4; g++) {
                const int rowB = wn * 64 + g * 16 + lrow;
                const uint32_t offB = SWZ(rowB, chunk);
                uint32_t qh[4];
                ldsm4(qh, st + BOFF + offB);
                #pragma unroll
                for (int mi = 0; mi < 4; mi++) {
                    mma_bf16(acc[mi][2*g],   ah[mi], qh[0], qh[2]);
                    if (ALO) mma_bf16(acc[mi][2*g], al[mi], qh[0], qh[2]);
                    mma_bf16(acc[mi][2*g+1], ah[mi], qh[1], qh[3]);
                    if (ALO) mma_bf16(acc[mi][2*g+1], al[mi], qh[1], qh[3]);
                }
            }
        }
    }
}

#define ZERO_ACC(acc)                                                \
    _Pragma("unroll")                                                \
    for (int mi = 0; mi < 4; mi++)                                   \
        _Pragma("unroll")                                            \
        for (int ni = 0; ni < 8; ni++)                               \
            _Pragma("unroll")                                        \
            for (int r = 0; r < 4; r++) acc[mi][ni][r] = 0.0f;

// ---------------------------------------------------------------------------
// Merged QKV projection: grid.z selects (W, bias, output) triple.
// out = relu(x W + b); Q -> bf16 hi/lo splits; K, V -> bf16 hi only.
// ---------------------------------------------------------------------------
__global__ __launch_bounds__(128, 2)
void proj_gemm(const float* __restrict__ bq, const float* __restrict__ bk,
               const float* __restrict__ bv)
{
    extern __shared__ char smem[];
    const uint32_t sb = smem_to_u32(smem);
    const int t = threadIdx.x, wid = t >> 5, lane = t & 31;
    const int wm = wid >> 1, wn = wid & 1;

    const int z = blockIdx.z;                 // 0=Q 1=K 2=V
    const int rowBase = blockIdx.y * 128;
    const int colBase = blockIdx.x * 128;

    const __nv_bfloat16* pAh = g_xh + (size_t)rowBase * DIM;
    const __nv_bfloat16* pAl = g_xl + (size_t)rowBase * DIM;
    const __nv_bfloat16* Wh = (z == 0) ? g_Wqt_h : (z == 1) ? g_Wkt_h : g_Wvt_h;
    const float* bias = (z == 0) ? bq : (z == 1) ? bk : bv;
    const __nv_bfloat16* pBh = Wh + (size_t)colBase * DIM;

    float acc[4][8][4];
    ZERO_ACC(acc)
    gemm_mainloop<true>(sb, pAh, pAl, pBh, DIM, DIM, DIM, t, wm, wn, lane, acc);

    __nv_bfloat16* Ch = (z == 0) ? g_Qh : (z == 1) ? g_Kh : g_Vh;

    #pragma unroll
    for (int mi = 0; mi < 4; mi++)
        #pragma unroll
        for (int rr = 0; rr < 2; rr++) {
            const int r = rowBase + wm * 64 + mi * 16 + rr * 8 + (lane >> 2);
            #pragma unroll
            for (int ni = 0; ni < 8; ni++) {
                const int cc = colBase + wn * 64 + ni * 8 + (lane & 3) * 2;
                float a = acc[mi][ni][rr * 2 + 0] + bias[cc];
                float b = acc[mi][ni][rr * 2 + 1] + bias[cc + 1];
                a = fmaxf(a, 0.0f); b = fmaxf(b, 0.0f);
                __nv_bfloat16 hA, lA, hB, lB;
                split2(a, hA, lA); split2(b, hB, lB);
                *(__nv_bfloat162*)(Ch + (size_t)r * DIM + cc) = __halves2bfloat162(hA, hB);
                if (z == 0)
                    *(__nv_bfloat162*)(g_Ql + (size_t)r * DIM + cc) = __halves2bfloat162(lA, lB);
            }
        }
}

// ---------------------------------------------------------------------------
// Scores GEMM with fused exp: P~ = exp(scale * Q K^T) (bf16 hi), plus
// deterministic partial row sums in g_rpart[row][ctaX*2+wn].
// ---------------------------------------------------------------------------
__global__ __launch_bounds__(128, 2)
void score_gemm(float scale)
{
    extern __shared__ char smem[];
    const uint32_t sb = smem_to_u32(smem);
    const int t = threadIdx.x, wid = t >> 5, lane = t & 31;
    const int wm = wid >> 1, wn = wid & 1;

    const int z = blockIdx.z;
    const int rowBase = blockIdx.y * 128;
    const int colBase = blockIdx.x * 128;

    const __nv_bfloat16* pAh = g_Qh + (size_t)z * SEQ * DIM + (size_t)rowBase * DIM;
    const __nv_bfloat16* pAl = g_Ql + (size_t)z * SEQ * DIM + (size_t)rowBase * DIM;
    const __nv_bfloat16* pBh = g_Kh + (size_t)z * SEQ * DIM + (size_t)colBase * DIM;

    float acc[4][8][4];
    ZERO_ACC(acc)
    gemm_mainloop<true>(sb, pAh, pAl, pBh, DIM, DIM, DIM, t, wm, wn, lane, acc);

    __nv_bfloat16* Ph = g_Ph + (size_t)z * SEQ * SEQ;

    #pragma unroll
    for (int mi = 0; mi < 4; mi++)
        #pragma unroll
        for (int rr = 0; rr < 2; rr++) {
            const int r = rowBase + wm * 64 + mi * 16 + rr * 8 + (lane >> 2);
            float rsum = 0.0f;
            #pragma unroll
            for (int ni = 0; ni < 8; ni++) {
                const int cc = colBase + wn * 64 + ni * 8 + (lane & 3) * 2;
                float ea = __expf(acc[mi][ni][rr * 2 + 0] * scale);
                float eb = __expf(acc[mi][ni][rr * 2 + 1] * scale);
                rsum += ea + eb;
                *(__nv_bfloat162*)(Ph + (size_t)r * SEQ + cc) =
                    __halves2bfloat162(__float2bfloat16(ea), __float2bfloat16(eb));
            }
            // reduce the 4 lanes (lane&3) holding this row's column chunks
            rsum += __shfl_xor_sync(0xffffffffu, rsum, 1);
            rsum += __shfl_xor_sync(0xffffffffu, rsum, 2);
            if ((lane & 3) == 0)
                g_rpart[((size_t)z * SEQ + r) * 32 + blockIdx.x * 2 + wn] = rsum;
        }
}

// ---------------------------------------------------------------------------
// Row-sum reduce: g_rinv[row] = 1 / sum(g_rpart[row][0..31])   (deterministic)
// ---------------------------------------------------------------------------
__global__ __launch_bounds__(256)
void rsum_reduce()
{
    const int row = blockIdx.x * 256 + threadIdx.x;
    if (row >= MTOT) return;
    const float* p = g_rpart + (size_t)row * 32;
    float s = 0.0f;
    #pragma unroll
    for (int i = 0; i < 32; i++) s += p[i];
    g_rinv[row] = 1.0f / s;
}

// ---------------------------------------------------------------------------
// PV GEMM (1-term): out = (P~ x Vt^T) * rinv[row]
// ---------------------------------------------------------------------------
__global__ __launch_bounds__(128, 2)
void pv_gemm(float* __restrict__ out)
{
    extern __shared__ char smem[];
    const uint32_t sb = smem_to_u32(smem);
    const int t = threadIdx.x, wid = t >> 5, lane = t & 31;
    const int wm = wid >> 1, wn = wid & 1;

    const int z = blockIdx.z;
    const int rowBase = blockIdx.y * 128;
    const int colBase = blockIdx.x * 128;

    const __nv_bfloat16* pAh = g_Ph  + (size_t)z * SEQ * SEQ + (size_t)rowBase * SEQ;
    const __nv_bfloat16* pBh = g_Vth + (size_t)z * DIM * SEQ + (size_t)colBase * SEQ;

    float acc[4][8][4];
    ZERO_ACC(acc)
    gemm_mainloop<false>(sb, pAh, nullptr, pBh, SEQ, SEQ, SEQ, t, wm, wn, lane, acc);

    #pragma unroll
    for (int mi = 0; mi < 4; mi++)
        #pragma unroll
        for (int rr = 0; rr < 2; rr++) {
            const int r = rowBase + wm * 64 + mi * 16 + rr * 8 + (lane >> 2);
            const float rinv = g_rinv[z * SEQ + r];
            #pragma unroll
            for (int ni = 0; ni < 8; ni++) {
                const int cc = colBase + wn * 64 + ni * 8 + (lane & 3) * 2;
                float a = acc[mi][ni][rr * 2 + 0] * rinv;
                float b = acc[mi][ni][rr * 2 + 1] * rinv;
                *(float2*)(out + (size_t)z * SEQ * DIM + (size_t)r * DIM + cc) =
                    make_float2(a, b);
            }
        }
}

// ---------------------------------------------------------------------------
// fp32 -> bf16 hi/lo elementwise split (for x)
// ---------------------------------------------------------------------------
__global__ __launch_bounds__(256)
void split_f32(const float* __restrict__ in, __nv_bfloat16* __restrict__ oh,
               __nv_bfloat16* __restrict__ ol, size_t n4)
{
    size_t i = (size_t)blockIdx.x * blockDim.x + threadIdx.x;
    if (i >= n4) return;
    float4 v = ((const float4*)in)[i];
    __nv_bfloat16 h0,l0,h1,l1,h2,l2,h3,l3;
    split2(v.x,h0,l0); split2(v.y,h1,l1); split2(v.z,h2,l2); split2(v.w,h3,l3);
    ((__nv_bfloat162*)oh)[2*i]   = __halves2bfloat162(h0,h1);
    ((__nv_bfloat162*)oh)[2*i+1] = __halves2bfloat162(h2,h3);
    ((__nv_bfloat162*)ol)[2*i]   = __halves2bfloat162(l0,l1);
    ((__nv_bfloat162*)ol)[2*i+1] = __halves2bfloat162(l2,l3);
}

// ---------------------------------------------------------------------------
// transpose fp32 [R,C] -> bf16 hi [C,R] (weights)
// ---------------------------------------------------------------------------
__global__ __launch_bounds__(256)
void transpose_h(const float* __restrict__ in, __nv_bfloat16* __restrict__ oh,
                 int R, int C)
{
    __shared__ float tile[32][33];
    const int c0 = blockIdx.x * 32, r0 = blockIdx.y * 32;
    const int tx = threadIdx.x & 31, ty = threadIdx.x >> 5;
    #pragma unroll
    for (int i = 0; i < 4; i++)
        tile[ty + i * 8][tx] = in[(size_t)(r0 + ty + i * 8) * C + c0 + tx];
    __syncthreads();
    #pragma unroll
    for (int i = 0; i < 4; i++) {
        const int ro = c0 + ty + i * 8;
        oh[(size_t)ro * R + r0 + tx] = __float2bfloat16(tile[tx][ty + i * 8]);
    }
}

// ---------------------------------------------------------------------------
// bf16 transpose (V): in [SEQ,DIM] per batch -> out [DIM,SEQ]
// ---------------------------------------------------------------------------
__global__ __launch_bounds__(256)
void transpose_bf16(const __nv_bfloat16* __restrict__ in, __nv_bfloat16* __restrict__ out)
{
    __shared__ __nv_bfloat16 tile[32][33];
    const int z = blockIdx.z;
    in  += (size_t)z * SEQ * DIM;
    out += (size_t)z * DIM * SEQ;
    const int c0 = blockIdx.x * 32, r0 = blockIdx.y * 32;
    const int tx = threadIdx.x & 31, ty = threadIdx.x >> 5;
    #pragma unroll
    for (int i = 0; i < 4; i++)
        tile[ty + i * 8][tx] = in[(size_t)(r0 + ty + i * 8) * DIM + c0 + tx];
    __syncthreads();
    #pragma unroll
    for (int i = 0; i < 4; i++)
        out[(size_t)(c0 + ty + i * 8) * SEQ + r0 + tx] = tile[tx][ty + i * 8];
}

// ---------------------------------------------------------------------------
extern "C" void kernel_launch(void* const* d_in, const int* in_sizes, int n_in,
                              void* d_out, int out_size)
{
    const float* x  = (const float*)d_in[0];
    const float* Wq = (const float*)d_in[1];
    const float* bq = (const float*)d_in[2];
    const float* Wk = (const float*)d_in[3];
    const float* bk = (const float*)d_in[4];
    const float* Wv = (const float*)d_in[5];
    const float* bv = (const float*)d_in[6];
    float* out = (float*)d_out;

    const int DSMEM3 = NSTAGE * 3 * T_B;   // 73728 B
    const int DSMEM2 = NSTAGE * 2 * T_B;   // 49152 B
    cudaFuncSetAttribute(proj_gemm,  cudaFuncAttributeMaxDynamicSharedMemorySize, DSMEM3);
    cudaFuncSetAttribute(score_gemm, cudaFuncAttributeMaxDynamicSharedMemorySize, DSMEM3);
    cudaFuncSetAttribute(pv_gemm,    cudaFuncAttributeMaxDynamicSharedMemorySize, DSMEM2);

    __nv_bfloat16 *xh, *xl, *wqh, *wkh, *wvh, *vh, *vth;
    cudaGetSymbolAddress((void**)&xh,  g_xh);   cudaGetSymbolAddress((void**)&xl,  g_xl);
    cudaGetSymbolAddress((void**)&wqh, g_Wqt_h);
    cudaGetSymbolAddress((void**)&wkh, g_Wkt_h);
    cudaGetSymbolAddress((void**)&wvh, g_Wvt_h);
    cudaGetSymbolAddress((void**)&vh,  g_Vh);
    cudaGetSymbolAddress((void**)&vth, g_Vth);

    // 1) split x -> bf16 hi/lo
    {
        size_t n4 = (size_t)MTOT * DIM / 4;
        split_f32<<<(unsigned)((n4 + 255) / 256), 256>>>(x, xh, xl, n4);
    }
    // 2) transpose weights (hi only): W[D, E] -> Wt[E, D]
    {
        dim3 g(DIM / 32, DIM / 32, 1);
        transpose_h<<<g, 256>>>(Wq, wqh, DIM, DIM);
        transpose_h<<<g, 256>>>(Wk, wkh, DIM, DIM);
        transpose_h<<<g, 256>>>(Wv, wvh, DIM, DIM);
    }
    // 3) merged QKV projections
    {
        dim3 g(DIM / 128, MTOT / 128, 3);
        proj_gemm<<<g, 128, DSMEM3>>>(bq, bk, bv);
    }
    // 4) transpose V (bf16 hi) per batch: [SEQ, DIM] -> [DIM, SEQ]
    {
        dim3 g(DIM / 32, SEQ / 32, BATCH);
        transpose_bf16<<<g, 256>>>(vh, vth);
    }
    // 5) P~ = exp(scale * Q K^T) + partial row sums (fused softmax, no max-sub)
    {
        const float scale = 1.0f / sqrtf((float)DIM);
        dim3 g(SEQ / 128, SEQ / 128, BATCH);
        score_gemm<<<g, 128, DSMEM3>>>(scale);
    }
    // 6) row-sum reduce -> 1/rowsum
    rsum_reduce<<<(MTOT + 255) / 256, 256>>>();

    // 7) out = (P~ V) / rowsum, 1-term PV
    {
        dim3 g(DIM / 128, SEQ / 128, BATCH);
        pv_gemm<<<g, 128, DSMEM2>>>(out);
    }
}

// round 11
// speedup vs baseline: 3.0690x; 1.4180x over previous
#include <cuda_runtime.h>
#include <cuda_bf16.h>
#include <math.h>
#include <stdint.h>

#define BATCH 8
#define SEQ   2048
#define DIM   512
#define MTOT  (BATCH*SEQ)   // 16384

// ---------------------------------------------------------------------------
// Device scratch (allocation-free rule: __device__ globals)
// ---------------------------------------------------------------------------
__device__ __nv_bfloat16 g_xh[MTOT * DIM];
__device__ __nv_bfloat16 g_Wqt_h[DIM * DIM];
__device__ __nv_bfloat16 g_Wkt_h[DIM * DIM];
__device__ __nv_bfloat16 g_Wvt_h[DIM * DIM];
__device__ __nv_bfloat16 g_Qh[MTOT * DIM];
__device__ __nv_bfloat16 g_Kh[MTOT * DIM];
__device__ __nv_bfloat16 g_Vh[MTOT * DIM];                      // row-major V hi
__device__ __nv_bfloat16 g_Vth[MTOT * DIM];                     // [B][DIM][SEQ]
__device__ __nv_bfloat16 g_Ph[(size_t)BATCH * SEQ * SEQ];       // unnormalized exp
__device__ float         g_rpart[(size_t)MTOT * 32];            // partial row sums
__device__ float         g_rinv[MTOT];                          // 1/rowsum

// ---------------------------------------------------------------------------
// Baseline-ISA helpers: ldmatrix / mma.sync / cp.async  (no 'a' features)
// ---------------------------------------------------------------------------
__device__ __forceinline__ uint32_t smem_to_u32(const void* p) {
    uint32_t a;
    asm("{ .reg .u64 t; cvta.to.shared.u64 t, %1; cvt.u32.u64 %0, t; }" : "=r"(a) : "l"(p));
    return a;
}
__device__ __forceinline__ void ldsm4(uint32_t* r, uint32_t addr) {
    asm volatile("ldmatrix.sync.aligned.m8n8.x4.shared.b16 {%0,%1,%2,%3}, [%4];"
                 : "=r"(r[0]), "=r"(r[1]), "=r"(r[2]), "=r"(r[3]) : "r"(addr));
}
__device__ __forceinline__ void mma_bf16(float* c, const uint32_t* a,
                                         uint32_t b0, uint32_t b1) {
    asm volatile("mma.sync.aligned.m16n8k16.row.col.f32.bf16.bf16.f32 "
                 "{%0,%1,%2,%3}, {%4,%5,%6,%7}, {%8,%9}, {%0,%1,%2,%3};"
                 : "+f"(c[0]), "+f"(c[1]), "+f"(c[2]), "+f"(c[3])
                 : "r"(a[0]), "r"(a[1]), "r"(a[2]), "r"(a[3]), "r"(b0), "r"(b1));
}
__device__ __forceinline__ void cp16(uint32_t dst, const void* src) {
    asm volatile("cp.async.cg.shared.global [%0], [%1], 16;" :: "r"(dst), "l"(src));
}
#define CP_COMMIT() asm volatile("cp.async.commit_group;" ::: "memory")
#define CP_WAIT1()  asm volatile("cp.async.wait_group 1;" ::: "memory")

// Bank-conflict-free swizzle for 64B rows.
#define SWZ(r, ch) ((uint32_t)(r) * 64u + (uint32_t)((((ch) ^ (((r) >> 1) & 3)) & 3) << 4))

// ---------------------------------------------------------------------------
// 1-term bf16 HMMA GEMM mainloop. Block tile 128x128, BK=32, 4 warps (2Mx2N)
// of 64x64 tiles, 3-stage cp.async pipeline, single __syncthreads per chunk.
// 2 smem tiles per stage (A, B), 48KB total -> 2 CTAs/SM.
// ---------------------------------------------------------------------------
#define T_B    (128 * 64)                  // 8192 B per tile
#define STAGEB (2 * T_B)                   // 16384 B
#define NSTAGE 3
#define GEMM_DSMEM (NSTAGE * STAGEB)       // 49152 B

__device__ __forceinline__ void issue_stage(uint32_t sAddr,
    const __nv_bfloat16* pA, const __nv_bfloat16* pB,
    int lda, int ldb, int k0, int t)
{
    #pragma unroll
    for (int i = 0; i < 8; i++) {           // 1024 x 16B transfers / 128 thr
        const int j    = t + i * 128;
        const int tile = j >> 9;            // 0..1
        const int r    = (j & 511) >> 2;    // 0..127
        const int ch   = j & 3;
        const __nv_bfloat16* src = (tile ? pB : pA) + (size_t)r * (tile ? ldb : lda)
                                   + k0 + ch * 8;
        cp16(sAddr + tile * T_B + SWZ(r, ch), src);
    }
}

__device__ __forceinline__ void gemm_mainloop(uint32_t sb,
    const __nv_bfloat16* pA, const __nv_bfloat16* pB,
    int lda, int ldb, int K, int t, int wm, int wn, int lane,
    float acc[4][8][4])
{
    const int nc = K / 32;

    issue_stage(sb,          pA, pB, lda, ldb,  0, t); CP_COMMIT();
    issue_stage(sb + STAGEB, pA, pB, lda, ldb, 32, t); CP_COMMIT();

    const int lrow = lane & 15;
    const int cS   = (lane >> 4) & 1;

    for (int c = 0; c < nc; c++) {
        CP_WAIT1();
        __syncthreads();
        if (c + 2 < nc)
            issue_stage(sb + ((c + 2) % NSTAGE) * STAGEB, pA, pB,
                        lda, ldb, (c + 2) * 32, t);
        CP_COMMIT();

        const uint32_t st = sb + (c % NSTAGE) * STAGEB;
        #pragma unroll
        for (int ks = 0; ks < 2; ks++) {
            const int chunk = ks * 2 + cS;
            uint32_t ah[4][4];
            #pragma unroll
            for (int mi = 0; mi < 4; mi++) {
                const int rowA = wm * 64 + mi * 16 + lrow;
                ldsm4(ah[mi], st + SWZ(rowA, chunk));
            }
            #pragma unroll
            for (int g = 0; g < 4; g++) {
                const int rowB = wn * 64 + g * 16 + lrow;
                uint32_t qh[4];
                ldsm4(qh, st + T_B + SWZ(rowB, chunk));
                #pragma unroll
                for (int mi = 0; mi < 4; mi++) {
                    mma_bf16(acc[mi][2*g],   ah[mi], qh[0], qh[2]);
                    mma_bf16(acc[mi][2*g+1], ah[mi], qh[1], qh[3]);
                }
            }
        }
    }
}

#define ZERO_ACC(acc)                                                \
    _Pragma("unroll")                                                \
    for (int mi = 0; mi < 4; mi++)                                   \
        _Pragma("unroll")                                            \
        for (int ni = 0; ni < 8; ni++)                               \
            _Pragma("unroll")                                        \
            for (int r = 0; r < 4; r++) acc[mi][ni][r] = 0.0f;

// ---------------------------------------------------------------------------
// Merged QKV projection: grid.z selects (W, bias, output) triple.
// out = relu(x W + b) -> bf16 hi.
// ---------------------------------------------------------------------------
__global__ __launch_bounds__(128, 2)
void proj_gemm(const float* __restrict__ bq, const float* __restrict__ bk,
               const float* __restrict__ bv)
{
    extern __shared__ char smem[];
    const uint32_t sb = smem_to_u32(smem);
    const int t = threadIdx.x, wid = t >> 5, lane = t & 31;
    const int wm = wid >> 1, wn = wid & 1;

    const int z = blockIdx.z;                 // 0=Q 1=K 2=V
    const int rowBase = blockIdx.y * 128;
    const int colBase = blockIdx.x * 128;

    const __nv_bfloat16* pA = g_xh + (size_t)rowBase * DIM;
    const __nv_bfloat16* Wh = (z == 0) ? g_Wqt_h : (z == 1) ? g_Wkt_h : g_Wvt_h;
    const float* bias = (z == 0) ? bq : (z == 1) ? bk : bv;
    const __nv_bfloat16* pB = Wh + (size_t)colBase * DIM;

    float acc[4][8][4];
    ZERO_ACC(acc)
    gemm_mainloop(sb, pA, pB, DIM, DIM, DIM, t, wm, wn, lane, acc);

    __nv_bfloat16* Ch = (z == 0) ? g_Qh : (z == 1) ? g_Kh : g_Vh;

    #pragma unroll
    for (int mi = 0; mi < 4; mi++)
        #pragma unroll
        for (int rr = 0; rr < 2; rr++) {
            const int r = rowBase + wm * 64 + mi * 16 + rr * 8 + (lane >> 2);
            #pragma unroll
            for (int ni = 0; ni < 8; ni++) {
                const int cc = colBase + wn * 64 + ni * 8 + (lane & 3) * 2;
                float a = acc[mi][ni][rr * 2 + 0] + bias[cc];
                float b = acc[mi][ni][rr * 2 + 1] + bias[cc + 1];
                a = fmaxf(a, 0.0f); b = fmaxf(b, 0.0f);
                *(__nv_bfloat162*)(Ch + (size_t)r * DIM + cc) =
                    __halves2bfloat162(__float2bfloat16(a), __float2bfloat16(b));
            }
        }
}

// ---------------------------------------------------------------------------
// Scores GEMM with fused exp: P~ = exp(scale * Q K^T) (bf16), plus
// deterministic partial row sums in g_rpart[row][ctaX*2+wn].
// ---------------------------------------------------------------------------
__global__ __launch_bounds__(128, 2)
void score_gemm(float scale)
{
    extern __shared__ char smem[];
    const uint32_t sb = smem_to_u32(smem);
    const int t = threadIdx.x, wid = t >> 5, lane = t & 31;
    const int wm = wid >> 1, wn = wid & 1;

    const int z = blockIdx.z;
    const int rowBase = blockIdx.y * 128;
    const int colBase = blockIdx.x * 128;

    const __nv_bfloat16* pA = g_Qh + (size_t)z * SEQ * DIM + (size_t)rowBase * DIM;
    const __nv_bfloat16* pB = g_Kh + (size_t)z * SEQ * DIM + (size_t)colBase * DIM;

    float acc[4][8][4];
    ZERO_ACC(acc)
    gemm_mainloop(sb, pA, pB, DIM, DIM, DIM, t, wm, wn, lane, acc);

    __nv_bfloat16* Ph = g_Ph + (size_t)z * SEQ * SEQ;

    #pragma unroll
    for (int mi = 0; mi < 4; mi++)
        #pragma unroll
        for (int rr = 0; rr < 2; rr++) {
            const int r = rowBase + wm * 64 + mi * 16 + rr * 8 + (lane >> 2);
            float rsum = 0.0f;
            #pragma unroll
            for (int ni = 0; ni < 8; ni++) {
                const int cc = colBase + wn * 64 + ni * 8 + (lane & 3) * 2;
                float ea = __expf(acc[mi][ni][rr * 2 + 0] * scale);
                float eb = __expf(acc[mi][ni][rr * 2 + 1] * scale);
                rsum += ea + eb;
                *(__nv_bfloat162*)(Ph + (size_t)r * SEQ + cc) =
                    __halves2bfloat162(__float2bfloat16(ea), __float2bfloat16(eb));
            }
            rsum += __shfl_xor_sync(0xffffffffu, rsum, 1);
            rsum += __shfl_xor_sync(0xffffffffu, rsum, 2);
            if ((lane & 3) == 0)
                g_rpart[((size_t)z * SEQ + r) * 32 + blockIdx.x * 2 + wn] = rsum;
        }
}

// ---------------------------------------------------------------------------
// Row-sum reduce: g_rinv[row] = 1 / sum(g_rpart[row][0..31])   (deterministic)
// ---------------------------------------------------------------------------
__global__ __launch_bounds__(256)
void rsum_reduce()
{
    const int row = blockIdx.x * 256 + threadIdx.x;
    if (row >= MTOT) return;
    const float* p = g_rpart + (size_t)row * 32;
    float s = 0.0f;
    #pragma unroll
    for (int i = 0; i < 32; i++) s += p[i];
    g_rinv[row] = 1.0f / s;
}

// ---------------------------------------------------------------------------
// PV GEMM (1-term): out = (P~ x Vt^T) * rinv[row]
// ---------------------------------------------------------------------------
__global__ __launch_bounds__(128, 2)
void pv_gemm(float* __restrict__ out)
{
    extern __shared__ char smem[];
    const uint32_t sb = smem_to_u32(smem);
    const int t = threadIdx.x, wid = t >> 5, lane = t & 31;
    const int wm = wid >> 1, wn = wid & 1;

    const int z = blockIdx.z;
    const int rowBase = blockIdx.y * 128;
    const int colBase = blockIdx.x * 128;

    const __nv_bfloat16* pA = g_Ph  + (size_t)z * SEQ * SEQ + (size_t)rowBase * SEQ;
    const __nv_bfloat16* pB = g_Vth + (size_t)z * DIM * SEQ + (size_t)colBase * SEQ;

    float acc[4][8][4];
    ZERO_ACC(acc)
    gemm_mainloop(sb, pA, pB, SEQ, SEQ, SEQ, t, wm, wn, lane, acc);

    #pragma unroll
    for (int mi = 0; mi < 4; mi++)
        #pragma unroll
        for (int rr = 0; rr < 2; rr++) {
            const int r = rowBase + wm * 64 + mi * 16 + rr * 8 + (lane >> 2);
            const float rinv = g_rinv[z * SEQ + r];
            #pragma unroll
            for (int ni = 0; ni < 8; ni++) {
                const int cc = colBase + wn * 64 + ni * 8 + (lane & 3) * 2;
                float a = acc[mi][ni][rr * 2 + 0] * rinv;
                float b = acc[mi][ni][rr * 2 + 1] * rinv;
                *(float2*)(out + (size_t)z * SEQ * DIM + (size_t)r * DIM + cc) =
                    make_float2(a, b);
            }
        }
}

// ---------------------------------------------------------------------------
// fp32 -> bf16 elementwise convert (for x)
// ---------------------------------------------------------------------------
__global__ __launch_bounds__(256)
void conv_f32(const float* __restrict__ in, __nv_bfloat16* __restrict__ oh, size_t n4)
{
    size_t i = (size_t)blockIdx.x * blockDim.x + threadIdx.x;
    if (i >= n4) return;
    float4 v = ((const float4*)in)[i];
    ((__nv_bfloat162*)oh)[2*i] =
        __halves2bfloat162(__float2bfloat16(v.x), __float2bfloat16(v.y));
    ((__nv_bfloat162*)oh)[2*i+1] =
        __halves2bfloat162(__float2bfloat16(v.z), __float2bfloat16(v.w));
}

// ---------------------------------------------------------------------------
// transpose fp32 [R,C] -> bf16 [C,R] (weights)
// ---------------------------------------------------------------------------
__global__ __launch_bounds__(256)
void transpose_h(const float* __restrict__ in, __nv_bfloat16* __restrict__ oh,
                 int R, int C)
{
    __shared__ float tile[32][33];
    const int c0 = blockIdx.x * 32, r0 = blockIdx.y * 32;
    const int tx = threadIdx.x & 31, ty = threadIdx.x >> 5;
    #pragma unroll
    for (int i = 0; i < 4; i++)
        tile[ty + i * 8][tx] = in[(size_t)(r0 + ty + i * 8) * C + c0 + tx];
    __syncthreads();
    #pragma unroll
    for (int i = 0; i < 4; i++) {
        const int ro = c0 + ty + i * 8;
        oh[(size_t)ro * R + r0 + tx] = __float2bfloat16(tile[tx][ty + i * 8]);
    }
}

// ---------------------------------------------------------------------------
// bf16 transpose (V): in [SEQ,DIM] per batch -> out [DIM,SEQ]
// ---------------------------------------------------------------------------
__global__ __launch_bounds__(256)
void transpose_bf16(const __nv_bfloat16* __restrict__ in, __nv_bfloat16* __restrict__ out)
{
    __shared__ __nv_bfloat16 tile[32][33];
    const int z = blockIdx.z;
    in  += (size_t)z * SEQ * DIM;
    out += (size_t)z * DIM * SEQ;
    const int c0 = blockIdx.x * 32, r0 = blockIdx.y * 32;
    const int tx = threadIdx.x & 31, ty = threadIdx.x >> 5;
    #pragma unroll
    for (int i = 0; i < 4; i++)
        tile[ty + i * 8][tx] = in[(size_t)(r0 + ty + i * 8) * DIM + c0 + tx];
    __syncthreads();
    #pragma unroll
    for (int i = 0; i < 4; i++)
        out[(size_t)(c0 + ty + i * 8) * SEQ + r0 + tx] = tile[tx][ty + i * 8];
}

// ---------------------------------------------------------------------------
extern "C" void kernel_launch(void* const* d_in, const int* in_sizes, int n_in,
                              void* d_out, int out_size)
{
    const float* x  = (const float*)d_in[0];
    const float* Wq = (const float*)d_in[1];
    const float* bq = (const float*)d_in[2];
    const float* Wk = (const float*)d_in[3];
    const float* bk = (const float*)d_in[4];
    const float* Wv = (const float*)d_in[5];
    const float* bv = (const float*)d_in[6];
    float* out = (float*)d_out;

    cudaFuncSetAttribute(proj_gemm,  cudaFuncAttributeMaxDynamicSharedMemorySize, GEMM_DSMEM);
    cudaFuncSetAttribute(score_gemm, cudaFuncAttributeMaxDynamicSharedMemorySize, GEMM_DSMEM);
    cudaFuncSetAttribute(pv_gemm,    cudaFuncAttributeMaxDynamicSharedMemorySize, GEMM_DSMEM);

    __nv_bfloat16 *xh, *wqh, *wkh, *wvh, *vh, *vth;
    cudaGetSymbolAddress((void**)&xh,  g_xh);
    cudaGetSymbolAddress((void**)&wqh, g_Wqt_h);
    cudaGetSymbolAddress((void**)&wkh, g_Wkt_h);
    cudaGetSymbolAddress((void**)&wvh, g_Wvt_h);
    cudaGetSymbolAddress((void**)&vh,  g_Vh);
    cudaGetSymbolAddress((void**)&vth, g_Vth);

    // 1) convert x -> bf16
    {
        size_t n4 = (size_t)MTOT * DIM / 4;
        conv_f32<<<(unsigned)((n4 + 255) / 256), 256>>>(x, xh, n4);
    }
    // 2) transpose weights: W[D, E] -> Wt[E, D] bf16
    {
        dim3 g(DIM / 32, DIM / 32, 1);
        transpose_h<<<g, 256>>>(Wq, wqh, DIM, DIM);
        transpose_h<<<g, 256>>>(Wk, wkh, DIM, DIM);
        transpose_h<<<g, 256>>>(Wv, wvh, DIM, DIM);
    }
    // 3) merged QKV projections (1-term)
    {
        dim3 g(DIM / 128, MTOT / 128, 3);
        proj_gemm<<<g, 128, GEMM_DSMEM>>>(bq, bk, bv);
    }
    // 4) transpose V (bf16) per batch: [SEQ, DIM] -> [DIM, SEQ]
    {
        dim3 g(DIM / 32, SEQ / 32, BATCH);
        transpose_bf16<<<g, 256>>>(vh, vth);
    }
    // 5) P~ = exp(scale * Q K^T) + partial row sums (fused softmax, no max-sub)
    {
        const float scale = 1.0f / sqrtf((float)DIM);
        dim3 g(SEQ / 128, SEQ / 128, BATCH);
        score_gemm<<<g, 128, GEMM_DSMEM>>>(scale);
    }
    // 6) row-sum reduce -> 1/rowsum
    rsum_reduce<<<(MTOT + 255) / 256, 256>>>();

    // 7) out = (P~ V) / rowsum, 1-term PV
    {
        dim3 g(DIM / 128, SEQ / 128, BATCH);
        pv_gemm<<<g, 128, GEMM_DSMEM>>>(out);
    }
}

// round 12
// speedup vs baseline: 3.5450x; 1.1551x over previous
#include <cuda_runtime.h>
#include <cuda_bf16.h>
#include <math.h>
#include <stdint.h>

#define BATCH 8
#define SEQ   2048
#define DIM   512
#define MTOT  (BATCH*SEQ)   // 16384

// ---------------------------------------------------------------------------
// Device scratch (allocation-free rule: __device__ globals)
// ---------------------------------------------------------------------------
__device__ __nv_bfloat16 g_xh[MTOT * DIM];
__device__ __nv_bfloat16 g_Wqt_h[DIM * DIM];
__device__ __nv_bfloat16 g_Wkt_h[DIM * DIM];
__device__ __nv_bfloat16 g_Wvt_h[DIM * DIM];
__device__ __nv_bfloat16 g_Qh[MTOT * DIM];
__device__ __nv_bfloat16 g_Kh[MTOT * DIM];
__device__ __nv_bfloat16 g_Vth[MTOT * DIM];                     // [B][DIM][SEQ]
__device__ __nv_bfloat16 g_Ph[(size_t)BATCH * SEQ * SEQ];       // unnormalized exp
__device__ float         g_rpart[(size_t)MTOT * 32];            // partial row sums
__device__ float         g_rinv[MTOT];                          // 1/rowsum

// ---------------------------------------------------------------------------
// Baseline-ISA helpers: ldmatrix / mma.sync / cp.async  (no 'a' features)
// ---------------------------------------------------------------------------
__device__ __forceinline__ uint32_t smem_to_u32(const void* p) {
    uint32_t a;
    asm("{ .reg .u64 t; cvta.to.shared.u64 t, %1; cvt.u32.u64 %0, t; }" : "=r"(a) : "l"(p));
    return a;
}
__device__ __forceinline__ void ldsm4(uint32_t* r, uint32_t addr) {
    asm volatile("ldmatrix.sync.aligned.m8n8.x4.shared.b16 {%0,%1,%2,%3}, [%4];"
                 : "=r"(r[0]), "=r"(r[1]), "=r"(r[2]), "=r"(r[3]) : "r"(addr));
}
__device__ __forceinline__ void mma_bf16(float* c, const uint32_t* a,
                                         uint32_t b0, uint32_t b1) {
    asm volatile("mma.sync.aligned.m16n8k16.row.col.f32.bf16.bf16.f32 "
                 "{%0,%1,%2,%3}, {%4,%5,%6,%7}, {%8,%9}, {%0,%1,%2,%3};"
                 : "+f"(c[0]), "+f"(c[1]), "+f"(c[2]), "+f"(c[3])
                 : "r"(a[0]), "r"(a[1]), "r"(a[2]), "r"(a[3]), "r"(b0), "r"(b1));
}
__device__ __forceinline__ void cp16(uint32_t dst, const void* src) {
    asm volatile("cp.async.cg.shared.global [%0], [%1], 16;" :: "r"(dst), "l"(src));
}
#define CP_COMMIT() asm volatile("cp.async.commit_group;" ::: "memory")
#define CP_WAIT1()  asm volatile("cp.async.wait_group 1;" ::: "memory")

// 8-way XOR swizzle for 128B rows: 16B-group = ch ^ (row & 7).
// Conflict-free for cp.async stores (per-row permutation) and for every
// 8-row-aligned ldmatrix phase (fixed ch, rows 0..7 -> 8 distinct groups).
#define SWZ(r, ch) ((uint32_t)(r) * 128u + (uint32_t)((((ch) ^ ((r) & 7)) & 7) << 4))

// ---------------------------------------------------------------------------
// 1-term bf16 HMMA GEMM mainloop. Block tile 128x128, BK=64, 4 warps (2Mx2N)
// of 64x64 tiles, 3-stage cp.async pipeline, single __syncthreads per chunk.
// 2 smem tiles per stage (A, B) of 16KB -> 96KB total -> 2 CTAs/SM.
// ---------------------------------------------------------------------------
#define T_B    (128 * 128)                 // 16384 B per tile
#define STAGEB (2 * T_B)                   // 32768 B
#define NSTAGE 3
#define GEMM_DSMEM (NSTAGE * STAGEB)       // 98304 B

__device__ __forceinline__ void issue_stage(uint32_t sAddr,
    const __nv_bfloat16* pA, const __nv_bfloat16* pB,
    int lda, int ldb, int k0, int t)
{
    #pragma unroll
    for (int i = 0; i < 16; i++) {          // 2048 x 16B transfers / 128 thr
        const int j    = t + i * 128;
        const int tile = j >> 10;           // 0..1
        const int r    = (j & 1023) >> 3;   // 0..127
        const int ch   = j & 7;
        const __nv_bfloat16* src = (tile ? pB : pA) + (size_t)r * (tile ? ldb : lda)
                                   + k0 + ch * 8;
        cp16(sAddr + tile * T_B + SWZ(r, ch), src);
    }
}

__device__ __forceinline__ void gemm_mainloop(uint32_t sb,
    const __nv_bfloat16* pA, const __nv_bfloat16* pB,
    int lda, int ldb, int K, int t, int wm, int wn, int lane,
    float acc[4][8][4])
{
    const int nc = K / 64;

    issue_stage(sb,          pA, pB, lda, ldb,  0, t); CP_COMMIT();
    issue_stage(sb + STAGEB, pA, pB, lda, ldb, 64, t); CP_COMMIT();

    const int lrow = lane & 15;
    const int cS   = (lane >> 4) & 1;

    for (int c = 0; c < nc; c++) {
        CP_WAIT1();
        __syncthreads();
        if (c + 2 < nc)
            issue_stage(sb + ((c + 2) % NSTAGE) * STAGEB, pA, pB,
                        lda, ldb, (c + 2) * 64, t);
        CP_COMMIT();

        const uint32_t st = sb + (c % NSTAGE) * STAGEB;
        #pragma unroll
        for (int ks = 0; ks < 4; ks++) {
            const int chunk = ks * 2 + cS;
            uint32_t ah[4][4];
            #pragma unroll
            for (int mi = 0; mi < 4; mi++) {
                const int rowA = wm * 64 + mi * 16 + lrow;
                ldsm4(ah[mi], st + SWZ(rowA, chunk));
            }
            #pragma unroll
            for (int g = 0; g < 4; g++) {
                const int rowB = wn * 64 + g * 16 + lrow;
                uint32_t qh[4];
                ldsm4(qh, st + T_B + SWZ(rowB, chunk));
                #pragma unroll
                for (int mi = 0; mi < 4; mi++) {
                    mma_bf16(acc[mi][2*g],   ah[mi], qh[0], qh[2]);
                    mma_bf16(acc[mi][2*g+1], ah[mi], qh[1], qh[3]);
                }
            }
        }
    }
}

#define ZERO_ACC(acc)                                                \
    _Pragma("unroll")                                                \
    for (int mi = 0; mi < 4; mi++)                                   \
        _Pragma("unroll")                                            \
        for (int ni = 0; ni < 8; ni++)                               \
            _Pragma("unroll")                                        \
            for (int r = 0; r < 4; r++) acc[mi][ni][r] = 0.0f;

// ---------------------------------------------------------------------------
// Merged QKV projection: grid.z selects (W, bias, output) triple.
// out = relu(x W + b) -> bf16. Q,K row-major; V written TRANSPOSED to g_Vth.
// ---------------------------------------------------------------------------
__global__ __launch_bounds__(128, 2)
void proj_gemm(const float* __restrict__ bq, const float* __restrict__ bk,
               const float* __restrict__ bv)
{
    extern __shared__ char smem[];
    const uint32_t sb = smem_to_u32(smem);
    const int t = threadIdx.x, wid = t >> 5, lane = t & 31;
    const int wm = wid >> 1, wn = wid & 1;

    const int z = blockIdx.z;                 // 0=Q 1=K 2=V
    const int rowBase = blockIdx.y * 128;
    const int colBase = blockIdx.x * 128;

    const __nv_bfloat16* pA = g_xh + (size_t)rowBase * DIM;
    const __nv_bfloat16* Wh = (z == 0) ? g_Wqt_h : (z == 1) ? g_Wkt_h : g_Wvt_h;
    const float* bias = (z == 0) ? bq : (z == 1) ? bk : bv;
    const __nv_bfloat16* pB = Wh + (size_t)colBase * DIM;

    float acc[4][8][4];
    ZERO_ACC(acc)
    gemm_mainloop(sb, pA, pB, DIM, DIM, DIM, t, wm, wn, lane, acc);

    #pragma unroll
    for (int mi = 0; mi < 4; mi++)
        #pragma unroll
        for (int rr = 0; rr < 2; rr++) {
            const int r = rowBase + wm * 64 + mi * 16 + rr * 8 + (lane >> 2);
            #pragma unroll
            for (int ni = 0; ni < 8; ni++) {
                const int cc = colBase + wn * 64 + ni * 8 + (lane & 3) * 2;
                float a = acc[mi][ni][rr * 2 + 0] + bias[cc];
                float b = acc[mi][ni][rr * 2 + 1] + bias[cc + 1];
                a = fmaxf(a, 0.0f); b = fmaxf(b, 0.0f);
                if (z < 2) {
                    __nv_bfloat16* Ch = (z == 0) ? g_Qh : g_Kh;
                    *(__nv_bfloat162*)(Ch + (size_t)r * DIM + cc) =
                        __halves2bfloat162(__float2bfloat16(a), __float2bfloat16(b));
                } else {
                    // V transposed: g_Vth[b][d][s], b = r>>11, s = r&2047, d = cc
                    const int bb = r >> 11, ss = r & (SEQ - 1);
                    __nv_bfloat16* vt = g_Vth + (size_t)bb * DIM * SEQ + ss;
                    vt[(size_t)cc * SEQ]       = __float2bfloat16(a);
                    vt[(size_t)(cc + 1) * SEQ] = __float2bfloat16(b);
                }
            }
        }
}

// ---------------------------------------------------------------------------
// Scores GEMM with fused exp: P~ = exp(scale * Q K^T) (bf16), plus
// deterministic partial row sums in g_rpart[row][ctaX*2+wn].
// ---------------------------------------------------------------------------
__global__ __launch_bounds__(128, 2)
void score_gemm(float scale)
{
    extern __shared__ char smem[];
    const uint32_t sb = smem_to_u32(smem);
    const int t = threadIdx.x, wid = t >> 5, lane = t & 31;
    const int wm = wid >> 1, wn = wid & 1;

    const int z = blockIdx.z;
    const int rowBase = blockIdx.y * 128;
    const int colBase = blockIdx.x * 128;

    const __nv_bfloat16* pA = g_Qh + (size_t)z * SEQ * DIM + (size_t)rowBase * DIM;
    const __nv_bfloat16* pB = g_Kh + (size_t)z * SEQ * DIM + (size_t)colBase * DIM;

    float acc[4][8][4];
    ZERO_ACC(acc)
    gemm_mainloop(sb, pA, pB, DIM, DIM, DIM, t, wm, wn, lane, acc);

    __nv_bfloat16* Ph = g_Ph + (size_t)z * SEQ * SEQ;

    #pragma unroll
    for (int mi = 0; mi < 4; mi++)
        #pragma unroll
        for (int rr = 0; rr < 2; rr++) {
            const int r = rowBase + wm * 64 + mi * 16 + rr * 8 + (lane >> 2);
            float rsum = 0.0f;
            #pragma unroll
            for (int ni = 0; ni < 8; ni++) {
                const int cc = colBase + wn * 64 + ni * 8 + (lane & 3) * 2;
                float ea = __expf(acc[mi][ni][rr * 2 + 0] * scale);
                float eb = __expf(acc[mi][ni][rr * 2 + 1] * scale);
                rsum += ea + eb;
                *(__nv_bfloat162*)(Ph + (size_t)r * SEQ + cc) =
                    __halves2bfloat162(__float2bfloat16(ea), __float2bfloat16(eb));
            }
            rsum += __shfl_xor_sync(0xffffffffu, rsum, 1);
            rsum += __shfl_xor_sync(0xffffffffu, rsum, 2);
            if ((lane & 3) == 0)
                g_rpart[((size_t)z * SEQ + r) * 32 + blockIdx.x * 2 + wn] = rsum;
        }
}

// ---------------------------------------------------------------------------
// Row-sum reduce: g_rinv[row] = 1 / sum(g_rpart[row][0..31])   (deterministic)
// ---------------------------------------------------------------------------
__global__ __launch_bounds__(256)
void rsum_reduce()
{
    const int row = blockIdx.x * 256 + threadIdx.x;
    if (row >= MTOT) return;
    const float* p = g_rpart + (size_t)row * 32;
    float s = 0.0f;
    #pragma unroll
    for (int i = 0; i < 32; i++) s += p[i];
    g_rinv[row] = 1.0f / s;
}

// ---------------------------------------------------------------------------
// PV GEMM (1-term): out = (P~ x Vt^T) * rinv[row]
// ---------------------------------------------------------------------------
__global__ __launch_bounds__(128, 2)
void pv_gemm(float* __restrict__ out)
{
    extern __shared__ char smem[];
    const uint32_t sb = smem_to_u32(smem);
    const int t = threadIdx.x, wid = t >> 5, lane = t & 31;
    const int wm = wid >> 1, wn = wid & 1;

    const int z = blockIdx.z;
    const int rowBase = blockIdx.y * 128;
    const int colBase = blockIdx.x * 128;

    const __nv_bfloat16* pA = g_Ph  + (size_t)z * SEQ * SEQ + (size_t)rowBase * SEQ;
    const __nv_bfloat16* pB = g_Vth + (size_t)z * DIM * SEQ + (size_t)colBase * SEQ;

    float acc[4][8][4];
    ZERO_ACC(acc)
    gemm_mainloop(sb, pA, pB, SEQ, SEQ, SEQ, t, wm, wn, lane, acc);

    #pragma unroll
    for (int mi = 0; mi < 4; mi++)
        #pragma unroll
        for (int rr = 0; rr < 2; rr++) {
            const int r = rowBase + wm * 64 + mi * 16 + rr * 8 + (lane >> 2);
            const float rinv = g_rinv[z * SEQ + r];
            #pragma unroll
            for (int ni = 0; ni < 8; ni++) {
                const int cc = colBase + wn * 64 + ni * 8 + (lane & 3) * 2;
                float a = acc[mi][ni][rr * 2 + 0] * rinv;
                float b = acc[mi][ni][rr * 2 + 1] * rinv;
                *(float2*)(out + (size_t)z * SEQ * DIM + (size_t)r * DIM + cc) =
                    make_float2(a, b);
            }
        }
}

// ---------------------------------------------------------------------------
// fp32 -> bf16 elementwise convert (for x)
// ---------------------------------------------------------------------------
__global__ __launch_bounds__(256)
void conv_f32(const float* __restrict__ in, __nv_bfloat16* __restrict__ oh, size_t n4)
{
    size_t i = (size_t)blockIdx.x * blockDim.x + threadIdx.x;
    if (i >= n4) return;
    float4 v = ((const float4*)in)[i];
    ((__nv_bfloat162*)oh)[2*i] =
        __halves2bfloat162(__float2bfloat16(v.x), __float2bfloat16(v.y));
    ((__nv_bfloat162*)oh)[2*i+1] =
        __halves2bfloat162(__float2bfloat16(v.z), __float2bfloat16(v.w));
}

// ---------------------------------------------------------------------------
// transpose fp32 [D,D] -> bf16 [D,D]^T, merged over 3 weights via grid.z
// ---------------------------------------------------------------------------
__global__ __launch_bounds__(256)
void transpose_w(const float* __restrict__ Wq, const float* __restrict__ Wk,
                 const float* __restrict__ Wv)
{
    __shared__ float tile[32][33];
    const int z = blockIdx.z;
    const float* in = (z == 0) ? Wq : (z == 1) ? Wk : Wv;
    __nv_bfloat16* oh = (z == 0) ? g_Wqt_h : (z == 1) ? g_Wkt_h : g_Wvt_h;
    const int c0 = blockIdx.x * 32, r0 = blockIdx.y * 32;
    const int tx = threadIdx.x & 31, ty = threadIdx.x >> 5;
    #pragma unroll
    for (int i = 0; i < 4; i++)
        tile[ty + i * 8][tx] = in[(size_t)(r0 + ty + i * 8) * DIM + c0 + tx];
    __syncthreads();
    #pragma unroll
    for (int i = 0; i < 4; i++) {
        const int ro = c0 + ty + i * 8;
        oh[(size_t)ro * DIM + r0 + tx] = __float2bfloat16(tile[tx][ty + i * 8]);
    }
}

// ---------------------------------------------------------------------------
extern "C" void kernel_launch(void* const* d_in, const int* in_sizes, int n_in,
                              void* d_out, int out_size)
{
    const float* x  = (const float*)d_in[0];
    const float* Wq = (const float*)d_in[1];
    const float* bq = (const float*)d_in[2];
    const float* Wk = (const float*)d_in[3];
    const float* bk = (const float*)d_in[4];
    const float* Wv = (const float*)d_in[5];
    const float* bv = (const float*)d_in[6];
    float* out = (float*)d_out;

    cudaFuncSetAttribute(proj_gemm,  cudaFuncAttributeMaxDynamicSharedMemorySize, GEMM_DSMEM);
    cudaFuncSetAttribute(score_gemm, cudaFuncAttributeMaxDynamicSharedMemorySize, GEMM_DSMEM);
    cudaFuncSetAttribute(pv_gemm,    cudaFuncAttributeMaxDynamicSharedMemorySize, GEMM_DSMEM);

    __nv_bfloat16 *xh;
    cudaGetSymbolAddress((void**)&xh, g_xh);

    // 1) convert x -> bf16
    {
        size_t n4 = (size_t)MTOT * DIM / 4;
        conv_f32<<<(unsigned)((n4 + 255) / 256), 256>>>(x, xh, n4);
    }
    // 2) transpose weights (merged): W[D,E] -> Wt[E,D] bf16
    {
        dim3 g(DIM / 32, DIM / 32, 3);
        transpose_w<<<g, 256>>>(Wq, Wk, Wv);
    }
    // 3) merged QKV projections (1-term); V written transposed
    {
        dim3 g(DIM / 128, MTOT / 128, 3);
        proj_gemm<<<g, 128, GEMM_DSMEM>>>(bq, bk, bv);
    }
    // 4) P~ = exp(scale * Q K^T) + partial row sums (fused softmax, no max-sub)
    {
        const float scale = 1.0f / sqrtf((float)DIM);
        dim3 g(SEQ / 128, SEQ / 128, BATCH);
        score_gemm<<<g, 128, GEMM_DSMEM>>>(scale);
    }
    // 5) row-sum reduce -> 1/rowsum
    rsum_reduce<<<(MTOT + 255) / 256, 256>>>();

    // 6) out = (P~ V) / rowsum, 1-term PV
    {
        dim3 g(DIM / 128, SEQ / 128, BATCH);
        pv_gemm<<<g, 128, GEMM_DSMEM>>>(out);
    }
}

// round 13
// speedup vs baseline: 3.5642x; 1.0054x over previous
#include <cuda_runtime.h>
#include <cuda_bf16.h>
#include <math.h>
#include <stdint.h>

#define BATCH 8
#define SEQ   2048
#define DIM   512
#define MTOT  (BATCH*SEQ)   // 16384

// ---------------------------------------------------------------------------
// Device scratch (allocation-free rule: __device__ globals)
// ---------------------------------------------------------------------------
__device__ __nv_bfloat16 g_xh[MTOT * DIM];
__device__ __nv_bfloat16 g_Wqt_h[DIM * DIM];
__device__ __nv_bfloat16 g_Wkt_h[DIM * DIM];
__device__ __nv_bfloat16 g_Wvt_h[DIM * DIM];
__device__ __nv_bfloat16 g_Qh[MTOT * DIM];
__device__ __nv_bfloat16 g_Kh[MTOT * DIM];
__device__ __nv_bfloat16 g_Vth[MTOT * DIM];                     // [B][DIM][SEQ]
__device__ __nv_bfloat16 g_Ph[(size_t)BATCH * SEQ * SEQ];       // unnormalized exp
__device__ float         g_rpart[(size_t)MTOT * 32];            // partial row sums
__device__ float         g_rinv[MTOT];                          // 1/rowsum

// ---------------------------------------------------------------------------
// Baseline-ISA helpers: ldmatrix / mma.sync / cp.async  (no 'a' features)
// ---------------------------------------------------------------------------
__device__ __forceinline__ uint32_t smem_to_u32(const void* p) {
    uint32_t a;
    asm("{ .reg .u64 t; cvta.to.shared.u64 t, %1; cvt.u32.u64 %0, t; }" : "=r"(a) : "l"(p));
    return a;
}
__device__ __forceinline__ void ldsm4(uint32_t* r, uint32_t addr) {
    asm volatile("ldmatrix.sync.aligned.m8n8.x4.shared.b16 {%0,%1,%2,%3}, [%4];"
                 : "=r"(r[0]), "=r"(r[1]), "=r"(r[2]), "=r"(r[3]) : "r"(addr));
}
__device__ __forceinline__ void mma_bf16(float* c, const uint32_t* a,
                                         uint32_t b0, uint32_t b1) {
    asm volatile("mma.sync.aligned.m16n8k16.row.col.f32.bf16.bf16.f32 "
                 "{%0,%1,%2,%3}, {%4,%5,%6,%7}, {%8,%9}, {%0,%1,%2,%3};"
                 : "+f"(c[0]), "+f"(c[1]), "+f"(c[2]), "+f"(c[3])
                 : "r"(a[0]), "r"(a[1]), "r"(a[2]), "r"(a[3]), "r"(b0), "r"(b1));
}
__device__ __forceinline__ void cp16(uint32_t dst, const void* src) {
    asm volatile("cp.async.cg.shared.global [%0], [%1], 16;" :: "r"(dst), "l"(src));
}
#define CP_COMMIT() asm volatile("cp.async.commit_group;" ::: "memory")
#define CP_WAIT1()  asm volatile("cp.async.wait_group 1;" ::: "memory")

// ---------------------------------------------------------------------------
// 1-term bf16 HMMA GEMM mainloop. Block tile 128x128, BK=64, 4 warps (2Mx2N)
// of 64x64 tiles, 3-stage cp.async pipeline, single __syncthreads per chunk.
// 128B rows, 8-way XOR swizzle (16B-group = ch ^ (row&7)).
// All addressing strength-reduced to loop-invariant bases + XOR/ADD.
// ---------------------------------------------------------------------------
#define T_B    (128 * 128)                 // 16384 B per tile
#define STAGEB (2 * T_B)                   // 32768 B
#define NSTAGE 3
#define GEMM_DSMEM (NSTAGE * STAGEB + 128) // +128 alignment slack

__device__ __forceinline__ void gemm_mainloop(uint32_t sbRaw,
    const __nv_bfloat16* pA, const __nv_bfloat16* pB,
    int lda, int ldb, int K, int t, int wm, int wn, int lane,
    float acc[4][8][4])
{
    const uint32_t sb = (sbRaw + 127u) & ~127u;    // 128B-aligned stage base
    const int nc = K / 64;

    // --- cp.async geometry (i-invariant swizzle; r = r0 + 16i) ---
    const int r0 = t >> 3, ch = t & 7;
    const uint32_t dst0 = (uint32_t)r0 * 128u + (uint32_t)(((ch ^ (r0 & 7)) & 7) << 4);
    const __nv_bfloat16* srcA = pA + (size_t)r0 * lda + ch * 8;
    const __nv_bfloat16* srcB = pB + (size_t)r0 * ldb + ch * 8;
    const size_t stepA = (size_t)16 * lda;
    const size_t stepB = (size_t)16 * ldb;

#define ISSUE(sAddr, k0)                                                     \
    do {                                                                     \
        const uint32_t _d = (sAddr) + dst0;                                  \
        const __nv_bfloat16* _sa = srcA + (k0);                              \
        const __nv_bfloat16* _sb2 = srcB + (k0);                             \
        _Pragma("unroll")                                                    \
        for (int _i = 0; _i < 8; _i++)                                       \
            cp16(_d + _i * 2048, _sa + _i * stepA);                          \
        _Pragma("unroll")                                                    \
        for (int _i = 0; _i < 8; _i++)                                       \
            cp16(_d + T_B + _i * 2048, _sb2 + _i * stepB);                   \
    } while (0)

    ISSUE(sb, 0);          CP_COMMIT();
    ISSUE(sb + STAGEB, 64); CP_COMMIT();

    // --- ldmatrix geometry (mi-invariant swizzle; chunk enters via XOR) ---
    const int lrow = lane & 15;
    const int cS   = (lane >> 4) & 1;
    const uint32_t aBase = (uint32_t)(wm * 64 + lrow) * 128u + (uint32_t)((lrow & 7) << 4);
    const uint32_t bBase = (uint32_t)(wn * 64 + lrow) * 128u + (uint32_t)((lrow & 7) << 4)
                           + (uint32_t)T_B;

    for (int c = 0; c < nc; c++) {
        CP_WAIT1();
        __syncthreads();
        if (c + 2 < nc)
            ISSUE(sb + ((c + 2) % NSTAGE) * STAGEB, (c + 2) * 64);
        CP_COMMIT();

        const uint32_t st = sb + (c % NSTAGE) * STAGEB;
        #pragma unroll
        for (int ks = 0; ks < 4; ks++) {
            const uint32_t cx = (uint32_t)((ks * 2 + cS) << 4);
            uint32_t ah[4][4];
            #pragma unroll
            for (int mi = 0; mi < 4; mi++)
                ldsm4(ah[mi], st + ((aBase + mi * 2048u) ^ cx));
            #pragma unroll
            for (int g = 0; g < 4; g++) {
                uint32_t qh[4];
                ldsm4(qh, st + ((bBase + g * 2048u) ^ cx));
                #pragma unroll
                for (int mi = 0; mi < 4; mi++) {
                    mma_bf16(acc[mi][2*g],   ah[mi], qh[0], qh[2]);
                    mma_bf16(acc[mi][2*g+1], ah[mi], qh[1], qh[3]);
                }
            }
        }
    }
#undef ISSUE
}

#define ZERO_ACC(acc)                                                \
    _Pragma("unroll")                                                \
    for (int mi = 0; mi < 4; mi++)                                   \
        _Pragma("unroll")                                            \
        for (int ni = 0; ni < 8; ni++)                               \
            _Pragma("unroll")                                        \
            for (int r = 0; r < 4; r++) acc[mi][ni][r] = 0.0f;

// ---------------------------------------------------------------------------
// Merged QKV projection: grid.z selects (W, bias, output) triple.
// out = relu(x W + b) -> bf16. Q,K row-major; V written TRANSPOSED to g_Vth.
// ---------------------------------------------------------------------------
__global__ __launch_bounds__(128, 2)
void proj_gemm(const float* __restrict__ bq, const float* __restrict__ bk,
               const float* __restrict__ bv)
{
    extern __shared__ char smem[];
    const uint32_t sb = smem_to_u32(smem);
    const int t = threadIdx.x, wid = t >> 5, lane = t & 31;
    const int wm = wid >> 1, wn = wid & 1;

    const int z = blockIdx.z;                 // 0=Q 1=K 2=V
    const int rowBase = blockIdx.y * 128;
    const int colBase = blockIdx.x * 128;

    const __nv_bfloat16* pA = g_xh + (size_t)rowBase * DIM;
    const __nv_bfloat16* Wh = (z == 0) ? g_Wqt_h : (z == 1) ? g_Wkt_h : g_Wvt_h;
    const float* bias = (z == 0) ? bq : (z == 1) ? bk : bv;
    const __nv_bfloat16* pB = Wh + (size_t)colBase * DIM;

    float acc[4][8][4];
    ZERO_ACC(acc)
    gemm_mainloop(sb, pA, pB, DIM, DIM, DIM, t, wm, wn, lane, acc);

    #pragma unroll
    for (int mi = 0; mi < 4; mi++)
        #pragma unroll
        for (int rr = 0; rr < 2; rr++) {
            const int r = rowBase + wm * 64 + mi * 16 + rr * 8 + (lane >> 2);
            #pragma unroll
            for (int ni = 0; ni < 8; ni++) {
                const int cc = colBase + wn * 64 + ni * 8 + (lane & 3) * 2;
                float a = acc[mi][ni][rr * 2 + 0] + bias[cc];
                float b = acc[mi][ni][rr * 2 + 1] + bias[cc + 1];
                a = fmaxf(a, 0.0f); b = fmaxf(b, 0.0f);
                if (z < 2) {
                    __nv_bfloat16* Ch = (z == 0) ? g_Qh : g_Kh;
                    *(__nv_bfloat162*)(Ch + (size_t)r * DIM + cc) =
                        __halves2bfloat162(__float2bfloat16(a), __float2bfloat16(b));
                } else {
                    // V transposed: g_Vth[b][d][s], b = r>>11, s = r&2047, d = cc
                    const int bb = r >> 11, ss = r & (SEQ - 1);
                    __nv_bfloat16* vt = g_Vth + (size_t)bb * DIM * SEQ + ss;
                    vt[(size_t)cc * SEQ]       = __float2bfloat16(a);
                    vt[(size_t)(cc + 1) * SEQ] = __float2bfloat16(b);
                }
            }
        }
}

// ---------------------------------------------------------------------------
// Scores GEMM with fused exp: P~ = exp(scale * Q K^T) (bf16), plus
// deterministic partial row sums in g_rpart[row][ctaX*2+wn].
// ---------------------------------------------------------------------------
__global__ __launch_bounds__(128, 2)
void score_gemm(float scale)
{
    extern __shared__ char smem[];
    const uint32_t sb = smem_to_u32(smem);
    const int t = threadIdx.x, wid = t >> 5, lane = t & 31;
    const int wm = wid >> 1, wn = wid & 1;

    const int z = blockIdx.z;
    const int rowBase = blockIdx.y * 128;
    const int colBase = blockIdx.x * 128;

    const __nv_bfloat16* pA = g_Qh + (size_t)z * SEQ * DIM + (size_t)rowBase * DIM;
    const __nv_bfloat16* pB = g_Kh + (size_t)z * SEQ * DIM + (size_t)colBase * DIM;

    float acc[4][8][4];
    ZERO_ACC(acc)
    gemm_mainloop(sb, pA, pB, DIM, DIM, DIM, t, wm, wn, lane, acc);

    __nv_bfloat16* Ph = g_Ph + (size_t)z * SEQ * SEQ;

    #pragma unroll
    for (int mi = 0; mi < 4; mi++)
        #pragma unroll
        for (int rr = 0; rr < 2; rr++) {
            const int r = rowBase + wm * 64 + mi * 16 + rr * 8 + (lane >> 2);
            float rsum = 0.0f;
            #pragma unroll
            for (int ni = 0; ni < 8; ni++) {
                const int cc = colBase + wn * 64 + ni * 8 + (lane & 3) * 2;
                float ea = __expf(acc[mi][ni][rr * 2 + 0] * scale);
                float eb = __expf(acc[mi][ni][rr * 2 + 1] * scale);
                rsum += ea + eb;
                *(__nv_bfloat162*)(Ph + (size_t)r * SEQ + cc) =
                    __halves2bfloat162(__float2bfloat16(ea), __float2bfloat16(eb));
            }
            rsum += __shfl_xor_sync(0xffffffffu, rsum, 1);
            rsum += __shfl_xor_sync(0xffffffffu, rsum, 2);
            if ((lane & 3) == 0)
                g_rpart[((size_t)z * SEQ + r) * 32 + blockIdx.x * 2 + wn] = rsum;
        }
}

// ---------------------------------------------------------------------------
// Row-sum reduce: g_rinv[row] = 1 / sum(g_rpart[row][0..31])   (deterministic)
// ---------------------------------------------------------------------------
__global__ __launch_bounds__(256)
void rsum_reduce()
{
    const int row = blockIdx.x * 256 + threadIdx.x;
    if (row >= MTOT) return;
    const float* p = g_rpart + (size_t)row * 32;
    float s = 0.0f;
    #pragma unroll
    for (int i = 0; i < 32; i++) s += p[i];
    g_rinv[row] = 1.0f / s;
}

// ---------------------------------------------------------------------------
// PV GEMM (1-term): out = (P~ x Vt^T) * rinv[row]
// ---------------------------------------------------------------------------
__global__ __launch_bounds__(128, 2)
void pv_gemm(float* __restrict__ out)
{
    extern __shared__ char smem[];
    const uint32_t sb = smem_to_u32(smem);
    const int t = threadIdx.x, wid = t >> 5, lane = t & 31;
    const int wm = wid >> 1, wn = wid & 1;

    const int z = blockIdx.z;
    const int rowBase = blockIdx.y * 128;
    const int colBase = blockIdx.x * 128;

    const __nv_bfloat16* pA = g_Ph  + (size_t)z * SEQ * SEQ + (size_t)rowBase * SEQ;
    const __nv_bfloat16* pB = g_Vth + (size_t)z * DIM * SEQ + (size_t)colBase * SEQ;

    float acc[4][8][4];
    ZERO_ACC(acc)
    gemm_mainloop(sb, pA, pB, SEQ, SEQ, SEQ, t, wm, wn, lane, acc);

    #pragma unroll
    for (int mi = 0; mi < 4; mi++)
        #pragma unroll
        for (int rr = 0; rr < 2; rr++) {
            const int r = rowBase + wm * 64 + mi * 16 + rr * 8 + (lane >> 2);
            const float rinv = g_rinv[z * SEQ + r];
            #pragma unroll
            for (int ni = 0; ni < 8; ni++) {
                const int cc = colBase + wn * 64 + ni * 8 + (lane & 3) * 2;
                float a = acc[mi][ni][rr * 2 + 0] * rinv;
                float b = acc[mi][ni][rr * 2 + 1] * rinv;
                *(float2*)(out + (size_t)z * SEQ * DIM + (size_t)r * DIM + cc) =
                    make_float2(a, b);
            }
        }
}

// ---------------------------------------------------------------------------
// fp32 -> bf16 elementwise convert (for x)
// ---------------------------------------------------------------------------
__global__ __launch_bounds__(256)
void conv_f32(const float* __restrict__ in, __nv_bfloat16* __restrict__ oh, size_t n4)
{
    size_t i = (size_t)blockIdx.x * blockDim.x + threadIdx.x;
    if (i >= n4) return;
    float4 v = ((const float4*)in)[i];
    ((__nv_bfloat162*)oh)[2*i] =
        __halves2bfloat162(__float2bfloat16(v.x), __float2bfloat16(v.y));
    ((__nv_bfloat162*)oh)[2*i+1] =
        __halves2bfloat162(__float2bfloat16(v.z), __float2bfloat16(v.w));
}

// ---------------------------------------------------------------------------
// transpose fp32 [D,D] -> bf16 [D,D]^T, merged over 3 weights via grid.z
// ---------------------------------------------------------------------------
__global__ __launch_bounds__(256)
void transpose_w(const float* __restrict__ Wq, const float* __restrict__ Wk,
                 const float* __restrict__ Wv)
{
    __shared__ float tile[32][33];
    const int z = blockIdx.z;
    const float* in = (z == 0) ? Wq : (z == 1) ? Wk : Wv;
    __nv_bfloat16* oh = (z == 0) ? g_Wqt_h : (z == 1) ? g_Wkt_h : g_Wvt_h;
    const int c0 = blockIdx.x * 32, r0 = blockIdx.y * 32;
    const int tx = threadIdx.x & 31, ty = threadIdx.x >> 5;
    #pragma unroll
    for (int i = 0; i < 4; i++)
        tile[ty + i * 8][tx] = in[(size_t)(r0 + ty + i * 8) * DIM + c0 + tx];
    __syncthreads();
    #pragma unroll
    for (int i = 0; i < 4; i++) {
        const int ro = c0 + ty + i * 8;
        oh[(size_t)ro * DIM + r0 + tx] = __float2bfloat16(tile[tx][ty + i * 8]);
    }
}

// ---------------------------------------------------------------------------
extern "C" void kernel_launch(void* const* d_in, const int* in_sizes, int n_in,
                              void* d_out, int out_size)
{
    const float* x  = (const float*)d_in[0];
    const float* Wq = (const float*)d_in[1];
    const float* bq = (const float*)d_in[2];
    const float* Wk = (const float*)d_in[3];
    const float* bk = (const float*)d_in[4];
    const float* Wv = (const float*)d_in[5];
    const float* bv = (const float*)d_in[6];
    float* out = (float*)d_out;

    cudaFuncSetAttribute(proj_gemm,  cudaFuncAttributeMaxDynamicSharedMemorySize, GEMM_DSMEM);
    cudaFuncSetAttribute(score_gemm, cudaFuncAttributeMaxDynamicSharedMemorySize, GEMM_DSMEM);
    cudaFuncSetAttribute(pv_gemm,    cudaFuncAttributeMaxDynamicSharedMemorySize, GEMM_DSMEM);

    __nv_bfloat16 *xh;
    cudaGetSymbolAddress((void**)&xh, g_xh);

    // 1) convert x -> bf16
    {
        size_t n4 = (size_t)MTOT * DIM / 4;
        conv_f32<<<(unsigned)((n4 + 255) / 256), 256>>>(x, xh, n4);
    }
    // 2) transpose weights (merged): W[D,E] -> Wt[E,D] bf16
    {
        dim3 g(DIM / 32, DIM / 32, 3);
        transpose_w<<<g, 256>>>(Wq, Wk, Wv);
    }
    // 3) merged QKV projections (1-term); V written transposed
    {
        dim3 g(DIM / 128, MTOT / 128, 3);
        proj_gemm<<<g, 128, GEMM_DSMEM>>>(bq, bk, bv);
    }
    // 4) P~ = exp(scale * Q K^T) + partial row sums (fused softmax, no max-sub)
    {
        const float scale = 1.0f / sqrtf((float)DIM);
        dim3 g(SEQ / 128, SEQ / 128, BATCH);
        score_gemm<<<g, 128, GEMM_DSMEM>>>(scale);
    }
    // 5) row-sum reduce -> 1/rowsum
    rsum_reduce<<<(MTOT + 255) / 256, 256>>>();

    // 6) out = (P~ V) / rowsum, 1-term PV
    {
        dim3 g(DIM / 128, SEQ / 128, BATCH);
        pv_gemm<<<g, 128, GEMM_DSMEM>>>(out);
    }
}